// round 9
// baseline (speedup 1.0000x reference)
#include <cuda_runtime.h>
#include <cuda_fp16.h>
#include <cstdint>

// ExtractorMLP: per-edge MLP 128->256->64->1 with per-graph instance norm.
// R9: gemm2 single-term fp16 mma (A and B both fp16, no split — validated
//     1.8e-4-class rounding), M=64 tiles, 256 thr, 3 CTAs/SM for natural
//     gather/mma overlap across co-resident CTAs. R8's failed intra-CTA
//     pipeline removed.

#define E_EDGES 1000000
#define EP      1000064   // multiple of 128
#define NG      512
#define NN      50000
#define C1      256
#define C2      64
#define EPS_IN  1e-5f
#define NT2     (EP / 64)    // 15626
#define G2GRID  444          // 148 SMs x 3 CTAs
#define TPC     ((NT2 + G2GRID - 1) / G2GRID)   // 36

typedef unsigned long long ull;
typedef unsigned int u32;

// ---------------- scratch ----------------
__device__ float g_Y[(size_t)NN * 512];
__device__ float g_x2[(size_t)EP * C2];
__device__ int   g_perm[EP];
__device__ int   g_gid[EP];
__device__ int   g_scol[EP];
__device__ int   g_srow[EP];
__device__ int   g_cnt[NG];
__device__ int   g_off[NG + 1];
__device__ int   g_cur[NG];
__device__ float g_inv1 [NG * C1];
__device__ float g_miv1 [NG * C1];
__device__ float g_inv2 [NG * C2];
__device__ float g_miv2 [NG * C2];
// W2 fp16 in mma-fragment-direct order (dense, 64 u32/atom; ni 8 x ki 16)
__device__ u32 g_B2h[8192];

// ---------------- helpers ----------------
__device__ __forceinline__ ull pack2(float x, float y) {
    ull r; asm("mov.b64 %0, {%1, %2};" : "=l"(r) : "f"(x), "f"(y)); return r;
}
__device__ __forceinline__ void unpack2(ull v, float& x, float& y) {
    asm("mov.b64 {%0, %1}, %2;" : "=f"(x), "=f"(y) : "l"(v));
}
__device__ __forceinline__ void fma2(ull& d, ull a, ull b) {
    asm("fma.rn.f32x2 %0, %1, %2, %0;" : "+l"(d) : "l"(a), "l"(b));
}
__device__ __forceinline__ u32 h2bits(float x, float y) {
    __half2 h = __floats2half2_rn(x, y);
    return *reinterpret_cast<u32*>(&h);
}
__device__ __forceinline__ void mma_f16(float* d, const u32* a, const u32* b) {
    asm volatile(
        "mma.sync.aligned.m16n8k16.row.col.f32.f16.f16.f32 "
        "{%0,%1,%2,%3}, {%4,%5,%6,%7}, {%8,%9}, {%0,%1,%2,%3};"
        : "+f"(d[0]), "+f"(d[1]), "+f"(d[2]), "+f"(d[3])
        : "r"(a[0]), "r"(a[1]), "r"(a[2]), "r"(a[3]), "r"(b[0]), "r"(b[1]));
}
__device__ __forceinline__ void ldm_x4(u32* r, u32 addr) {
    asm volatile("ldmatrix.sync.aligned.m8n8.x4.shared.b16 {%0,%1,%2,%3}, [%4];"
        : "=r"(r[0]), "=r"(r[1]), "=r"(r[2]), "=r"(r[3]) : "r"(addr));
}
__device__ __forceinline__ u32 smem_u32(const void* p) {
    u32 a;
    asm("{ .reg .u64 t; cvta.to.shared.u64 t, %1; cvt.u32.u64 %0, t; }"
        : "=r"(a) : "l"(p));
    return a;
}

// ---------------- init ----------------
__global__ void k_zero() {
    int t = threadIdx.x;
    if (t < NG) g_cnt[t] = 0;
    if (t < (EP - E_EDGES)) {
        g_gid[E_EDGES + t] = 0;
        g_perm[E_EDGES + t] = 0;
        g_scol[E_EDGES + t] = 0;
        g_srow[E_EDGES + t] = 0;
    }
}

// W2 [256,64] -> mma B fragments, single fp16
__global__ void k_prep2(const float* __restrict__ W2) {
    int idx = blockIdx.x * blockDim.x + threadIdx.x;
    if (idx >= 8192) return;
    int a = idx >> 6, l = (idx >> 1) & 31, r = idx & 1;
    int ng = a >> 4, ki = a & 15;
    int k = ki * 16 + (l & 3) * 2 + r * 8;
    int n = ng * 8 + (l >> 2);
    g_B2h[idx] = h2bits(W2[k * 64 + n], W2[(k + 1) * 64 + n]);
}

// ---------------- sort pipeline ----------------
__global__ void k_hist(const int* __restrict__ col, const int* __restrict__ batch) {
    __shared__ int h[NG];
    int t = threadIdx.x;
    for (int g = t; g < NG; g += blockDim.x) h[g] = 0;
    __syncthreads();
    int idx = blockIdx.x * blockDim.x + t;
    int stride = gridDim.x * blockDim.x;
    for (int e = idx; e < E_EDGES; e += stride)
        atomicAdd(&h[batch[col[e]]], 1);
    __syncthreads();
    for (int g = t; g < NG; g += blockDim.x)
        if (h[g]) atomicAdd(&g_cnt[g], h[g]);
}

__global__ void k_scan() {
    __shared__ int s[NG];
    int t = threadIdx.x;
    int c = g_cnt[t];
    s[t] = c;
    __syncthreads();
    for (int o = 1; o < NG; o <<= 1) {
        int v = (t >= o) ? s[t - o] : 0;
        __syncthreads();
        s[t] += v;
        __syncthreads();
    }
    int excl = s[t] - c;
    g_off[t] = excl;
    g_cur[t] = excl;
    if (t == NG - 1) g_off[NG] = s[t];
}

__global__ void k_scatter(const int* __restrict__ col, const int* __restrict__ row,
                          const int* __restrict__ batch) {
    __shared__ int sg[2048];
    __shared__ int hist[NG], base_[NG], cnt2[NG];
    int t = threadIdx.x;
    for (int g = t; g < NG; g += 256) { hist[g] = 0; cnt2[g] = 0; }
    __syncthreads();
    int e0 = blockIdx.x * 2048;
    #pragma unroll
    for (int j = 0; j < 8; j++) {
        int e = e0 + t + j * 256;
        int g = -1;
        if (e < E_EDGES) { g = batch[col[e]]; atomicAdd(&hist[g], 1); }
        sg[t + j * 256] = g;
    }
    __syncthreads();
    for (int g = t; g < NG; g += 256)
        if (hist[g]) base_[g] = atomicAdd(&g_cur[g], hist[g]);
    __syncthreads();
    #pragma unroll
    for (int j = 0; j < 8; j++) {
        int e = e0 + t + j * 256;
        if (e < E_EDGES) {
            int g = sg[t + j * 256];
            int l = atomicAdd(&cnt2[g], 1);
            int p = base_[g] + l;
            g_perm[p] = e;
            g_gid[p] = g;
            g_scol[p] = col[e];
            g_srow[p] = row[e];
        }
    }
}

// ---------------- Y = emb @ [W1top | W1bot] ----------------
__global__ __launch_bounds__(256) void k_emb(const float* __restrict__ emb,
                                             const float* __restrict__ W1)
{
    __shared__ float sE[64][66];
    __shared__ float sW[64][128];
    int nb = blockIdx.x * 64;
    int cb = blockIdx.y * 128;
    int tid = threadIdx.x;

    for (int i = tid; i < 64 * 16; i += 256) {
        int node = i >> 4, f4 = i & 15;
        float4 v = make_float4(0.f, 0.f, 0.f, 0.f);
        if (nb + node < NN)
            v = ((const float4*)emb)[(size_t)(nb + node) * 16 + f4];
        int k = f4 * 4;
        sE[k    ][node] = v.x;
        sE[k + 1][node] = v.y;
        sE[k + 2][node] = v.z;
        sE[k + 3][node] = v.w;
    }
    const float* Wsrc = (cb < 256) ? (W1 + cb) : (W1 + 64 * 256 + (cb - 256));
    for (int i = tid; i < 2048; i += 256) {
        int k = i >> 5, c4 = i & 31;
        ((float4*)sW[k])[c4] = ((const float4*)(Wsrc + (size_t)k * 256))[c4];
    }
    __syncthreads();

    int tn = tid >> 4, tc = tid & 15;
    ull acc[2][8];
    #pragma unroll
    for (int p = 0; p < 2; p++)
        #pragma unroll
        for (int j = 0; j < 8; j++) acc[p][j] = 0ull;

    #pragma unroll 8
    for (int k = 0; k < 64; k++) {
        ull p0 = *(const ull*)&sE[k][tn * 4];
        ull p1 = *(const ull*)&sE[k][tn * 4 + 2];
        float4 b0 = *(const float4*)&sW[k][tc * 8];
        float4 b1 = *(const float4*)&sW[k][tc * 8 + 4];
        float bs[8] = {b0.x, b0.y, b0.z, b0.w, b1.x, b1.y, b1.z, b1.w};
        #pragma unroll
        for (int j = 0; j < 8; j++) {
            ull bb = pack2(bs[j], bs[j]);
            fma2(acc[0][j], p0, bb);
            fma2(acc[1][j], p1, bb);
        }
    }
    #pragma unroll
    for (int p = 0; p < 2; p++) {
        float lo[8], hi[8];
        #pragma unroll
        for (int j = 0; j < 8; j++) unpack2(acc[p][j], lo[j], hi[j]);
        int n0 = nb + tn * 4 + 2 * p;
        if (n0 < NN) {
            float* r = g_Y + (size_t)n0 * 512 + cb + tc * 8;
            ((float4*)r)[0] = make_float4(lo[0], lo[1], lo[2], lo[3]);
            ((float4*)r)[1] = make_float4(lo[4], lo[5], lo[6], lo[7]);
        }
        if (n0 + 1 < NN) {
            float* r = g_Y + (size_t)(n0 + 1) * 512 + cb + tc * 8;
            ((float4*)r)[0] = make_float4(hi[0], hi[1], hi[2], hi[3]);
            ((float4*)r)[1] = make_float4(hi[4], hi[5], hi[6], hi[7]);
        }
    }
}

// ---------------- stats1: per (graph, 64-ch chunk), gather from Y ----------------
__global__ void k_stats1g() {
    int g  = blockIdx.x >> 2;
    int c0 = (blockIdx.x & 3) * 64;
    int t = threadIdx.x;
    int c = c0 + (t & 63), lane = t >> 6;
    int s = g_off[g], eend = g_off[g + 1];
    float S = 0.f, Q = 0.f;
    for (int p = s + lane; p < eend; p += 4) {
        int nc = g_scol[p], nr = g_srow[p];
        float v = g_Y[nc * 512 + c] + g_Y[nr * 512 + 256 + c];
        S += v; Q += v * v;
    }
    __shared__ float sS[256], sQ[256];
    sS[t] = S; sQ[t] = Q;
    __syncthreads();
    if (t < 128) { sS[t] += sS[t + 128]; sQ[t] += sQ[t + 128]; }
    __syncthreads();
    if (t < 64) {
        float Ssum = sS[t] + sS[t + 64];
        float Qsum = sQ[t] + sQ[t + 64];
        float cnt = (float)max(eend - s, 1);
        float m = Ssum / cnt;
        float var = Qsum / cnt - m * m;
        float iv = rsqrtf(var + EPS_IN);
        g_inv1 [g * C1 + c0 + t] = iv;
        g_miv1 [g * C1 + c0 + t] = m * iv;
    }
}

// ---------------- GEMM2: single-term fp16 mma, M=64 tiles, 3 CTAs/SM ----------------
// smem bytes: [0) B fp16 frags 33792 | [33792) A fp16 rows 32768.  total 66560.
// A layout: fp16 [64 edges][256 ch]; 16B granule = m*32 + (oct ^ (m&7)).
__global__ __launch_bounds__(256, 3) void k_gemm2_mma()
{
    extern __shared__ u32 sm[];
    u32* sB = sm;
    char* cA = (char*)sm + 33792;
    u32 aA = smem_u32(cA);

    int tid = threadIdx.x;
    for (int i = tid; i < 8192; i += 256) {
        int a = i >> 6, j = i & 63;
        sB[a * 66 + j] = g_B2h[i];
    }

    int w = tid >> 5, lane = tid & 31;
    int wm = w & 1, wn = w >> 1;        // M 32-slice (2), N 16-slice (4)
    int q = tid >> 6, m = tid & 63;     // producer: channel quarter, edge
    int lt = lane >> 3, lr = lane & 7;
    int lrow8 = (lt & 1) * 8 + lr;
    int lth = lt >> 1;
    int msw = m & 7;

    int t0 = blockIdx.x * TPC;
    int tend = t0 + TPC;
    if (tend > NT2) tend = NT2;

    __syncthreads();   // sB ready

    for (int tile = t0; tile < tend; tile++) {
        // ---- gather: Y[col]+Y[row] -> norm+relu -> fp16 -> swizzled rows ----
        {
            int pos = tile * 64 + m;
            int g = g_gid[pos];
            int nc = g_scol[pos], nr = g_srow[pos];
            const float4* yc = (const float4*)(g_Y + nc * 512) + q * 16;
            const float4* yr = (const float4*)(g_Y + nr * 512 + 256) + q * 16;
            const float4* vr = (const float4*)(g_inv1 + g * C1) + q * 16;
            const float4* mv = (const float4*)(g_miv1 + g * C1) + q * 16;
            u32 s0 = 0, s1 = 0;
            #pragma unroll
            for (int jj = 0; jj < 16; jj++) {
                float4 a = yc[jj], b = yr[jj], iv = vr[jj], mm = mv[jj];
                float v0 = fmaxf(fmaf(a.x + b.x, iv.x, -mm.x), 0.f);
                float v1 = fmaxf(fmaf(a.y + b.y, iv.y, -mm.y), 0.f);
                float v2 = fmaxf(fmaf(a.z + b.z, iv.z, -mm.z), 0.f);
                float v3 = fmaxf(fmaf(a.w + b.w, iv.w, -mm.w), 0.f);
                u32 h0 = h2bits(v0, v1);
                u32 h1 = h2bits(v2, v3);
                if ((jj & 1) == 0) { s0 = h0; s1 = h1; }
                else {
                    int oct = q * 8 + (jj >> 1);
                    int gran = m * 32 + (oct ^ msw);
                    *(uint4*)(cA + gran * 16) = make_uint4(s0, s1, h0, h1);
                }
            }
        }
        __syncthreads();
        // ---- mma ----
        float d[2][2][4];
        #pragma unroll
        for (int mi2 = 0; mi2 < 2; mi2++)
            #pragma unroll
            for (int ni = 0; ni < 2; ni++)
                #pragma unroll
                for (int r = 0; r < 4; r++) d[mi2][ni][r] = 0.f;

        #pragma unroll
        for (int ki = 0; ki < 16; ki++) {
            u32 ah[2][4];
            #pragma unroll
            for (int mi2 = 0; mi2 < 2; mi2++) {
                int ml = wm * 32 + mi2 * 16 + lrow8;
                int oct = 2 * ki + lth;
                u32 goff = (u32)(ml * 32 + (oct ^ (ml & 7))) * 16;
                ldm_x4(ah[mi2], aA + goff);
            }
            #pragma unroll
            for (int ni = 0; ni < 2; ni++) {
                int batom = ((wn * 2 + ni) * 16 + ki) * 66 + lane * 2;
                uint2 bv = *(const uint2*)(sB + batom);
                u32 bb[2] = {bv.x, bv.y};
                mma_f16(d[0][ni], ah[0], bb);
                mma_f16(d[1][ni], ah[1], bb);
            }
        }
        // ---- epilogue ----
        {
            int r0base = tile * 64 + wm * 32 + (lane >> 2);
            int cbase = wn * 16 + (lane & 3) * 2;
            #pragma unroll
            for (int mi2 = 0; mi2 < 2; mi2++) {
                size_t rA = (size_t)(r0base + mi2 * 16);
                size_t rB = rA + 8;
                #pragma unroll
                for (int ni = 0; ni < 2; ni++) {
                    int c = cbase + ni * 8;
                    *(float2*)(g_x2 + rA * C2 + c) = make_float2(d[mi2][ni][0], d[mi2][ni][1]);
                    *(float2*)(g_x2 + rB * C2 + c) = make_float2(d[mi2][ni][2], d[mi2][ni][3]);
                }
            }
        }
        __syncthreads();   // A consumed before next gather overwrites
    }
}

// ---------------- stats2 ----------------
__global__ void k_stats2() {
    int g  = blockIdx.x >> 1;
    int c0 = (blockIdx.x & 1) * 32;
    int t = threadIdx.x;
    int c = c0 + (t & 31), r = t >> 5;
    int s = g_off[g], eend = g_off[g + 1];
    float S = 0.f, Q = 0.f;
    for (int p = s + r; p < eend; p += 8) {
        float v = g_x2[(size_t)p * C2 + c];
        S += v; Q += v * v;
    }
    __shared__ float sS[256], sQ[256];
    sS[t] = S; sQ[t] = Q;
    __syncthreads();
    for (int h2 = 128; h2 >= 32; h2 >>= 1) {
        if (t < h2) { sS[t] += sS[t + h2]; sQ[t] += sQ[t + h2]; }
        __syncthreads();
    }
    if (t < 32) {
        float cnt = (float)max(eend - s, 1);
        float m = sS[t] / cnt;
        float var = sQ[t] / cnt - m * m;
        float iv = rsqrtf(var + EPS_IN);
        g_inv2 [g * C2 + c0 + t] = iv;
        g_miv2 [g * C2 + c0 + t] = m * iv;
    }
}

// ---------------- final layer ----------------
__global__ void k_final(const float* __restrict__ W3, const float* __restrict__ b3,
                        float* __restrict__ out)
{
    __shared__ float sw[64];
    int tid = threadIdx.x;
    if (tid < 64) sw[tid] = W3[tid];
    __syncthreads();
    int pos = blockIdx.x * 128 + (tid >> 1);
    int half = tid & 1;
    float acc = 0.f;
    if (pos < E_EDGES) {
        int g = g_gid[pos];
        const float4* xr = (const float4*)g_x2    + (size_t)pos * 16 + half * 8;
        const float4* vr = (const float4*)g_inv2  + g * 16 + half * 8;
        const float4* mr = (const float4*)g_miv2  + g * 16 + half * 8;
        #pragma unroll
        for (int j = 0; j < 8; j++) {
            float4 x = xr[j], iv = vr[j], mv = mr[j];
            int k = half * 32 + j * 4;
            acc += fmaxf(fmaf(x.x, iv.x, -mv.x), 0.f) * sw[k]
                 + fmaxf(fmaf(x.y, iv.y, -mv.y), 0.f) * sw[k + 1]
                 + fmaxf(fmaf(x.z, iv.z, -mv.z), 0.f) * sw[k + 2]
                 + fmaxf(fmaf(x.w, iv.w, -mv.w), 0.f) * sw[k + 3];
        }
    }
    float other = __shfl_xor_sync(0xffffffffu, acc, 1);
    if (half == 0 && pos < E_EDGES) out[g_perm[pos]] = acc + other + b3[0];
}

// ---------------- launch ----------------
extern "C" void kernel_launch(void* const* d_in, const int* in_sizes, int n_in,
                              void* d_out, int out_size)
{
    const float* emb   = (const float*)d_in[0];
    const float* W1    = (const float*)d_in[1];
    const float* W2    = (const float*)d_in[3];
    const float* W3    = (const float*)d_in[5];
    const float* b3    = (const float*)d_in[6];
    const int*   ei    = (const int*)d_in[7];
    const int*   batch = (const int*)d_in[8];
    const int* col = ei;
    const int* row = ei + E_EDGES;
    float* out = (float*)d_out;

    static int attr_set = 0;
    if (!attr_set) {
        cudaFuncSetAttribute(k_gemm2_mma, cudaFuncAttributeMaxDynamicSharedMemorySize, 66560);
        attr_set = 1;
    }

    k_zero<<<1, 512>>>();
    k_hist<<<1024, 256>>>(col, batch);
    k_scan<<<1, 512>>>();
    k_emb<<<dim3((NN + 63) / 64, 4), 256>>>(emb, W1);   // launch idx 3 -> profiled
    k_scatter<<<(E_EDGES + 2047) / 2048, 256>>>(col, row, batch);
    k_prep2<<<16, 512>>>(W2);
    k_stats1g<<<NG * 4, 256>>>();
    k_gemm2_mma<<<G2GRID, 256, 66560>>>();
    k_stats2<<<NG * 2, 256>>>();
    k_final<<<EP / 128, 256>>>(W3, b3, out);
}

// round 10
// speedup vs baseline: 1.9210x; 1.9210x over previous
#include <cuda_runtime.h>
#include <cuda_fp16.h>
#include <cstdint>

// ExtractorMLP: per-edge MLP 128->256->64->1 with per-graph instance norm.
// R10: R7 tile structure (M=128, 512 thr, proven) + single-term fp16 mma
//      + Y/norm-params stored fp16 (halves gather bytes + register pressure;
//      2 CTAs/SM without spills). R8/R9 structural regressions reverted.

#define E_EDGES 1000000
#define EP      1000064   // multiple of 128
#define NG      512
#define NN      50000
#define C1      256
#define C2      64
#define EPS_IN  1e-5f
#define NT      (EP / 128)   // 7813
#define GRID2   296          // 148 SMs x 2 CTAs

typedef unsigned long long ull;
typedef unsigned int u32;

// ---------------- scratch ----------------
__device__ u32   g_Yh[(size_t)NN * 256];   // 51 MB, half2-packed Y
__device__ float g_x2[(size_t)EP * C2];
__device__ int   g_perm[EP];
__device__ int   g_gid[EP];
__device__ int   g_scol[EP];
__device__ int   g_srow[EP];
__device__ int   g_cnt[NG];
__device__ int   g_off[NG + 1];
__device__ int   g_cur[NG];
__device__ u32   g_iv1h [NG * 128];        // half2-packed inv1
__device__ u32   g_miv1h[NG * 128];        // half2-packed mean1*inv1
__device__ float g_inv2 [NG * C2];
__device__ float g_miv2 [NG * C2];
// W2 fp16 in mma-fragment-direct order (dense, 64 u32/atom; ni 8 x ki 16)
__device__ u32 g_B2h[8192];

// ---------------- helpers ----------------
__device__ __forceinline__ ull pack2(float x, float y) {
    ull r; asm("mov.b64 %0, {%1, %2};" : "=l"(r) : "f"(x), "f"(y)); return r;
}
__device__ __forceinline__ void unpack2(ull v, float& x, float& y) {
    asm("mov.b64 {%0, %1}, %2;" : "=f"(x), "=f"(y) : "l"(v));
}
__device__ __forceinline__ void fma2(ull& d, ull a, ull b) {
    asm("fma.rn.f32x2 %0, %1, %2, %0;" : "+l"(d) : "l"(a), "l"(b));
}
__device__ __forceinline__ u32 h2bits(float x, float y) {
    __half2 h = __floats2half2_rn(x, y);
    return *reinterpret_cast<u32*>(&h);
}
__device__ __forceinline__ float2 h22f2(u32 v) {
    __half2 h = *reinterpret_cast<__half2*>(&v);
    return __half22float2(h);
}
__device__ __forceinline__ void mma_f16(float* d, const u32* a, const u32* b) {
    asm volatile(
        "mma.sync.aligned.m16n8k16.row.col.f32.f16.f16.f32 "
        "{%0,%1,%2,%3}, {%4,%5,%6,%7}, {%8,%9}, {%0,%1,%2,%3};"
        : "+f"(d[0]), "+f"(d[1]), "+f"(d[2]), "+f"(d[3])
        : "r"(a[0]), "r"(a[1]), "r"(a[2]), "r"(a[3]), "r"(b[0]), "r"(b[1]));
}
__device__ __forceinline__ void ldm_x4(u32* r, u32 addr) {
    asm volatile("ldmatrix.sync.aligned.m8n8.x4.shared.b16 {%0,%1,%2,%3}, [%4];"
        : "=r"(r[0]), "=r"(r[1]), "=r"(r[2]), "=r"(r[3]) : "r"(addr));
}
__device__ __forceinline__ u32 smem_u32(const void* p) {
    u32 a;
    asm("{ .reg .u64 t; cvta.to.shared.u64 t, %1; cvt.u32.u64 %0, t; }"
        : "=r"(a) : "l"(p));
    return a;
}

// ---------------- init ----------------
__global__ void k_zero() {
    int t = threadIdx.x;
    if (t < NG) g_cnt[t] = 0;
    if (t < (EP - E_EDGES)) {
        g_gid[E_EDGES + t] = 0;
        g_perm[E_EDGES + t] = 0;
        g_scol[E_EDGES + t] = 0;
        g_srow[E_EDGES + t] = 0;
    }
}

// W2 [256,64] -> mma B fragments, single fp16
__global__ void k_prep2(const float* __restrict__ W2) {
    int idx = blockIdx.x * blockDim.x + threadIdx.x;
    if (idx >= 8192) return;
    int a = idx >> 6, l = (idx >> 1) & 31, r = idx & 1;
    int ng = a >> 4, ki = a & 15;
    int k = ki * 16 + (l & 3) * 2 + r * 8;
    int n = ng * 8 + (l >> 2);
    g_B2h[idx] = h2bits(W2[k * 64 + n], W2[(k + 1) * 64 + n]);
}

// ---------------- sort pipeline ----------------
__global__ void k_hist(const int* __restrict__ col, const int* __restrict__ batch) {
    __shared__ int h[NG];
    int t = threadIdx.x;
    for (int g = t; g < NG; g += blockDim.x) h[g] = 0;
    __syncthreads();
    int idx = blockIdx.x * blockDim.x + t;
    int stride = gridDim.x * blockDim.x;
    for (int e = idx; e < E_EDGES; e += stride)
        atomicAdd(&h[batch[col[e]]], 1);
    __syncthreads();
    for (int g = t; g < NG; g += blockDim.x)
        if (h[g]) atomicAdd(&g_cnt[g], h[g]);
}

__global__ void k_scan() {
    __shared__ int s[NG];
    int t = threadIdx.x;
    int c = g_cnt[t];
    s[t] = c;
    __syncthreads();
    for (int o = 1; o < NG; o <<= 1) {
        int v = (t >= o) ? s[t - o] : 0;
        __syncthreads();
        s[t] += v;
        __syncthreads();
    }
    int excl = s[t] - c;
    g_off[t] = excl;
    g_cur[t] = excl;
    if (t == NG - 1) g_off[NG] = s[t];
}

__global__ void k_scatter(const int* __restrict__ col, const int* __restrict__ row,
                          const int* __restrict__ batch) {
    __shared__ int sg[2048];
    __shared__ int hist[NG], base_[NG], cnt2[NG];
    int t = threadIdx.x;
    for (int g = t; g < NG; g += 256) { hist[g] = 0; cnt2[g] = 0; }
    __syncthreads();
    int e0 = blockIdx.x * 2048;
    #pragma unroll
    for (int j = 0; j < 8; j++) {
        int e = e0 + t + j * 256;
        int g = -1;
        if (e < E_EDGES) { g = batch[col[e]]; atomicAdd(&hist[g], 1); }
        sg[t + j * 256] = g;
    }
    __syncthreads();
    for (int g = t; g < NG; g += 256)
        if (hist[g]) base_[g] = atomicAdd(&g_cur[g], hist[g]);
    __syncthreads();
    #pragma unroll
    for (int j = 0; j < 8; j++) {
        int e = e0 + t + j * 256;
        if (e < E_EDGES) {
            int g = sg[t + j * 256];
            int l = atomicAdd(&cnt2[g], 1);
            int p = base_[g] + l;
            g_perm[p] = e;
            g_gid[p] = g;
            g_scol[p] = col[e];
            g_srow[p] = row[e];
        }
    }
}

// ---------------- Y = emb @ [W1top | W1bot], output fp16-packed ----------------
__global__ __launch_bounds__(256) void k_emb(const float* __restrict__ emb,
                                             const float* __restrict__ W1)
{
    __shared__ float sE[64][66];
    __shared__ float sW[64][128];
    int nb = blockIdx.x * 64;
    int cb = blockIdx.y * 128;
    int tid = threadIdx.x;

    for (int i = tid; i < 64 * 16; i += 256) {
        int node = i >> 4, f4 = i & 15;
        float4 v = make_float4(0.f, 0.f, 0.f, 0.f);
        if (nb + node < NN)
            v = ((const float4*)emb)[(size_t)(nb + node) * 16 + f4];
        int k = f4 * 4;
        sE[k    ][node] = v.x;
        sE[k + 1][node] = v.y;
        sE[k + 2][node] = v.z;
        sE[k + 3][node] = v.w;
    }
    const float* Wsrc = (cb < 256) ? (W1 + cb) : (W1 + 64 * 256 + (cb - 256));
    for (int i = tid; i < 2048; i += 256) {
        int k = i >> 5, c4 = i & 31;
        ((float4*)sW[k])[c4] = ((const float4*)(Wsrc + (size_t)k * 256))[c4];
    }
    __syncthreads();

    int tn = tid >> 4, tc = tid & 15;
    ull acc[2][8];
    #pragma unroll
    for (int p = 0; p < 2; p++)
        #pragma unroll
        for (int j = 0; j < 8; j++) acc[p][j] = 0ull;

    #pragma unroll 8
    for (int k = 0; k < 64; k++) {
        ull p0 = *(const ull*)&sE[k][tn * 4];
        ull p1 = *(const ull*)&sE[k][tn * 4 + 2];
        float4 b0 = *(const float4*)&sW[k][tc * 8];
        float4 b1 = *(const float4*)&sW[k][tc * 8 + 4];
        float bs[8] = {b0.x, b0.y, b0.z, b0.w, b1.x, b1.y, b1.z, b1.w};
        #pragma unroll
        for (int j = 0; j < 8; j++) {
            ull bb = pack2(bs[j], bs[j]);
            fma2(acc[0][j], p0, bb);
            fma2(acc[1][j], p1, bb);
        }
    }
    #pragma unroll
    for (int p = 0; p < 2; p++) {
        float lo[8], hi[8];
        #pragma unroll
        for (int j = 0; j < 8; j++) unpack2(acc[p][j], lo[j], hi[j]);
        int n0 = nb + tn * 4 + 2 * p;
        if (n0 < NN) {
            *(uint4*)(g_Yh + (size_t)n0 * 256 + cb / 2 + tc * 4) = make_uint4(
                h2bits(lo[0], lo[1]), h2bits(lo[2], lo[3]),
                h2bits(lo[4], lo[5]), h2bits(lo[6], lo[7]));
        }
        if (n0 + 1 < NN) {
            *(uint4*)(g_Yh + (size_t)(n0 + 1) * 256 + cb / 2 + tc * 4) = make_uint4(
                h2bits(hi[0], hi[1]), h2bits(hi[2], hi[3]),
                h2bits(hi[4], hi[5]), h2bits(hi[6], hi[7]));
        }
    }
}

// ---------------- stats1: per (graph, 64-ch chunk), gather fp16 Y ----------------
__global__ void k_stats1g() {
    int g  = blockIdx.x >> 2;
    int c0u = (blockIdx.x & 3) * 32;   // u32 (channel-pair) base within 128
    int t = threadIdx.x;
    int c2 = t & 31, r = t >> 5;       // pair index, strided row
    int s = g_off[g], eend = g_off[g + 1];
    float Sx = 0.f, Sy = 0.f, Qx = 0.f, Qy = 0.f;
    int cb = c0u + c2;
    for (int p = s + r; p < eend; p += 8) {
        int nc = g_scol[p], nr = g_srow[p];
        float2 fa = h22f2(g_Yh[(size_t)nc * 256 + cb]);
        float2 fb = h22f2(g_Yh[(size_t)nr * 256 + 128 + cb]);
        float vx = fa.x + fb.x, vy = fa.y + fb.y;
        Sx += vx; Qx += vx * vx;
        Sy += vy; Qy += vy * vy;
    }
    __shared__ float4 sS[256];
    sS[t] = make_float4(Sx, Sy, Qx, Qy);
    __syncthreads();
    for (int h2 = 128; h2 >= 32; h2 >>= 1) {
        if (t < h2) {
            float4 o = sS[t + h2];
            sS[t].x += o.x; sS[t].y += o.y; sS[t].z += o.z; sS[t].w += o.w;
        }
        __syncthreads();
    }
    if (t < 32) {
        float4 v = sS[t];
        float cnt = (float)max(eend - s, 1);
        float mx = v.x / cnt, my = v.y / cnt;
        float ivx = rsqrtf(v.z / cnt - mx * mx + EPS_IN);
        float ivy = rsqrtf(v.w / cnt - my * my + EPS_IN);
        g_iv1h [g * 128 + c0u + t] = h2bits(ivx, ivy);
        g_miv1h[g * 128 + c0u + t] = h2bits(mx * ivx, my * ivy);
    }
}

// ---------------- GEMM2: single fp16 mma, M=128 tiles, 512 thr, 2 CTAs/SM ----------------
// smem bytes: [0) B frags 33792 | [33792) A fp16 rows 65536.  total 99328.
// A layout: fp16 [128 edges][256 ch]; 16B granule = m*32 + (oct ^ (m&7)).
__global__ __launch_bounds__(512, 2) void k_gemm2_mma()
{
    extern __shared__ u32 sm[];
    u32* sB = sm;
    char* cA = (char*)sm + 33792;
    u32 aA = smem_u32(cA);

    int tid = threadIdx.x;
    for (int i = tid; i < 8192; i += 512) {
        int a = i >> 6, j = i & 63;
        sB[a * 66 + j] = g_B2h[i];
    }

    int w = tid >> 5, lane = tid & 31;
    int wm = w & 3, wn = w >> 2;        // M 32-slice (4), N 16-slice (4)
    int q = tid >> 7, m = tid & 127;    // producer: channel quarter, edge
    int msw = m & 7;
    int lt = lane >> 3, lr = lane & 7;
    int lrow8 = (lt & 1) * 8 + lr;
    int lth = lt >> 1;

    __syncthreads();   // sB ready

    for (int tile = blockIdx.x; tile < NT; tile += GRID2) {
        // ---- gather: fp16 Y[col]+Y[row] -> norm+relu -> fp16 swizzled rows ----
        {
            int pos = tile * 128 + m;
            int g = g_gid[pos];
            int nc = g_scol[pos], nr = g_srow[pos];
            const uint4* yc = (const uint4*)(g_Yh + (size_t)nc * 256 + q * 32);
            const uint4* yr = (const uint4*)(g_Yh + (size_t)nr * 256 + 128 + q * 32);
            const uint4* hiv = (const uint4*)(g_iv1h  + g * 128 + q * 32);
            const uint4* hmv = (const uint4*)(g_miv1h + g * 128 + q * 32);
            #pragma unroll
            for (int jj = 0; jj < 8; jj++) {
                uint4 va = yc[jj], vb = yr[jj], vi = hiv[jj], vm = hmv[jj];
                u32 o[4];
                {
                    float2 fa = h22f2(va.x), fb = h22f2(vb.x), fi = h22f2(vi.x), fm = h22f2(vm.x);
                    o[0] = h2bits(fmaxf(fmaf(fa.x + fb.x, fi.x, -fm.x), 0.f),
                                  fmaxf(fmaf(fa.y + fb.y, fi.y, -fm.y), 0.f));
                }
                {
                    float2 fa = h22f2(va.y), fb = h22f2(vb.y), fi = h22f2(vi.y), fm = h22f2(vm.y);
                    o[1] = h2bits(fmaxf(fmaf(fa.x + fb.x, fi.x, -fm.x), 0.f),
                                  fmaxf(fmaf(fa.y + fb.y, fi.y, -fm.y), 0.f));
                }
                {
                    float2 fa = h22f2(va.z), fb = h22f2(vb.z), fi = h22f2(vi.z), fm = h22f2(vm.z);
                    o[2] = h2bits(fmaxf(fmaf(fa.x + fb.x, fi.x, -fm.x), 0.f),
                                  fmaxf(fmaf(fa.y + fb.y, fi.y, -fm.y), 0.f));
                }
                {
                    float2 fa = h22f2(va.w), fb = h22f2(vb.w), fi = h22f2(vi.w), fm = h22f2(vm.w);
                    o[3] = h2bits(fmaxf(fmaf(fa.x + fb.x, fi.x, -fm.x), 0.f),
                                  fmaxf(fmaf(fa.y + fb.y, fi.y, -fm.y), 0.f));
                }
                int oct = q * 8 + jj;
                int gran = m * 32 + (oct ^ msw);
                *(uint4*)(cA + gran * 16) = make_uint4(o[0], o[1], o[2], o[3]);
            }
        }
        __syncthreads();
        // ---- mma ----
        float d[2][2][4];
        #pragma unroll
        for (int mi2 = 0; mi2 < 2; mi2++)
            #pragma unroll
            for (int ni = 0; ni < 2; ni++)
                #pragma unroll
                for (int r = 0; r < 4; r++) d[mi2][ni][r] = 0.f;

        #pragma unroll
        for (int ki = 0; ki < 16; ki++) {
            u32 ah[2][4];
            #pragma unroll
            for (int mi2 = 0; mi2 < 2; mi2++) {
                int ml = wm * 32 + mi2 * 16 + lrow8;
                int oct = 2 * ki + lth;
                u32 goff = (u32)(ml * 32 + (oct ^ (ml & 7))) * 16;
                ldm_x4(ah[mi2], aA + goff);
            }
            #pragma unroll
            for (int ni = 0; ni < 2; ni++) {
                int batom = ((wn * 2 + ni) * 16 + ki) * 66 + lane * 2;
                uint2 bv = *(const uint2*)(sB + batom);
                u32 bb[2] = {bv.x, bv.y};
                mma_f16(d[0][ni], ah[0], bb);
                mma_f16(d[1][ni], ah[1], bb);
            }
        }
        // ---- epilogue ----
        {
            int r0base = tile * 128 + wm * 32 + (lane >> 2);
            int cbase = wn * 16 + (lane & 3) * 2;
            #pragma unroll
            for (int mi2 = 0; mi2 < 2; mi2++) {
                size_t rA = (size_t)(r0base + mi2 * 16);
                size_t rB = rA + 8;
                #pragma unroll
                for (int ni = 0; ni < 2; ni++) {
                    int c = cbase + ni * 8;
                    *(float2*)(g_x2 + rA * C2 + c) = make_float2(d[mi2][ni][0], d[mi2][ni][1]);
                    *(float2*)(g_x2 + rB * C2 + c) = make_float2(d[mi2][ni][2], d[mi2][ni][3]);
                }
            }
        }
        __syncthreads();   // A consumed before next gather overwrites
    }
}

// ---------------- stats2 ----------------
__global__ void k_stats2() {
    int g  = blockIdx.x >> 1;
    int c0 = (blockIdx.x & 1) * 32;
    int t = threadIdx.x;
    int c = c0 + (t & 31), r = t >> 5;
    int s = g_off[g], eend = g_off[g + 1];
    float S = 0.f, Q = 0.f;
    for (int p = s + r; p < eend; p += 8) {
        float v = g_x2[(size_t)p * C2 + c];
        S += v; Q += v * v;
    }
    __shared__ float sS[256], sQ[256];
    sS[t] = S; sQ[t] = Q;
    __syncthreads();
    for (int h2 = 128; h2 >= 32; h2 >>= 1) {
        if (t < h2) { sS[t] += sS[t + h2]; sQ[t] += sQ[t + h2]; }
        __syncthreads();
    }
    if (t < 32) {
        float cnt = (float)max(eend - s, 1);
        float m = sS[t] / cnt;
        float var = sQ[t] / cnt - m * m;
        float iv = rsqrtf(var + EPS_IN);
        g_inv2 [g * C2 + c0 + t] = iv;
        g_miv2 [g * C2 + c0 + t] = m * iv;
    }
}

// ---------------- final layer ----------------
__global__ void k_final(const float* __restrict__ W3, const float* __restrict__ b3,
                        float* __restrict__ out)
{
    __shared__ float sw[64];
    int tid = threadIdx.x;
    if (tid < 64) sw[tid] = W3[tid];
    __syncthreads();
    int pos = blockIdx.x * 128 + (tid >> 1);
    int half = tid & 1;
    float acc = 0.f;
    if (pos < E_EDGES) {
        int g = g_gid[pos];
        const float4* xr = (const float4*)g_x2    + (size_t)pos * 16 + half * 8;
        const float4* vr = (const float4*)g_inv2  + g * 16 + half * 8;
        const float4* mr = (const float4*)g_miv2  + g * 16 + half * 8;
        #pragma unroll
        for (int j = 0; j < 8; j++) {
            float4 x = xr[j], iv = vr[j], mv = mr[j];
            int k = half * 32 + j * 4;
            acc += fmaxf(fmaf(x.x, iv.x, -mv.x), 0.f) * sw[k]
                 + fmaxf(fmaf(x.y, iv.y, -mv.y), 0.f) * sw[k + 1]
                 + fmaxf(fmaf(x.z, iv.z, -mv.z), 0.f) * sw[k + 2]
                 + fmaxf(fmaf(x.w, iv.w, -mv.w), 0.f) * sw[k + 3];
        }
    }
    float other = __shfl_xor_sync(0xffffffffu, acc, 1);
    if (half == 0 && pos < E_EDGES) out[g_perm[pos]] = acc + other + b3[0];
}

// ---------------- launch ----------------
extern "C" void kernel_launch(void* const* d_in, const int* in_sizes, int n_in,
                              void* d_out, int out_size)
{
    const float* emb   = (const float*)d_in[0];
    const float* W1    = (const float*)d_in[1];
    const float* W2    = (const float*)d_in[3];
    const float* W3    = (const float*)d_in[5];
    const float* b3    = (const float*)d_in[6];
    const int*   ei    = (const int*)d_in[7];
    const int*   batch = (const int*)d_in[8];
    const int* col = ei;
    const int* row = ei + E_EDGES;
    float* out = (float*)d_out;

    static int attr_set = 0;
    if (!attr_set) {
        cudaFuncSetAttribute(k_gemm2_mma, cudaFuncAttributeMaxDynamicSharedMemorySize, 99328);
        attr_set = 1;
    }

    k_zero<<<1, 512>>>();
    k_hist<<<1024, 256>>>(col, batch);
    k_scan<<<1, 512>>>();
    k_emb<<<dim3((NN + 63) / 64, 4), 256>>>(emb, W1);   // launch idx 3 -> profiled
    k_scatter<<<(E_EDGES + 2047) / 2048, 256>>>(col, row, batch);
    k_prep2<<<16, 512>>>(W2);
    k_stats1g<<<NG * 4, 256>>>();
    k_gemm2_mma<<<GRID2, 512, 99328>>>();
    k_stats2<<<NG * 2, 256>>>();
    k_final<<<EP / 128, 256>>>(W3, b3, out);
}

// round 11
// speedup vs baseline: 2.2749x; 1.1842x over previous
#include <cuda_runtime.h>
#include <cuda_fp16.h>
#include <cstdint>

// ExtractorMLP: per-edge MLP 128->256->64->1 with per-graph instance norm.
// R11: k_emb moved to fp16 mma.sync (was LDS-bound FFMA2); x2 stored fp16
//      (halves stats2/final read traffic). All on the R10-proven machinery.

#define E_EDGES 1000000
#define EP      1000064   // multiple of 128
#define NG      512
#define NN      50000
#define C1      256
#define C2      64
#define EPS_IN  1e-5f
#define NT      (EP / 128)   // 7813
#define GRID2   296          // 148 SMs x 2 CTAs

typedef unsigned long long ull;
typedef unsigned int u32;

// ---------------- scratch ----------------
__device__ u32   g_Yh[(size_t)NN * 256];   // 51 MB, half2-packed Y
__device__ u32   g_x2h[(size_t)EP * 32];   // 128 MB, half2-packed x2
__device__ u32   g_embh[(size_t)NN * 32];  // 6.4 MB, half2-packed emb
__device__ int   g_perm[EP];
__device__ int   g_gid[EP];
__device__ int   g_scol[EP];
__device__ int   g_srow[EP];
__device__ int   g_cnt[NG];
__device__ int   g_off[NG + 1];
__device__ int   g_cur[NG];
__device__ u32   g_iv1h [NG * 128];        // half2-packed inv1
__device__ u32   g_miv1h[NG * 128];        // half2-packed mean1*inv1
__device__ float g_inv2 [NG * C2];
__device__ float g_miv2 [NG * C2];
// W frags fp16, mma-fragment order (dense, 64 u32/atom)
__device__ u32 g_B1h[16384];   // [W1top|W1bot]: 2 halves x 128 atoms (ng32 x ki4)
__device__ u32 g_B2h[8192];    // W2: 128 atoms (ng8 x ki16)

// ---------------- helpers ----------------
__device__ __forceinline__ u32 h2bits(float x, float y) {
    __half2 h = __floats2half2_rn(x, y);
    return *reinterpret_cast<u32*>(&h);
}
__device__ __forceinline__ float2 h22f2(u32 v) {
    __half2 h = *reinterpret_cast<__half2*>(&v);
    return __half22float2(h);
}
__device__ __forceinline__ void mma_f16(float* d, const u32* a, const u32* b) {
    asm volatile(
        "mma.sync.aligned.m16n8k16.row.col.f32.f16.f16.f32 "
        "{%0,%1,%2,%3}, {%4,%5,%6,%7}, {%8,%9}, {%0,%1,%2,%3};"
        : "+f"(d[0]), "+f"(d[1]), "+f"(d[2]), "+f"(d[3])
        : "r"(a[0]), "r"(a[1]), "r"(a[2]), "r"(a[3]), "r"(b[0]), "r"(b[1]));
}
__device__ __forceinline__ void ldm_x4(u32* r, u32 addr) {
    asm volatile("ldmatrix.sync.aligned.m8n8.x4.shared.b16 {%0,%1,%2,%3}, [%4];"
        : "=r"(r[0]), "=r"(r[1]), "=r"(r[2]), "=r"(r[3]) : "r"(addr));
}
__device__ __forceinline__ u32 smem_u32(const void* p) {
    u32 a;
    asm("{ .reg .u64 t; cvta.to.shared.u64 t, %1; cvt.u32.u64 %0, t; }"
        : "=r"(a) : "l"(p));
    return a;
}

// ---------------- init / prep ----------------
__global__ void k_zero() {
    int t = threadIdx.x;
    if (t < NG) g_cnt[t] = 0;
    if (t < (EP - E_EDGES)) {
        g_gid[E_EDGES + t] = 0;
        g_perm[E_EDGES + t] = 0;
        g_scol[E_EDGES + t] = 0;
        g_srow[E_EDGES + t] = 0;
    }
}

__global__ void k_prep_emb(const float* __restrict__ emb) {
    int idx = blockIdx.x * blockDim.x + threadIdx.x;   // < NN*32
    float2 v = ((const float2*)emb)[idx];
    g_embh[idx] = h2bits(v.x, v.y);
}

// [W1top|W1bot] ([64,512]) -> mma B fragments fp16 (two 256-col halves)
__global__ void k_prep1(const float* __restrict__ W1) {
    int idx = blockIdx.x * blockDim.x + threadIdx.x;
    if (idx >= 16384) return;
    int half = idx >> 13, i = idx & 8191;
    int a = i >> 6, l = (i >> 1) & 31, r = i & 1;
    int ng = a >> 2, ki = a & 3;
    int k = ki * 16 + (l & 3) * 2 + r * 8;   // pair rows k, k+1
    int n = ng * 8 + (l >> 2);
    const float* base = half ? (W1 + 64 * 256 + n) : (W1 + n);
    g_B1h[idx] = h2bits(base[k * 256], base[(k + 1) * 256]);
}

// W2 [256,64] -> mma B fragments fp16
__global__ void k_prep2(const float* __restrict__ W2) {
    int idx = blockIdx.x * blockDim.x + threadIdx.x;
    if (idx >= 8192) return;
    int a = idx >> 6, l = (idx >> 1) & 31, r = idx & 1;
    int ng = a >> 4, ki = a & 15;
    int k = ki * 16 + (l & 3) * 2 + r * 8;
    int n = ng * 8 + (l >> 2);
    g_B2h[idx] = h2bits(W2[k * 64 + n], W2[(k + 1) * 64 + n]);
}

// ---------------- Y = emb @ [W1top | W1bot], fp16 mma ----------------
// grid (391, 2): 128 nodes x 256 cols per CTA, K=64.
// smem: B frags 128*66 u32 = 33792 B | A fp16 128 rows x 8 granules = 16384 B.
__global__ __launch_bounds__(512) void k_emb_mma()
{
    extern __shared__ u32 sm[];
    u32* sB = sm;
    char* cA = (char*)sm + 33792;
    u32 aA = smem_u32(cA);

    int tid = threadIdx.x;
    int half = blockIdx.y;
    int nb = blockIdx.x * 128;

    for (int i = tid; i < 8192; i += 512)
        sB[(i >> 6) * 66 + (i & 63)] = g_B1h[half * 8192 + i];

    // gather A: emb fp16 rows, swizzled granules
    {
        int m = tid >> 2, q = tid & 3;
        int node = nb + m, msw = m & 7;
        uint4 v0 = make_uint4(0, 0, 0, 0), v1 = v0;
        if (node < NN) {
            const uint4* src = (const uint4*)(g_embh + (size_t)node * 32);
            v0 = src[q * 2]; v1 = src[q * 2 + 1];
        }
        *(uint4*)(cA + (m * 8 + ((q * 2)     ^ msw)) * 16) = v0;
        *(uint4*)(cA + (m * 8 + ((q * 2 + 1) ^ msw)) * 16) = v1;
    }
    __syncthreads();

    int w = tid >> 5, lane = tid & 31;
    int wm = w & 3, wn = w >> 2;        // M 32-slice (4), N 64-slice (4)
    int lt = lane >> 3, lr = lane & 7;
    int lrow8 = (lt & 1) * 8 + lr, lth = lt >> 1;

    float d[2][8][4];
    #pragma unroll
    for (int a = 0; a < 2; a++)
        #pragma unroll
        for (int b = 0; b < 8; b++)
            #pragma unroll
            for (int c = 0; c < 4; c++) d[a][b][c] = 0.f;

    #pragma unroll
    for (int ki = 0; ki < 4; ki++) {
        u32 ah[2][4];
        #pragma unroll
        for (int mi2 = 0; mi2 < 2; mi2++) {
            int ml = wm * 32 + mi2 * 16 + lrow8;
            int oct = 2 * ki + lth;
            u32 goff = (u32)(ml * 8 + (oct ^ (ml & 7))) * 16;
            ldm_x4(ah[mi2], aA + goff);
        }
        #pragma unroll
        for (int ni = 0; ni < 8; ni++) {
            int batom = ((wn * 8 + ni) * 4 + ki) * 66 + lane * 2;
            uint2 bv = *(const uint2*)(sB + batom);
            u32 bb[2] = {bv.x, bv.y};
            mma_f16(d[0][ni], ah[0], bb);
            mma_f16(d[1][ni], ah[1], bb);
        }
    }
    // epilogue: pack fp16 pairs -> g_Yh
    {
        int r0 = nb + wm * 32 + (lane >> 2);
        int cpb = (half * 256 + wn * 64 + (lane & 3) * 2) >> 1;  // u32 pair index
        #pragma unroll
        for (int mi2 = 0; mi2 < 2; mi2++) {
            int rA = r0 + mi2 * 16, rB = rA + 8;
            if (rA < NN) {
                #pragma unroll
                for (int ni = 0; ni < 8; ni++)
                    g_Yh[(size_t)rA * 256 + cpb + ni * 4] = h2bits(d[mi2][ni][0], d[mi2][ni][1]);
            }
            if (rB < NN) {
                #pragma unroll
                for (int ni = 0; ni < 8; ni++)
                    g_Yh[(size_t)rB * 256 + cpb + ni * 4] = h2bits(d[mi2][ni][2], d[mi2][ni][3]);
            }
        }
    }
}

// ---------------- sort pipeline ----------------
__global__ void k_hist(const int* __restrict__ col, const int* __restrict__ batch) {
    __shared__ int h[NG];
    int t = threadIdx.x;
    for (int g = t; g < NG; g += blockDim.x) h[g] = 0;
    __syncthreads();
    int idx = blockIdx.x * blockDim.x + t;
    int stride = gridDim.x * blockDim.x;
    for (int e = idx; e < E_EDGES; e += stride)
        atomicAdd(&h[batch[col[e]]], 1);
    __syncthreads();
    for (int g = t; g < NG; g += blockDim.x)
        if (h[g]) atomicAdd(&g_cnt[g], h[g]);
}

__global__ void k_scan() {
    __shared__ int s[NG];
    int t = threadIdx.x;
    int c = g_cnt[t];
    s[t] = c;
    __syncthreads();
    for (int o = 1; o < NG; o <<= 1) {
        int v = (t >= o) ? s[t - o] : 0;
        __syncthreads();
        s[t] += v;
        __syncthreads();
    }
    int excl = s[t] - c;
    g_off[t] = excl;
    g_cur[t] = excl;
    if (t == NG - 1) g_off[NG] = s[t];
}

__global__ void k_scatter(const int* __restrict__ col, const int* __restrict__ row,
                          const int* __restrict__ batch) {
    __shared__ int sg[2048];
    __shared__ int hist[NG], base_[NG], cnt2[NG];
    int t = threadIdx.x;
    for (int g = t; g < NG; g += 256) { hist[g] = 0; cnt2[g] = 0; }
    __syncthreads();
    int e0 = blockIdx.x * 2048;
    #pragma unroll
    for (int j = 0; j < 8; j++) {
        int e = e0 + t + j * 256;
        int g = -1;
        if (e < E_EDGES) { g = batch[col[e]]; atomicAdd(&hist[g], 1); }
        sg[t + j * 256] = g;
    }
    __syncthreads();
    for (int g = t; g < NG; g += 256)
        if (hist[g]) base_[g] = atomicAdd(&g_cur[g], hist[g]);
    __syncthreads();
    #pragma unroll
    for (int j = 0; j < 8; j++) {
        int e = e0 + t + j * 256;
        if (e < E_EDGES) {
            int g = sg[t + j * 256];
            int l = atomicAdd(&cnt2[g], 1);
            int p = base_[g] + l;
            g_perm[p] = e;
            g_gid[p] = g;
            g_scol[p] = col[e];
            g_srow[p] = row[e];
        }
    }
}

// ---------------- stats1: per (graph, 64-ch chunk), gather fp16 Y ----------------
__global__ void k_stats1g() {
    int g  = blockIdx.x >> 2;
    int c0u = (blockIdx.x & 3) * 32;
    int t = threadIdx.x;
    int c2 = t & 31, r = t >> 5;
    int s = g_off[g], eend = g_off[g + 1];
    float Sx = 0.f, Sy = 0.f, Qx = 0.f, Qy = 0.f;
    int cb = c0u + c2;
    for (int p = s + r; p < eend; p += 8) {
        int nc = g_scol[p], nr = g_srow[p];
        float2 fa = h22f2(g_Yh[(size_t)nc * 256 + cb]);
        float2 fb = h22f2(g_Yh[(size_t)nr * 256 + 128 + cb]);
        float vx = fa.x + fb.x, vy = fa.y + fb.y;
        Sx += vx; Qx += vx * vx;
        Sy += vy; Qy += vy * vy;
    }
    __shared__ float4 sS[256];
    sS[t] = make_float4(Sx, Sy, Qx, Qy);
    __syncthreads();
    for (int h2 = 128; h2 >= 32; h2 >>= 1) {
        if (t < h2) {
            float4 o = sS[t + h2];
            sS[t].x += o.x; sS[t].y += o.y; sS[t].z += o.z; sS[t].w += o.w;
        }
        __syncthreads();
    }
    if (t < 32) {
        float4 v = sS[t];
        float cnt = (float)max(eend - s, 1);
        float mx = v.x / cnt, my = v.y / cnt;
        float ivx = rsqrtf(v.z / cnt - mx * mx + EPS_IN);
        float ivy = rsqrtf(v.w / cnt - my * my + EPS_IN);
        g_iv1h [g * 128 + c0u + t] = h2bits(ivx, ivy);
        g_miv1h[g * 128 + c0u + t] = h2bits(mx * ivx, my * ivy);
    }
}

// ---------------- GEMM2: single fp16 mma, M=128 tiles, 512 thr, 2 CTAs/SM ----------------
// smem bytes: [0) B frags 33792 | [33792) A fp16 rows 65536.  total 99328.
__global__ __launch_bounds__(512, 2) void k_gemm2_mma()
{
    extern __shared__ u32 sm[];
    u32* sB = sm;
    char* cA = (char*)sm + 33792;
    u32 aA = smem_u32(cA);

    int tid = threadIdx.x;
    for (int i = tid; i < 8192; i += 512) {
        int a = i >> 6, j = i & 63;
        sB[a * 66 + j] = g_B2h[i];
    }

    int w = tid >> 5, lane = tid & 31;
    int wm = w & 3, wn = w >> 2;
    int q = tid >> 7, m = tid & 127;
    int msw = m & 7;
    int lt = lane >> 3, lr = lane & 7;
    int lrow8 = (lt & 1) * 8 + lr;
    int lth = lt >> 1;

    __syncthreads();   // sB ready

    for (int tile = blockIdx.x; tile < NT; tile += GRID2) {
        // ---- gather: fp16 Y[col]+Y[row] -> norm+relu -> fp16 swizzled rows ----
        {
            int pos = tile * 128 + m;
            int g = g_gid[pos];
            int nc = g_scol[pos], nr = g_srow[pos];
            const uint4* yc = (const uint4*)(g_Yh + (size_t)nc * 256 + q * 32);
            const uint4* yr = (const uint4*)(g_Yh + (size_t)nr * 256 + 128 + q * 32);
            const uint4* hiv = (const uint4*)(g_iv1h  + g * 128 + q * 32);
            const uint4* hmv = (const uint4*)(g_miv1h + g * 128 + q * 32);
            #pragma unroll
            for (int jj = 0; jj < 8; jj++) {
                uint4 va = yc[jj], vb = yr[jj], vi = hiv[jj], vm = hmv[jj];
                u32 o[4];
                {
                    float2 fa = h22f2(va.x), fb = h22f2(vb.x), fi = h22f2(vi.x), fm = h22f2(vm.x);
                    o[0] = h2bits(fmaxf(fmaf(fa.x + fb.x, fi.x, -fm.x), 0.f),
                                  fmaxf(fmaf(fa.y + fb.y, fi.y, -fm.y), 0.f));
                }
                {
                    float2 fa = h22f2(va.y), fb = h22f2(vb.y), fi = h22f2(vi.y), fm = h22f2(vm.y);
                    o[1] = h2bits(fmaxf(fmaf(fa.x + fb.x, fi.x, -fm.x), 0.f),
                                  fmaxf(fmaf(fa.y + fb.y, fi.y, -fm.y), 0.f));
                }
                {
                    float2 fa = h22f2(va.z), fb = h22f2(vb.z), fi = h22f2(vi.z), fm = h22f2(vm.z);
                    o[2] = h2bits(fmaxf(fmaf(fa.x + fb.x, fi.x, -fm.x), 0.f),
                                  fmaxf(fmaf(fa.y + fb.y, fi.y, -fm.y), 0.f));
                }
                {
                    float2 fa = h22f2(va.w), fb = h22f2(vb.w), fi = h22f2(vi.w), fm = h22f2(vm.w);
                    o[3] = h2bits(fmaxf(fmaf(fa.x + fb.x, fi.x, -fm.x), 0.f),
                                  fmaxf(fmaf(fa.y + fb.y, fi.y, -fm.y), 0.f));
                }
                int oct = q * 8 + jj;
                int gran = m * 32 + (oct ^ msw);
                *(uint4*)(cA + gran * 16) = make_uint4(o[0], o[1], o[2], o[3]);
            }
        }
        __syncthreads();
        // ---- mma ----
        float d[2][2][4];
        #pragma unroll
        for (int mi2 = 0; mi2 < 2; mi2++)
            #pragma unroll
            for (int ni = 0; ni < 2; ni++)
                #pragma unroll
                for (int r = 0; r < 4; r++) d[mi2][ni][r] = 0.f;

        #pragma unroll
        for (int ki = 0; ki < 16; ki++) {
            u32 ah[2][4];
            #pragma unroll
            for (int mi2 = 0; mi2 < 2; mi2++) {
                int ml = wm * 32 + mi2 * 16 + lrow8;
                int oct = 2 * ki + lth;
                u32 goff = (u32)(ml * 32 + (oct ^ (ml & 7))) * 16;
                ldm_x4(ah[mi2], aA + goff);
            }
            #pragma unroll
            for (int ni = 0; ni < 2; ni++) {
                int batom = ((wn * 2 + ni) * 16 + ki) * 66 + lane * 2;
                uint2 bv = *(const uint2*)(sB + batom);
                u32 bb[2] = {bv.x, bv.y};
                mma_f16(d[0][ni], ah[0], bb);
                mma_f16(d[1][ni], ah[1], bb);
            }
        }
        // ---- epilogue: pack fp16 -> g_x2h ----
        {
            int r0base = tile * 128 + wm * 32 + (lane >> 2);
            int cpb = wn * 8 + (lane & 3);   // u32 pair index base
            #pragma unroll
            for (int mi2 = 0; mi2 < 2; mi2++) {
                size_t rA = (size_t)(r0base + mi2 * 16);
                size_t rB = rA + 8;
                #pragma unroll
                for (int ni = 0; ni < 2; ni++) {
                    g_x2h[rA * 32 + cpb + ni * 4] = h2bits(d[mi2][ni][0], d[mi2][ni][1]);
                    g_x2h[rB * 32 + cpb + ni * 4] = h2bits(d[mi2][ni][2], d[mi2][ni][3]);
                }
            }
        }
        __syncthreads();
    }
}

// ---------------- stats2 (fp16 x2) ----------------
__global__ void k_stats2() {
    int g = blockIdx.x;
    int t = threadIdx.x;
    int c2 = t & 31, r = t >> 5;
    int s = g_off[g], eend = g_off[g + 1];
    float Sx = 0.f, Sy = 0.f, Qx = 0.f, Qy = 0.f;
    for (int p = s + r; p < eend; p += 8) {
        float2 f = h22f2(g_x2h[(size_t)p * 32 + c2]);
        Sx += f.x; Qx += f.x * f.x;
        Sy += f.y; Qy += f.y * f.y;
    }
    __shared__ float4 sS[256];
    sS[t] = make_float4(Sx, Sy, Qx, Qy);
    __syncthreads();
    for (int h2 = 128; h2 >= 32; h2 >>= 1) {
        if (t < h2) {
            float4 o = sS[t + h2];
            sS[t].x += o.x; sS[t].y += o.y; sS[t].z += o.z; sS[t].w += o.w;
        }
        __syncthreads();
    }
    if (t < 32) {
        float4 v = sS[t];
        float cnt = (float)max(eend - s, 1);
        float mx = v.x / cnt, my = v.y / cnt;
        float ivx = rsqrtf(v.z / cnt - mx * mx + EPS_IN);
        float ivy = rsqrtf(v.w / cnt - my * my + EPS_IN);
        g_inv2 [g * C2 + t * 2]     = ivx;
        g_inv2 [g * C2 + t * 2 + 1] = ivy;
        g_miv2 [g * C2 + t * 2]     = mx * ivx;
        g_miv2 [g * C2 + t * 2 + 1] = my * ivy;
    }
}

// ---------------- final layer (fp16 x2) ----------------
__global__ void k_final(const float* __restrict__ W3, const float* __restrict__ b3,
                        float* __restrict__ out)
{
    __shared__ float sw[64];
    int tid = threadIdx.x;
    if (tid < 64) sw[tid] = W3[tid];
    __syncthreads();
    int pos = blockIdx.x * 128 + (tid >> 1);
    int half = tid & 1;
    float acc = 0.f;
    if (pos < E_EDGES) {
        int g = g_gid[pos];
        const uint4* xr = (const uint4*)(g_x2h + (size_t)pos * 32 + half * 16);
        const float4* vr = (const float4*)(g_inv2 + g * C2 + half * 32);
        const float4* mr = (const float4*)(g_miv2 + g * C2 + half * 32);
        #pragma unroll
        for (int j = 0; j < 4; j++) {
            uint4 xv = xr[j];
            float4 iv0 = vr[2 * j], iv1 = vr[2 * j + 1];
            float4 mv0 = mr[2 * j], mv1 = mr[2 * j + 1];
            float2 a0 = h22f2(xv.x), a1 = h22f2(xv.y);
            float2 a2 = h22f2(xv.z), a3 = h22f2(xv.w);
            int k = half * 32 + j * 8;
            acc += fmaxf(fmaf(a0.x, iv0.x, -mv0.x), 0.f) * sw[k]
                 + fmaxf(fmaf(a0.y, iv0.y, -mv0.y), 0.f) * sw[k + 1]
                 + fmaxf(fmaf(a1.x, iv0.z, -mv0.z), 0.f) * sw[k + 2]
                 + fmaxf(fmaf(a1.y, iv0.w, -mv0.w), 0.f) * sw[k + 3]
                 + fmaxf(fmaf(a2.x, iv1.x, -mv1.x), 0.f) * sw[k + 4]
                 + fmaxf(fmaf(a2.y, iv1.y, -mv1.y), 0.f) * sw[k + 5]
                 + fmaxf(fmaf(a3.x, iv1.z, -mv1.z), 0.f) * sw[k + 6]
                 + fmaxf(fmaf(a3.y, iv1.w, -mv1.w), 0.f) * sw[k + 7];
        }
    }
    float other = __shfl_xor_sync(0xffffffffu, acc, 1);
    if (half == 0 && pos < E_EDGES) out[g_perm[pos]] = acc + other + b3[0];
}

// ---------------- launch ----------------
extern "C" void kernel_launch(void* const* d_in, const int* in_sizes, int n_in,
                              void* d_out, int out_size)
{
    const float* emb   = (const float*)d_in[0];
    const float* W1    = (const float*)d_in[1];
    const float* W2    = (const float*)d_in[3];
    const float* W3    = (const float*)d_in[5];
    const float* b3    = (const float*)d_in[6];
    const int*   ei    = (const int*)d_in[7];
    const int*   batch = (const int*)d_in[8];
    const int* col = ei;
    const int* row = ei + E_EDGES;
    float* out = (float*)d_out;

    static int attr_set = 0;
    if (!attr_set) {
        cudaFuncSetAttribute(k_gemm2_mma, cudaFuncAttributeMaxDynamicSharedMemorySize, 99328);
        cudaFuncSetAttribute(k_emb_mma, cudaFuncAttributeMaxDynamicSharedMemorySize, 50176);
        attr_set = 1;
    }

    k_zero<<<1, 512>>>();
    k_prep_emb<<<(NN * 32) / 512, 512>>>(emb);
    k_prep1<<<32, 512>>>(W1);
    k_emb_mma<<<dim3((NN + 127) / 128, 2), 512, 50176>>>();   // idx 3 -> profiled
    k_hist<<<1024, 256>>>(col, batch);
    k_scan<<<1, 512>>>();
    k_scatter<<<(E_EDGES + 2047) / 2048, 256>>>(col, row, batch);
    k_prep2<<<16, 512>>>(W2);
    k_stats1g<<<NG * 4, 256>>>();
    k_gemm2_mma<<<GRID2, 512, 99328>>>();
    k_stats2<<<NG, 256>>>();
    k_final<<<EP / 128, 256>>>(W3, b3, out);
}

// round 12
// speedup vs baseline: 2.3066x; 1.0139x over previous
#include <cuda_runtime.h>
#include <cuda_fp16.h>
#include <cstdint>

// ExtractorMLP: per-edge MLP 128->256->64->1 with per-graph instance norm.
// R12: prep kernels fused into consumers (W1/W2 frag conversion in-CTA,
//      emb fp32 read directly in emb_mma, self-cleaning k_scan replaces
//      k_zero); gemm2 gather norm in native half2 SIMD with pre-negated miv.

#define E_EDGES 1000000
#define EP      1000064   // multiple of 128
#define NG      512
#define NN      50000
#define C1      256
#define C2      64
#define EPS_IN  1e-5f
#define NT      (EP / 128)   // 7813
#define GRID2   296          // 148 SMs x 2 CTAs

typedef unsigned long long ull;
typedef unsigned int u32;

// ---------------- scratch ----------------
__device__ u32   g_Yh[(size_t)NN * 256];   // 51 MB, half2-packed Y
__device__ u32   g_x2h[(size_t)EP * 32];   // 128 MB, half2-packed x2
__device__ int   g_perm[EP];
__device__ int   g_gid[EP];
__device__ int   g_scol[EP];
__device__ int   g_srow[EP];
__device__ int   g_cnt[NG];                // invariant: zero at kernel_launch entry
__device__ int   g_off[NG + 1];
__device__ int   g_cur[NG];
__device__ u32   g_iv1h [NG * 128];        // half2-packed inv1
__device__ u32   g_nmiv1h[NG * 128];       // half2-packed NEGATED mean1*inv1
__device__ float g_inv2 [NG * C2];
__device__ float g_miv2 [NG * C2];

// ---------------- helpers ----------------
__device__ __forceinline__ u32 h2bits(float x, float y) {
    __half2 h = __floats2half2_rn(x, y);
    return *reinterpret_cast<u32*>(&h);
}
__device__ __forceinline__ __half2 u2h(u32 v) {
    return *reinterpret_cast<__half2*>(&v);
}
__device__ __forceinline__ u32 h2u(__half2 h) {
    return *reinterpret_cast<u32*>(&h);
}
__device__ __forceinline__ float2 h22f2(u32 v) {
    __half2 h = *reinterpret_cast<__half2*>(&v);
    return __half22float2(h);
}
__device__ __forceinline__ void mma_f16(float* d, const u32* a, const u32* b) {
    asm volatile(
        "mma.sync.aligned.m16n8k16.row.col.f32.f16.f16.f32 "
        "{%0,%1,%2,%3}, {%4,%5,%6,%7}, {%8,%9}, {%0,%1,%2,%3};"
        : "+f"(d[0]), "+f"(d[1]), "+f"(d[2]), "+f"(d[3])
        : "r"(a[0]), "r"(a[1]), "r"(a[2]), "r"(a[3]), "r"(b[0]), "r"(b[1]));
}
__device__ __forceinline__ void ldm_x4(u32* r, u32 addr) {
    asm volatile("ldmatrix.sync.aligned.m8n8.x4.shared.b16 {%0,%1,%2,%3}, [%4];"
        : "=r"(r[0]), "=r"(r[1]), "=r"(r[2]), "=r"(r[3]) : "r"(addr));
}
__device__ __forceinline__ u32 smem_u32(const void* p) {
    u32 a;
    asm("{ .reg .u64 t; cvta.to.shared.u64 t, %1; cvt.u32.u64 %0, t; }"
        : "=r"(a) : "l"(p));
    return a;
}

// ---------------- sort pipeline ----------------
// g_cnt is zero at entry (static init on first run; k_scan re-zeroes after use).
__global__ void k_hist(const int* __restrict__ col, const int* __restrict__ batch) {
    __shared__ int h[NG];
    int t = threadIdx.x;
    for (int g = t; g < NG; g += blockDim.x) h[g] = 0;
    __syncthreads();
    int idx = blockIdx.x * blockDim.x + t;
    int stride = gridDim.x * blockDim.x;
    for (int e = idx; e < E_EDGES; e += stride)
        atomicAdd(&h[batch[col[e]]], 1);
    __syncthreads();
    for (int g = t; g < NG; g += blockDim.x)
        if (h[g]) atomicAdd(&g_cnt[g], h[g]);
}

__global__ void k_scan() {
    __shared__ int s[NG];
    int t = threadIdx.x;
    int c = g_cnt[t];
    s[t] = c;
    __syncthreads();
    for (int o = 1; o < NG; o <<= 1) {
        int v = (t >= o) ? s[t - o] : 0;
        __syncthreads();
        s[t] += v;
        __syncthreads();
    }
    int excl = s[t] - c;
    g_off[t] = excl;
    g_cur[t] = excl;
    if (t == NG - 1) g_off[NG] = s[t];
    g_cnt[t] = 0;                       // restore invariant for next replay
    if (t < (EP - E_EDGES)) {           // padding entries (idempotent)
        g_gid[E_EDGES + t] = 0;
        g_perm[E_EDGES + t] = 0;
        g_scol[E_EDGES + t] = 0;
        g_srow[E_EDGES + t] = 0;
    }
}

__global__ void k_scatter(const int* __restrict__ col, const int* __restrict__ row,
                          const int* __restrict__ batch) {
    __shared__ int sg[2048];
    __shared__ int hist[NG], base_[NG], cnt2[NG];
    int t = threadIdx.x;
    for (int g = t; g < NG; g += 256) { hist[g] = 0; cnt2[g] = 0; }
    __syncthreads();
    int e0 = blockIdx.x * 2048;
    #pragma unroll
    for (int j = 0; j < 8; j++) {
        int e = e0 + t + j * 256;
        int g = -1;
        if (e < E_EDGES) { g = batch[col[e]]; atomicAdd(&hist[g], 1); }
        sg[t + j * 256] = g;
    }
    __syncthreads();
    for (int g = t; g < NG; g += 256)
        if (hist[g]) base_[g] = atomicAdd(&g_cur[g], hist[g]);
    __syncthreads();
    #pragma unroll
    for (int j = 0; j < 8; j++) {
        int e = e0 + t + j * 256;
        if (e < E_EDGES) {
            int g = sg[t + j * 256];
            int l = atomicAdd(&cnt2[g], 1);
            int p = base_[g] + l;
            g_perm[p] = e;
            g_gid[p] = g;
            g_scol[p] = col[e];
            g_srow[p] = row[e];
        }
    }
}

// ---------------- Y = emb @ [W1top | W1bot], fp16 mma, all conversion fused ----------------
// grid (391, 2): 128 nodes x 256 cols per CTA, K=64.
// smem: B frags 128*66 u32 = 33792 B | A fp16 128 rows x 8 granules = 16384 B.
__global__ __launch_bounds__(512) void k_emb_mma(const float* __restrict__ emb,
                                                 const float* __restrict__ W1)
{
    extern __shared__ u32 sm[];
    u32* sB = sm;
    char* cA = (char*)sm + 33792;
    u32 aA = smem_u32(cA);

    int tid = threadIdx.x;
    int half = blockIdx.y;
    int nb = blockIdx.x * 128;

    // B frags: convert W1 fp32 -> fp16 fragments in-CTA
    for (int i = tid; i < 8192; i += 512) {
        int a = i >> 6, l = (i >> 1) & 31, r = i & 1;
        int ng = a >> 2, ki = a & 3;
        int k = ki * 16 + (l & 3) * 2 + r * 8;
        int n = ng * 8 + (l >> 2);
        const float* base = W1 + half * 64 * 256 + n;
        sB[a * 66 + (i & 63)] = h2bits(base[k * 256], base[(k + 1) * 256]);
    }

    // A: emb fp32 rows -> fp16 swizzled granules
    {
        int m = tid >> 2, q = tid & 3;
        int node = nb + m, msw = m & 7;
        u32 h[8] = {0, 0, 0, 0, 0, 0, 0, 0};
        if (node < NN) {
            const float4* src = (const float4*)(emb + (size_t)node * 64 + q * 16);
            float4 v0 = src[0], v1 = src[1], v2 = src[2], v3 = src[3];
            h[0] = h2bits(v0.x, v0.y); h[1] = h2bits(v0.z, v0.w);
            h[2] = h2bits(v1.x, v1.y); h[3] = h2bits(v1.z, v1.w);
            h[4] = h2bits(v2.x, v2.y); h[5] = h2bits(v2.z, v2.w);
            h[6] = h2bits(v3.x, v3.y); h[7] = h2bits(v3.z, v3.w);
        }
        *(uint4*)(cA + (m * 8 + ((q * 2)     ^ msw)) * 16) = make_uint4(h[0], h[1], h[2], h[3]);
        *(uint4*)(cA + (m * 8 + ((q * 2 + 1) ^ msw)) * 16) = make_uint4(h[4], h[5], h[6], h[7]);
    }
    __syncthreads();

    int w = tid >> 5, lane = tid & 31;
    int wm = w & 3, wn = w >> 2;
    int lt = lane >> 3, lr = lane & 7;
    int lrow8 = (lt & 1) * 8 + lr, lth = lt >> 1;

    float d[2][8][4];
    #pragma unroll
    for (int a = 0; a < 2; a++)
        #pragma unroll
        for (int b = 0; b < 8; b++)
            #pragma unroll
            for (int c = 0; c < 4; c++) d[a][b][c] = 0.f;

    #pragma unroll
    for (int ki = 0; ki < 4; ki++) {
        u32 ah[2][4];
        #pragma unroll
        for (int mi2 = 0; mi2 < 2; mi2++) {
            int ml = wm * 32 + mi2 * 16 + lrow8;
            int oct = 2 * ki + lth;
            u32 goff = (u32)(ml * 8 + (oct ^ (ml & 7))) * 16;
            ldm_x4(ah[mi2], aA + goff);
        }
        #pragma unroll
        for (int ni = 0; ni < 8; ni++) {
            int batom = ((wn * 8 + ni) * 4 + ki) * 66 + lane * 2;
            uint2 bv = *(const uint2*)(sB + batom);
            u32 bb[2] = {bv.x, bv.y};
            mma_f16(d[0][ni], ah[0], bb);
            mma_f16(d[1][ni], ah[1], bb);
        }
    }
    {
        int r0 = nb + wm * 32 + (lane >> 2);
        int cpb = (half * 256 + wn * 64 + (lane & 3) * 2) >> 1;
        #pragma unroll
        for (int mi2 = 0; mi2 < 2; mi2++) {
            int rA = r0 + mi2 * 16, rB = rA + 8;
            if (rA < NN) {
                #pragma unroll
                for (int ni = 0; ni < 8; ni++)
                    g_Yh[(size_t)rA * 256 + cpb + ni * 4] = h2bits(d[mi2][ni][0], d[mi2][ni][1]);
            }
            if (rB < NN) {
                #pragma unroll
                for (int ni = 0; ni < 8; ni++)
                    g_Yh[(size_t)rB * 256 + cpb + ni * 4] = h2bits(d[mi2][ni][2], d[mi2][ni][3]);
            }
        }
    }
}

// ---------------- stats1: per (graph, 64-ch chunk), gather fp16 Y ----------------
__global__ void k_stats1g() {
    int g  = blockIdx.x >> 2;
    int c0u = (blockIdx.x & 3) * 32;
    int t = threadIdx.x;
    int c2 = t & 31, r = t >> 5;
    int s = g_off[g], eend = g_off[g + 1];
    float Sx = 0.f, Sy = 0.f, Qx = 0.f, Qy = 0.f;
    int cb = c0u + c2;
    for (int p = s + r; p < eend; p += 8) {
        int nc = g_scol[p], nr = g_srow[p];
        __half2 v = __hadd2(u2h(g_Yh[(size_t)nc * 256 + cb]),
                            u2h(g_Yh[(size_t)nr * 256 + 128 + cb]));
        float2 f = __half22float2(v);
        Sx += f.x; Qx += f.x * f.x;
        Sy += f.y; Qy += f.y * f.y;
    }
    __shared__ float4 sS[256];
    sS[t] = make_float4(Sx, Sy, Qx, Qy);
    __syncthreads();
    for (int h2 = 128; h2 >= 32; h2 >>= 1) {
        if (t < h2) {
            float4 o = sS[t + h2];
            sS[t].x += o.x; sS[t].y += o.y; sS[t].z += o.z; sS[t].w += o.w;
        }
        __syncthreads();
    }
    if (t < 32) {
        float4 v = sS[t];
        float cnt = (float)max(eend - s, 1);
        float mx = v.x / cnt, my = v.y / cnt;
        float ivx = rsqrtf(v.z / cnt - mx * mx + EPS_IN);
        float ivy = rsqrtf(v.w / cnt - my * my + EPS_IN);
        g_iv1h  [g * 128 + c0u + t] = h2bits(ivx, ivy);
        g_nmiv1h[g * 128 + c0u + t] = h2bits(-mx * ivx, -my * ivy);
    }
}

// ---------------- GEMM2: single fp16 mma, half2 SIMD gather, 2 CTAs/SM ----------------
// smem bytes: [0) B frags 33792 | [33792) A fp16 rows 65536.  total 99328.
__global__ __launch_bounds__(512, 2) void k_gemm2_mma(const float* __restrict__ W2)
{
    extern __shared__ u32 sm[];
    u32* sB = sm;
    char* cA = (char*)sm + 33792;
    u32 aA = smem_u32(cA);

    int tid = threadIdx.x;
    // B frags: convert W2 fp32 -> fp16 fragments in-CTA
    for (int i = tid; i < 8192; i += 512) {
        int a = i >> 6, l = (i >> 1) & 31, r = i & 1;
        int ng = a >> 4, ki = a & 15;
        int k = ki * 16 + (l & 3) * 2 + r * 8;
        int n = ng * 8 + (l >> 2);
        sB[a * 66 + (i & 63)] = h2bits(W2[k * 64 + n], W2[(k + 1) * 64 + n]);
    }

    int w = tid >> 5, lane = tid & 31;
    int wm = w & 3, wn = w >> 2;
    int q = tid >> 7, m = tid & 127;
    int msw = m & 7;
    int lt = lane >> 3, lr = lane & 7;
    int lrow8 = (lt & 1) * 8 + lr;
    int lth = lt >> 1;
    const __half2 hz = __float2half2_rn(0.f);

    __syncthreads();   // sB ready

    for (int tile = blockIdx.x; tile < NT; tile += GRID2) {
        // ---- gather: half2 SIMD norm+relu -> swizzled rows ----
        {
            int pos = tile * 128 + m;
            int g = g_gid[pos];
            int nc = g_scol[pos], nr = g_srow[pos];
            const uint4* yc = (const uint4*)(g_Yh + (size_t)nc * 256 + q * 32);
            const uint4* yr = (const uint4*)(g_Yh + (size_t)nr * 256 + 128 + q * 32);
            const uint4* hiv = (const uint4*)(g_iv1h   + g * 128 + q * 32);
            const uint4* hmv = (const uint4*)(g_nmiv1h + g * 128 + q * 32);
            #pragma unroll
            for (int jj = 0; jj < 8; jj++) {
                uint4 va = yc[jj], vb = yr[jj], vi = hiv[jj], vm = hmv[jj];
                u32 o0 = h2u(__hmax2(__hfma2(__hadd2(u2h(va.x), u2h(vb.x)), u2h(vi.x), u2h(vm.x)), hz));
                u32 o1 = h2u(__hmax2(__hfma2(__hadd2(u2h(va.y), u2h(vb.y)), u2h(vi.y), u2h(vm.y)), hz));
                u32 o2 = h2u(__hmax2(__hfma2(__hadd2(u2h(va.z), u2h(vb.z)), u2h(vi.z), u2h(vm.z)), hz));
                u32 o3 = h2u(__hmax2(__hfma2(__hadd2(u2h(va.w), u2h(vb.w)), u2h(vi.w), u2h(vm.w)), hz));
                int oct = q * 8 + jj;
                int gran = m * 32 + (oct ^ msw);
                *(uint4*)(cA + gran * 16) = make_uint4(o0, o1, o2, o3);
            }
        }
        __syncthreads();
        // ---- mma ----
        float d[2][2][4];
        #pragma unroll
        for (int mi2 = 0; mi2 < 2; mi2++)
            #pragma unroll
            for (int ni = 0; ni < 2; ni++)
                #pragma unroll
                for (int r = 0; r < 4; r++) d[mi2][ni][r] = 0.f;

        #pragma unroll
        for (int ki = 0; ki < 16; ki++) {
            u32 ah[2][4];
            #pragma unroll
            for (int mi2 = 0; mi2 < 2; mi2++) {
                int ml = wm * 32 + mi2 * 16 + lrow8;
                int oct = 2 * ki + lth;
                u32 goff = (u32)(ml * 32 + (oct ^ (ml & 7))) * 16;
                ldm_x4(ah[mi2], aA + goff);
            }
            #pragma unroll
            for (int ni = 0; ni < 2; ni++) {
                int batom = ((wn * 2 + ni) * 16 + ki) * 66 + lane * 2;
                uint2 bv = *(const uint2*)(sB + batom);
                u32 bb[2] = {bv.x, bv.y};
                mma_f16(d[0][ni], ah[0], bb);
                mma_f16(d[1][ni], ah[1], bb);
            }
        }
        // ---- epilogue: pack fp16 -> g_x2h ----
        {
            int r0base = tile * 128 + wm * 32 + (lane >> 2);
            int cpb = wn * 8 + (lane & 3);
            #pragma unroll
            for (int mi2 = 0; mi2 < 2; mi2++) {
                size_t rA = (size_t)(r0base + mi2 * 16);
                size_t rB = rA + 8;
                #pragma unroll
                for (int ni = 0; ni < 2; ni++) {
                    g_x2h[rA * 32 + cpb + ni * 4] = h2bits(d[mi2][ni][0], d[mi2][ni][1]);
                    g_x2h[rB * 32 + cpb + ni * 4] = h2bits(d[mi2][ni][2], d[mi2][ni][3]);
                }
            }
        }
        __syncthreads();
    }
}

// ---------------- stats2 (fp16 x2) ----------------
__global__ void k_stats2() {
    int g = blockIdx.x;
    int t = threadIdx.x;
    int c2 = t & 31, r = t >> 5;
    int s = g_off[g], eend = g_off[g + 1];
    float Sx = 0.f, Sy = 0.f, Qx = 0.f, Qy = 0.f;
    for (int p = s + r; p < eend; p += 8) {
        float2 f = h22f2(g_x2h[(size_t)p * 32 + c2]);
        Sx += f.x; Qx += f.x * f.x;
        Sy += f.y; Qy += f.y * f.y;
    }
    __shared__ float4 sS[256];
    sS[t] = make_float4(Sx, Sy, Qx, Qy);
    __syncthreads();
    for (int h2 = 128; h2 >= 32; h2 >>= 1) {
        if (t < h2) {
            float4 o = sS[t + h2];
            sS[t].x += o.x; sS[t].y += o.y; sS[t].z += o.z; sS[t].w += o.w;
        }
        __syncthreads();
    }
    if (t < 32) {
        float4 v = sS[t];
        float cnt = (float)max(eend - s, 1);
        float mx = v.x / cnt, my = v.y / cnt;
        float ivx = rsqrtf(v.z / cnt - mx * mx + EPS_IN);
        float ivy = rsqrtf(v.w / cnt - my * my + EPS_IN);
        g_inv2 [g * C2 + t * 2]     = ivx;
        g_inv2 [g * C2 + t * 2 + 1] = ivy;
        g_miv2 [g * C2 + t * 2]     = mx * ivx;
        g_miv2 [g * C2 + t * 2 + 1] = my * ivy;
    }
}

// ---------------- final layer (fp16 x2) ----------------
__global__ void k_final(const float* __restrict__ W3, const float* __restrict__ b3,
                        float* __restrict__ out)
{
    __shared__ float sw[64];
    int tid = threadIdx.x;
    if (tid < 64) sw[tid] = W3[tid];
    __syncthreads();
    int pos = blockIdx.x * 128 + (tid >> 1);
    int half = tid & 1;
    float acc = 0.f;
    if (pos < E_EDGES) {
        int g = g_gid[pos];
        const uint4* xr = (const uint4*)(g_x2h + (size_t)pos * 32 + half * 16);
        const float4* vr = (const float4*)(g_inv2 + g * C2 + half * 32);
        const float4* mr = (const float4*)(g_miv2 + g * C2 + half * 32);
        #pragma unroll
        for (int j = 0; j < 4; j++) {
            uint4 xv = xr[j];
            float4 iv0 = vr[2 * j], iv1 = vr[2 * j + 1];
            float4 mv0 = mr[2 * j], mv1 = mr[2 * j + 1];
            float2 a0 = h22f2(xv.x), a1 = h22f2(xv.y);
            float2 a2 = h22f2(xv.z), a3 = h22f2(xv.w);
            int k = half * 32 + j * 8;
            acc += fmaxf(fmaf(a0.x, iv0.x, -mv0.x), 0.f) * sw[k]
                 + fmaxf(fmaf(a0.y, iv0.y, -mv0.y), 0.f) * sw[k + 1]
                 + fmaxf(fmaf(a1.x, iv0.z, -mv0.z), 0.f) * sw[k + 2]
                 + fmaxf(fmaf(a1.y, iv0.w, -mv0.w), 0.f) * sw[k + 3]
                 + fmaxf(fmaf(a2.x, iv1.x, -mv1.x), 0.f) * sw[k + 4]
                 + fmaxf(fmaf(a2.y, iv1.y, -mv1.y), 0.f) * sw[k + 5]
                 + fmaxf(fmaf(a3.x, iv1.z, -mv1.z), 0.f) * sw[k + 6]
                 + fmaxf(fmaf(a3.y, iv1.w, -mv1.w), 0.f) * sw[k + 7];
        }
    }
    float other = __shfl_xor_sync(0xffffffffu, acc, 1);
    if (half == 0 && pos < E_EDGES) out[g_perm[pos]] = acc + other + b3[0];
}

// ---------------- launch ----------------
extern "C" void kernel_launch(void* const* d_in, const int* in_sizes, int n_in,
                              void* d_out, int out_size)
{
    const float* emb   = (const float*)d_in[0];
    const float* W1    = (const float*)d_in[1];
    const float* W2    = (const float*)d_in[3];
    const float* W3    = (const float*)d_in[5];
    const float* b3    = (const float*)d_in[6];
    const int*   ei    = (const int*)d_in[7];
    const int*   batch = (const int*)d_in[8];
    const int* col = ei;
    const int* row = ei + E_EDGES;
    float* out = (float*)d_out;

    static int attr_set = 0;
    if (!attr_set) {
        cudaFuncSetAttribute(k_gemm2_mma, cudaFuncAttributeMaxDynamicSharedMemorySize, 99328);
        cudaFuncSetAttribute(k_emb_mma, cudaFuncAttributeMaxDynamicSharedMemorySize, 50176);
        attr_set = 1;
    }

    k_hist<<<1024, 256>>>(col, batch);
    k_emb_mma<<<dim3((NN + 127) / 128, 2), 512, 50176>>>(emb, W1);
    k_scan<<<1, 512>>>();
    k_scatter<<<(E_EDGES + 2047) / 2048, 256>>>(col, row, batch);
    k_stats1g<<<NG * 4, 256>>>();
    k_gemm2_mma<<<GRID2, 512, 99328>>>(W2);
    k_stats2<<<NG, 256>>>();
    k_final<<<EP / 128, 256>>>(W3, b3, out);
}

// round 13
// speedup vs baseline: 2.4091x; 1.0445x over previous
#include <cuda_runtime.h>
#include <cuda_fp16.h>
#include <cstdint>

// ExtractorMLP: per-edge MLP 128->256->64->1 with per-graph instance norm.
// R13: (a) emb_mma forked onto a side stream, overlapping the sort chain
//      inside the captured graph; (b) per-edge metadata packed into one int4
//      (1 LDG.128 / 1 STG.128 instead of 3-4 scattered 4B accesses).

#define E_EDGES 1000000
#define EP      1000064   // multiple of 128
#define NG      512
#define NN      50000
#define C1      256
#define C2      64
#define EPS_IN  1e-5f
#define NT      (EP / 128)   // 7813
#define GRID2   296          // 148 SMs x 2 CTAs

typedef unsigned long long ull;
typedef unsigned int u32;

// ---------------- scratch ----------------
__device__ u32   g_Yh[(size_t)NN * 256];   // 51 MB, half2-packed Y
__device__ u32   g_x2h[(size_t)EP * 32];   // 128 MB, half2-packed x2
__device__ int4  g_meta[EP];               // {perm, gid, col, row} per sorted pos
__device__ int   g_cnt[NG];                // invariant: zero at kernel_launch entry
__device__ int   g_off[NG + 1];
__device__ int   g_cur[NG];
__device__ u32   g_iv1h [NG * 128];        // half2-packed inv1
__device__ u32   g_nmiv1h[NG * 128];       // half2-packed NEGATED mean1*inv1
__device__ float g_inv2 [NG * C2];
__device__ float g_miv2 [NG * C2];

// ---------------- helpers ----------------
__device__ __forceinline__ u32 h2bits(float x, float y) {
    __half2 h = __floats2half2_rn(x, y);
    return *reinterpret_cast<u32*>(&h);
}
__device__ __forceinline__ __half2 u2h(u32 v) {
    return *reinterpret_cast<__half2*>(&v);
}
__device__ __forceinline__ u32 h2u(__half2 h) {
    return *reinterpret_cast<u32*>(&h);
}
__device__ __forceinline__ float2 h22f2(u32 v) {
    __half2 h = *reinterpret_cast<__half2*>(&v);
    return __half22float2(h);
}
__device__ __forceinline__ void mma_f16(float* d, const u32* a, const u32* b) {
    asm volatile(
        "mma.sync.aligned.m16n8k16.row.col.f32.f16.f16.f32 "
        "{%0,%1,%2,%3}, {%4,%5,%6,%7}, {%8,%9}, {%0,%1,%2,%3};"
        : "+f"(d[0]), "+f"(d[1]), "+f"(d[2]), "+f"(d[3])
        : "r"(a[0]), "r"(a[1]), "r"(a[2]), "r"(a[3]), "r"(b[0]), "r"(b[1]));
}
__device__ __forceinline__ void ldm_x4(u32* r, u32 addr) {
    asm volatile("ldmatrix.sync.aligned.m8n8.x4.shared.b16 {%0,%1,%2,%3}, [%4];"
        : "=r"(r[0]), "=r"(r[1]), "=r"(r[2]), "=r"(r[3]) : "r"(addr));
}
__device__ __forceinline__ u32 smem_u32(const void* p) {
    u32 a;
    asm("{ .reg .u64 t; cvta.to.shared.u64 t, %1; cvt.u32.u64 %0, t; }"
        : "=r"(a) : "l"(p));
    return a;
}

// ---------------- sort pipeline ----------------
__global__ void k_hist(const int* __restrict__ col, const int* __restrict__ batch) {
    __shared__ int h[NG];
    int t = threadIdx.x;
    for (int g = t; g < NG; g += blockDim.x) h[g] = 0;
    __syncthreads();
    int idx = blockIdx.x * blockDim.x + t;
    int stride = gridDim.x * blockDim.x;
    for (int e = idx; e < E_EDGES; e += stride)
        atomicAdd(&h[batch[col[e]]], 1);
    __syncthreads();
    for (int g = t; g < NG; g += blockDim.x)
        if (h[g]) atomicAdd(&g_cnt[g], h[g]);
}

__global__ void k_scan() {
    __shared__ int s[NG];
    int t = threadIdx.x;
    int c = g_cnt[t];
    s[t] = c;
    __syncthreads();
    for (int o = 1; o < NG; o <<= 1) {
        int v = (t >= o) ? s[t - o] : 0;
        __syncthreads();
        s[t] += v;
        __syncthreads();
    }
    int excl = s[t] - c;
    g_off[t] = excl;
    g_cur[t] = excl;
    if (t == NG - 1) g_off[NG] = s[t];
    g_cnt[t] = 0;                       // restore invariant for next replay
    if (t < (EP - E_EDGES))             // padding entries (idempotent)
        g_meta[E_EDGES + t] = make_int4(0, 0, 0, 0);
}

__global__ void k_scatter(const int* __restrict__ col, const int* __restrict__ row,
                          const int* __restrict__ batch) {
    __shared__ int sg[2048], sc[2048];
    __shared__ int hist[NG], base_[NG], cnt2[NG];
    int t = threadIdx.x;
    for (int g = t; g < NG; g += 256) { hist[g] = 0; cnt2[g] = 0; }
    __syncthreads();
    int e0 = blockIdx.x * 2048;
    #pragma unroll
    for (int j = 0; j < 8; j++) {
        int e = e0 + t + j * 256;
        int g = -1, c = 0;
        if (e < E_EDGES) {
            c = col[e];
            g = batch[c];
            atomicAdd(&hist[g], 1);
        }
        sg[t + j * 256] = g;
        sc[t + j * 256] = c;
    }
    __syncthreads();
    for (int g = t; g < NG; g += 256)
        if (hist[g]) base_[g] = atomicAdd(&g_cur[g], hist[g]);
    __syncthreads();
    #pragma unroll
    for (int j = 0; j < 8; j++) {
        int e = e0 + t + j * 256;
        if (e < E_EDGES) {
            int g = sg[t + j * 256];
            int l = atomicAdd(&cnt2[g], 1);
            g_meta[base_[g] + l] = make_int4(e, g, sc[t + j * 256], row[e]);
        }
    }
}

// ---------------- Y = emb @ [W1top | W1bot], fp16 mma ----------------
__global__ __launch_bounds__(512) void k_emb_mma(const float* __restrict__ emb,
                                                 const float* __restrict__ W1)
{
    extern __shared__ u32 sm[];
    u32* sB = sm;
    char* cA = (char*)sm + 33792;
    u32 aA = smem_u32(cA);

    int tid = threadIdx.x;
    int half = blockIdx.y;
    int nb = blockIdx.x * 128;

    for (int i = tid; i < 8192; i += 512) {
        int a = i >> 6, l = (i >> 1) & 31, r = i & 1;
        int ng = a >> 2, ki = a & 3;
        int k = ki * 16 + (l & 3) * 2 + r * 8;
        int n = ng * 8 + (l >> 2);
        const float* base = W1 + half * 64 * 256 + n;
        sB[a * 66 + (i & 63)] = h2bits(base[k * 256], base[(k + 1) * 256]);
    }
    {
        int m = tid >> 2, q = tid & 3;
        int node = nb + m, msw = m & 7;
        u32 h[8] = {0, 0, 0, 0, 0, 0, 0, 0};
        if (node < NN) {
            const float4* src = (const float4*)(emb + (size_t)node * 64 + q * 16);
            float4 v0 = src[0], v1 = src[1], v2 = src[2], v3 = src[3];
            h[0] = h2bits(v0.x, v0.y); h[1] = h2bits(v0.z, v0.w);
            h[2] = h2bits(v1.x, v1.y); h[3] = h2bits(v1.z, v1.w);
            h[4] = h2bits(v2.x, v2.y); h[5] = h2bits(v2.z, v2.w);
            h[6] = h2bits(v3.x, v3.y); h[7] = h2bits(v3.z, v3.w);
        }
        *(uint4*)(cA + (m * 8 + ((q * 2)     ^ msw)) * 16) = make_uint4(h[0], h[1], h[2], h[3]);
        *(uint4*)(cA + (m * 8 + ((q * 2 + 1) ^ msw)) * 16) = make_uint4(h[4], h[5], h[6], h[7]);
    }
    __syncthreads();

    int w = tid >> 5, lane = tid & 31;
    int wm = w & 3, wn = w >> 2;
    int lt = lane >> 3, lr = lane & 7;
    int lrow8 = (lt & 1) * 8 + lr, lth = lt >> 1;

    float d[2][8][4];
    #pragma unroll
    for (int a = 0; a < 2; a++)
        #pragma unroll
        for (int b = 0; b < 8; b++)
            #pragma unroll
            for (int c = 0; c < 4; c++) d[a][b][c] = 0.f;

    #pragma unroll
    for (int ki = 0; ki < 4; ki++) {
        u32 ah[2][4];
        #pragma unroll
        for (int mi2 = 0; mi2 < 2; mi2++) {
            int ml = wm * 32 + mi2 * 16 + lrow8;
            int oct = 2 * ki + lth;
            u32 goff = (u32)(ml * 8 + (oct ^ (ml & 7))) * 16;
            ldm_x4(ah[mi2], aA + goff);
        }
        #pragma unroll
        for (int ni = 0; ni < 8; ni++) {
            int batom = ((wn * 8 + ni) * 4 + ki) * 66 + lane * 2;
            uint2 bv = *(const uint2*)(sB + batom);
            u32 bb[2] = {bv.x, bv.y};
            mma_f16(d[0][ni], ah[0], bb);
            mma_f16(d[1][ni], ah[1], bb);
        }
    }
    {
        int r0 = nb + wm * 32 + (lane >> 2);
        int cpb = (half * 256 + wn * 64 + (lane & 3) * 2) >> 1;
        #pragma unroll
        for (int mi2 = 0; mi2 < 2; mi2++) {
            int rA = r0 + mi2 * 16, rB = rA + 8;
            if (rA < NN) {
                #pragma unroll
                for (int ni = 0; ni < 8; ni++)
                    g_Yh[(size_t)rA * 256 + cpb + ni * 4] = h2bits(d[mi2][ni][0], d[mi2][ni][1]);
            }
            if (rB < NN) {
                #pragma unroll
                for (int ni = 0; ni < 8; ni++)
                    g_Yh[(size_t)rB * 256 + cpb + ni * 4] = h2bits(d[mi2][ni][2], d[mi2][ni][3]);
            }
        }
    }
}

// ---------------- stats1: per (graph, 64-ch chunk), gather fp16 Y ----------------
__global__ void k_stats1g() {
    int g  = blockIdx.x >> 2;
    int c0u = (blockIdx.x & 3) * 32;
    int t = threadIdx.x;
    int c2 = t & 31, r = t >> 5;
    int s = g_off[g], eend = g_off[g + 1];
    float Sx = 0.f, Sy = 0.f, Qx = 0.f, Qy = 0.f;
    int cb = c0u + c2;
    for (int p = s + r; p < eend; p += 8) {
        int4 md = g_meta[p];
        __half2 v = __hadd2(u2h(g_Yh[(size_t)md.z * 256 + cb]),
                            u2h(g_Yh[(size_t)md.w * 256 + 128 + cb]));
        float2 f = __half22float2(v);
        Sx += f.x; Qx += f.x * f.x;
        Sy += f.y; Qy += f.y * f.y;
    }
    __shared__ float4 sS[256];
    sS[t] = make_float4(Sx, Sy, Qx, Qy);
    __syncthreads();
    for (int h2 = 128; h2 >= 32; h2 >>= 1) {
        if (t < h2) {
            float4 o = sS[t + h2];
            sS[t].x += o.x; sS[t].y += o.y; sS[t].z += o.z; sS[t].w += o.w;
        }
        __syncthreads();
    }
    if (t < 32) {
        float4 v = sS[t];
        float cnt = (float)max(eend - s, 1);
        float mx = v.x / cnt, my = v.y / cnt;
        float ivx = rsqrtf(v.z / cnt - mx * mx + EPS_IN);
        float ivy = rsqrtf(v.w / cnt - my * my + EPS_IN);
        g_iv1h  [g * 128 + c0u + t] = h2bits(ivx, ivy);
        g_nmiv1h[g * 128 + c0u + t] = h2bits(-mx * ivx, -my * ivy);
    }
}

// ---------------- GEMM2: single fp16 mma, half2 SIMD gather, 2 CTAs/SM ----------------
__global__ __launch_bounds__(512, 2) void k_gemm2_mma(const float* __restrict__ W2)
{
    extern __shared__ u32 sm[];
    u32* sB = sm;
    char* cA = (char*)sm + 33792;
    u32 aA = smem_u32(cA);

    int tid = threadIdx.x;
    for (int i = tid; i < 8192; i += 512) {
        int a = i >> 6, l = (i >> 1) & 31, r = i & 1;
        int ng = a >> 4, ki = a & 15;
        int k = ki * 16 + (l & 3) * 2 + r * 8;
        int n = ng * 8 + (l >> 2);
        sB[a * 66 + (i & 63)] = h2bits(W2[k * 64 + n], W2[(k + 1) * 64 + n]);
    }

    int w = tid >> 5, lane = tid & 31;
    int wm = w & 3, wn = w >> 2;
    int q = tid >> 7, m = tid & 127;
    int msw = m & 7;
    int lt = lane >> 3, lr = lane & 7;
    int lrow8 = (lt & 1) * 8 + lr;
    int lth = lt >> 1;
    const __half2 hz = __float2half2_rn(0.f);

    __syncthreads();   // sB ready

    for (int tile = blockIdx.x; tile < NT; tile += GRID2) {
        {
            int pos = tile * 128 + m;
            int4 md = g_meta[pos];
            int g = md.y, nc = md.z, nr = md.w;
            const uint4* yc = (const uint4*)(g_Yh + (size_t)nc * 256 + q * 32);
            const uint4* yr = (const uint4*)(g_Yh + (size_t)nr * 256 + 128 + q * 32);
            const uint4* hiv = (const uint4*)(g_iv1h   + g * 128 + q * 32);
            const uint4* hmv = (const uint4*)(g_nmiv1h + g * 128 + q * 32);
            #pragma unroll
            for (int jj = 0; jj < 8; jj++) {
                uint4 va = yc[jj], vb = yr[jj], vi = hiv[jj], vm = hmv[jj];
                u32 o0 = h2u(__hmax2(__hfma2(__hadd2(u2h(va.x), u2h(vb.x)), u2h(vi.x), u2h(vm.x)), hz));
                u32 o1 = h2u(__hmax2(__hfma2(__hadd2(u2h(va.y), u2h(vb.y)), u2h(vi.y), u2h(vm.y)), hz));
                u32 o2 = h2u(__hmax2(__hfma2(__hadd2(u2h(va.z), u2h(vb.z)), u2h(vi.z), u2h(vm.z)), hz));
                u32 o3 = h2u(__hmax2(__hfma2(__hadd2(u2h(va.w), u2h(vb.w)), u2h(vi.w), u2h(vm.w)), hz));
                int oct = q * 8 + jj;
                int gran = m * 32 + (oct ^ msw);
                *(uint4*)(cA + gran * 16) = make_uint4(o0, o1, o2, o3);
            }
        }
        __syncthreads();
        float d[2][2][4];
        #pragma unroll
        for (int mi2 = 0; mi2 < 2; mi2++)
            #pragma unroll
            for (int ni = 0; ni < 2; ni++)
                #pragma unroll
                for (int r = 0; r < 4; r++) d[mi2][ni][r] = 0.f;

        #pragma unroll
        for (int ki = 0; ki < 16; ki++) {
            u32 ah[2][4];
            #pragma unroll
            for (int mi2 = 0; mi2 < 2; mi2++) {
                int ml = wm * 32 + mi2 * 16 + lrow8;
                int oct = 2 * ki + lth;
                u32 goff = (u32)(ml * 32 + (oct ^ (ml & 7))) * 16;
                ldm_x4(ah[mi2], aA + goff);
            }
            #pragma unroll
            for (int ni = 0; ni < 2; ni++) {
                int batom = ((wn * 2 + ni) * 16 + ki) * 66 + lane * 2;
                uint2 bv = *(const uint2*)(sB + batom);
                u32 bb[2] = {bv.x, bv.y};
                mma_f16(d[0][ni], ah[0], bb);
                mma_f16(d[1][ni], ah[1], bb);
            }
        }
        {
            int r0base = tile * 128 + wm * 32 + (lane >> 2);
            int cpb = wn * 8 + (lane & 3);
            #pragma unroll
            for (int mi2 = 0; mi2 < 2; mi2++) {
                size_t rA = (size_t)(r0base + mi2 * 16);
                size_t rB = rA + 8;
                #pragma unroll
                for (int ni = 0; ni < 2; ni++) {
                    g_x2h[rA * 32 + cpb + ni * 4] = h2bits(d[mi2][ni][0], d[mi2][ni][1]);
                    g_x2h[rB * 32 + cpb + ni * 4] = h2bits(d[mi2][ni][2], d[mi2][ni][3]);
                }
            }
        }
        __syncthreads();
    }
}

// ---------------- stats2 (fp16 x2) ----------------
__global__ void k_stats2() {
    int g = blockIdx.x;
    int t = threadIdx.x;
    int c2 = t & 31, r = t >> 5;
    int s = g_off[g], eend = g_off[g + 1];
    float Sx = 0.f, Sy = 0.f, Qx = 0.f, Qy = 0.f;
    for (int p = s + r; p < eend; p += 8) {
        float2 f = h22f2(g_x2h[(size_t)p * 32 + c2]);
        Sx += f.x; Qx += f.x * f.x;
        Sy += f.y; Qy += f.y * f.y;
    }
    __shared__ float4 sS[256];
    sS[t] = make_float4(Sx, Sy, Qx, Qy);
    __syncthreads();
    for (int h2 = 128; h2 >= 32; h2 >>= 1) {
        if (t < h2) {
            float4 o = sS[t + h2];
            sS[t].x += o.x; sS[t].y += o.y; sS[t].z += o.z; sS[t].w += o.w;
        }
        __syncthreads();
    }
    if (t < 32) {
        float4 v = sS[t];
        float cnt = (float)max(eend - s, 1);
        float mx = v.x / cnt, my = v.y / cnt;
        float ivx = rsqrtf(v.z / cnt - mx * mx + EPS_IN);
        float ivy = rsqrtf(v.w / cnt - my * my + EPS_IN);
        g_inv2 [g * C2 + t * 2]     = ivx;
        g_inv2 [g * C2 + t * 2 + 1] = ivy;
        g_miv2 [g * C2 + t * 2]     = mx * ivx;
        g_miv2 [g * C2 + t * 2 + 1] = my * ivy;
    }
}

// ---------------- final layer (fp16 x2) ----------------
__global__ void k_final(const float* __restrict__ W3, const float* __restrict__ b3,
                        float* __restrict__ out)
{
    __shared__ float sw[64];
    int tid = threadIdx.x;
    if (tid < 64) sw[tid] = W3[tid];
    __syncthreads();
    int pos = blockIdx.x * 128 + (tid >> 1);
    int half = tid & 1;
    float acc = 0.f;
    int perm = 0;
    if (pos < E_EDGES) {
        int4 md = g_meta[pos];
        perm = md.x;
        int g = md.y;
        const uint4* xr = (const uint4*)(g_x2h + (size_t)pos * 32 + half * 16);
        const float4* vr = (const float4*)(g_inv2 + g * C2 + half * 32);
        const float4* mr = (const float4*)(g_miv2 + g * C2 + half * 32);
        #pragma unroll
        for (int j = 0; j < 4; j++) {
            uint4 xv = xr[j];
            float4 iv0 = vr[2 * j], iv1 = vr[2 * j + 1];
            float4 mv0 = mr[2 * j], mv1 = mr[2 * j + 1];
            float2 a0 = h22f2(xv.x), a1 = h22f2(xv.y);
            float2 a2 = h22f2(xv.z), a3 = h22f2(xv.w);
            int k = half * 32 + j * 8;
            acc += fmaxf(fmaf(a0.x, iv0.x, -mv0.x), 0.f) * sw[k]
                 + fmaxf(fmaf(a0.y, iv0.y, -mv0.y), 0.f) * sw[k + 1]
                 + fmaxf(fmaf(a1.x, iv0.z, -mv0.z), 0.f) * sw[k + 2]
                 + fmaxf(fmaf(a1.y, iv0.w, -mv0.w), 0.f) * sw[k + 3]
                 + fmaxf(fmaf(a2.x, iv1.x, -mv1.x), 0.f) * sw[k + 4]
                 + fmaxf(fmaf(a2.y, iv1.y, -mv1.y), 0.f) * sw[k + 5]
                 + fmaxf(fmaf(a3.x, iv1.z, -mv1.z), 0.f) * sw[k + 6]
                 + fmaxf(fmaf(a3.y, iv1.w, -mv1.w), 0.f) * sw[k + 7];
        }
    }
    float other = __shfl_xor_sync(0xffffffffu, acc, 1);
    if (half == 0 && pos < E_EDGES) out[perm] = acc + other + b3[0];
}

// ---------------- launch ----------------
extern "C" void kernel_launch(void* const* d_in, const int* in_sizes, int n_in,
                              void* d_out, int out_size)
{
    const float* emb   = (const float*)d_in[0];
    const float* W1    = (const float*)d_in[1];
    const float* W2    = (const float*)d_in[3];
    const float* W3    = (const float*)d_in[5];
    const float* b3    = (const float*)d_in[6];
    const int*   ei    = (const int*)d_in[7];
    const int*   batch = (const int*)d_in[8];
    const int* col = ei;
    const int* row = ei + E_EDGES;
    float* out = (float*)d_out;

    static cudaStream_t s2;
    static cudaEvent_t ev1, ev2;
    static int init_done = 0;
    if (!init_done) {
        cudaFuncSetAttribute(k_gemm2_mma, cudaFuncAttributeMaxDynamicSharedMemorySize, 99328);
        cudaFuncSetAttribute(k_emb_mma, cudaFuncAttributeMaxDynamicSharedMemorySize, 50176);
        cudaStreamCreateWithFlags(&s2, cudaStreamNonBlocking);
        cudaEventCreateWithFlags(&ev1, cudaEventDisableTiming);
        cudaEventCreateWithFlags(&ev2, cudaEventDisableTiming);
        init_done = 1;
    }

    // fork: emb_mma on side stream overlaps hist/scan/scatter on main stream
    cudaEventRecord(ev1, 0);
    cudaStreamWaitEvent(s2, ev1, 0);
    k_emb_mma<<<dim3((NN + 127) / 128, 2), 512, 50176, s2>>>(emb, W1);
    cudaEventRecord(ev2, s2);

    k_hist<<<1024, 256>>>(col, batch);
    k_scan<<<1, 512>>>();
    k_scatter<<<(E_EDGES + 2047) / 2048, 256>>>(col, row, batch);

    cudaStreamWaitEvent(0, ev2, 0);   // join before stats1g (needs Y + sorted meta)
    k_stats1g<<<NG * 4, 256>>>();
    k_gemm2_mma<<<GRID2, 512, 99328>>>(W2);
    k_stats2<<<NG, 256>>>();
    k_final<<<EP / 128, 256>>>(W3, b3, out);
}

// round 14
// speedup vs baseline: 2.4362x; 1.0112x over previous
#include <cuda_runtime.h>
#include <cuda_fp16.h>
#include <cstdint>

// ExtractorMLP: per-edge MLP 128->256->64->1 with per-graph instance norm.
// R14: gemm2 next-tile meta prefetch + sync moved before epilogue (store/gather
//      overlap); stats1g widened to LDG.64 with 16 rows in flight.

#define E_EDGES 1000000
#define EP      1000064   // multiple of 128
#define NG      512
#define NN      50000
#define C1      256
#define C2      64
#define EPS_IN  1e-5f
#define NT      (EP / 128)   // 7813
#define GRID2   296          // 148 SMs x 2 CTAs

typedef unsigned long long ull;
typedef unsigned int u32;

// ---------------- scratch ----------------
__device__ u32   g_Yh[(size_t)NN * 256];   // 51 MB, half2-packed Y
__device__ u32   g_x2h[(size_t)EP * 32];   // 128 MB, half2-packed x2
__device__ int4  g_meta[EP];               // {perm, gid, col, row} per sorted pos
__device__ int   g_cnt[NG];                // invariant: zero at kernel_launch entry
__device__ int   g_off[NG + 1];
__device__ int   g_cur[NG];
__device__ u32   g_iv1h [NG * 128];        // half2-packed inv1
__device__ u32   g_nmiv1h[NG * 128];       // half2-packed NEGATED mean1*inv1
__device__ float g_inv2 [NG * C2];
__device__ float g_miv2 [NG * C2];

// ---------------- helpers ----------------
__device__ __forceinline__ u32 h2bits(float x, float y) {
    __half2 h = __floats2half2_rn(x, y);
    return *reinterpret_cast<u32*>(&h);
}
__device__ __forceinline__ __half2 u2h(u32 v) {
    return *reinterpret_cast<__half2*>(&v);
}
__device__ __forceinline__ u32 h2u(__half2 h) {
    return *reinterpret_cast<u32*>(&h);
}
__device__ __forceinline__ float2 h22f2(u32 v) {
    __half2 h = *reinterpret_cast<__half2*>(&v);
    return __half22float2(h);
}
__device__ __forceinline__ void mma_f16(float* d, const u32* a, const u32* b) {
    asm volatile(
        "mma.sync.aligned.m16n8k16.row.col.f32.f16.f16.f32 "
        "{%0,%1,%2,%3}, {%4,%5,%6,%7}, {%8,%9}, {%0,%1,%2,%3};"
        : "+f"(d[0]), "+f"(d[1]), "+f"(d[2]), "+f"(d[3])
        : "r"(a[0]), "r"(a[1]), "r"(a[2]), "r"(a[3]), "r"(b[0]), "r"(b[1]));
}
__device__ __forceinline__ void ldm_x4(u32* r, u32 addr) {
    asm volatile("ldmatrix.sync.aligned.m8n8.x4.shared.b16 {%0,%1,%2,%3}, [%4];"
        : "=r"(r[0]), "=r"(r[1]), "=r"(r[2]), "=r"(r[3]) : "r"(addr));
}
__device__ __forceinline__ u32 smem_u32(const void* p) {
    u32 a;
    asm("{ .reg .u64 t; cvta.to.shared.u64 t, %1; cvt.u32.u64 %0, t; }"
        : "=r"(a) : "l"(p));
    return a;
}

// ---------------- sort pipeline ----------------
__global__ void k_hist(const int* __restrict__ col, const int* __restrict__ batch) {
    __shared__ int h[NG];
    int t = threadIdx.x;
    for (int g = t; g < NG; g += blockDim.x) h[g] = 0;
    __syncthreads();
    int idx = blockIdx.x * blockDim.x + t;
    int stride = gridDim.x * blockDim.x;
    for (int e = idx; e < E_EDGES; e += stride)
        atomicAdd(&h[batch[col[e]]], 1);
    __syncthreads();
    for (int g = t; g < NG; g += blockDim.x)
        if (h[g]) atomicAdd(&g_cnt[g], h[g]);
}

__global__ void k_scan() {
    __shared__ int s[NG];
    int t = threadIdx.x;
    int c = g_cnt[t];
    s[t] = c;
    __syncthreads();
    for (int o = 1; o < NG; o <<= 1) {
        int v = (t >= o) ? s[t - o] : 0;
        __syncthreads();
        s[t] += v;
        __syncthreads();
    }
    int excl = s[t] - c;
    g_off[t] = excl;
    g_cur[t] = excl;
    if (t == NG - 1) g_off[NG] = s[t];
    g_cnt[t] = 0;                       // restore invariant for next replay
    if (t < (EP - E_EDGES))             // padding entries (idempotent)
        g_meta[E_EDGES + t] = make_int4(0, 0, 0, 0);
}

__global__ void k_scatter(const int* __restrict__ col, const int* __restrict__ row,
                          const int* __restrict__ batch) {
    __shared__ int sg[2048], sc[2048];
    __shared__ int hist[NG], base_[NG], cnt2[NG];
    int t = threadIdx.x;
    for (int g = t; g < NG; g += 256) { hist[g] = 0; cnt2[g] = 0; }
    __syncthreads();
    int e0 = blockIdx.x * 2048;
    #pragma unroll
    for (int j = 0; j < 8; j++) {
        int e = e0 + t + j * 256;
        int g = -1, c = 0;
        if (e < E_EDGES) {
            c = col[e];
            g = batch[c];
            atomicAdd(&hist[g], 1);
        }
        sg[t + j * 256] = g;
        sc[t + j * 256] = c;
    }
    __syncthreads();
    for (int g = t; g < NG; g += 256)
        if (hist[g]) base_[g] = atomicAdd(&g_cur[g], hist[g]);
    __syncthreads();
    #pragma unroll
    for (int j = 0; j < 8; j++) {
        int e = e0 + t + j * 256;
        if (e < E_EDGES) {
            int g = sg[t + j * 256];
            int l = atomicAdd(&cnt2[g], 1);
            g_meta[base_[g] + l] = make_int4(e, g, sc[t + j * 256], row[e]);
        }
    }
}

// ---------------- Y = emb @ [W1top | W1bot], fp16 mma ----------------
__global__ __launch_bounds__(512) void k_emb_mma(const float* __restrict__ emb,
                                                 const float* __restrict__ W1)
{
    extern __shared__ u32 sm[];
    u32* sB = sm;
    char* cA = (char*)sm + 33792;
    u32 aA = smem_u32(cA);

    int tid = threadIdx.x;
    int half = blockIdx.y;
    int nb = blockIdx.x * 128;

    for (int i = tid; i < 8192; i += 512) {
        int a = i >> 6, l = (i >> 1) & 31, r = i & 1;
        int ng = a >> 2, ki = a & 3;
        int k = ki * 16 + (l & 3) * 2 + r * 8;
        int n = ng * 8 + (l >> 2);
        const float* base = W1 + half * 64 * 256 + n;
        sB[a * 66 + (i & 63)] = h2bits(base[k * 256], base[(k + 1) * 256]);
    }
    {
        int m = tid >> 2, q = tid & 3;
        int node = nb + m, msw = m & 7;
        u32 h[8] = {0, 0, 0, 0, 0, 0, 0, 0};
        if (node < NN) {
            const float4* src = (const float4*)(emb + (size_t)node * 64 + q * 16);
            float4 v0 = src[0], v1 = src[1], v2 = src[2], v3 = src[3];
            h[0] = h2bits(v0.x, v0.y); h[1] = h2bits(v0.z, v0.w);
            h[2] = h2bits(v1.x, v1.y); h[3] = h2bits(v1.z, v1.w);
            h[4] = h2bits(v2.x, v2.y); h[5] = h2bits(v2.z, v2.w);
            h[6] = h2bits(v3.x, v3.y); h[7] = h2bits(v3.z, v3.w);
        }
        *(uint4*)(cA + (m * 8 + ((q * 2)     ^ msw)) * 16) = make_uint4(h[0], h[1], h[2], h[3]);
        *(uint4*)(cA + (m * 8 + ((q * 2 + 1) ^ msw)) * 16) = make_uint4(h[4], h[5], h[6], h[7]);
    }
    __syncthreads();

    int w = tid >> 5, lane = tid & 31;
    int wm = w & 3, wn = w >> 2;
    int lt = lane >> 3, lr = lane & 7;
    int lrow8 = (lt & 1) * 8 + lr, lth = lt >> 1;

    float d[2][8][4];
    #pragma unroll
    for (int a = 0; a < 2; a++)
        #pragma unroll
        for (int b = 0; b < 8; b++)
            #pragma unroll
            for (int c = 0; c < 4; c++) d[a][b][c] = 0.f;

    #pragma unroll
    for (int ki = 0; ki < 4; ki++) {
        u32 ah[2][4];
        #pragma unroll
        for (int mi2 = 0; mi2 < 2; mi2++) {
            int ml = wm * 32 + mi2 * 16 + lrow8;
            int oct = 2 * ki + lth;
            u32 goff = (u32)(ml * 8 + (oct ^ (ml & 7))) * 16;
            ldm_x4(ah[mi2], aA + goff);
        }
        #pragma unroll
        for (int ni = 0; ni < 8; ni++) {
            int batom = ((wn * 8 + ni) * 4 + ki) * 66 + lane * 2;
            uint2 bv = *(const uint2*)(sB + batom);
            u32 bb[2] = {bv.x, bv.y};
            mma_f16(d[0][ni], ah[0], bb);
            mma_f16(d[1][ni], ah[1], bb);
        }
    }
    {
        int r0 = nb + wm * 32 + (lane >> 2);
        int cpb = (half * 256 + wn * 64 + (lane & 3) * 2) >> 1;
        #pragma unroll
        for (int mi2 = 0; mi2 < 2; mi2++) {
            int rA = r0 + mi2 * 16, rB = rA + 8;
            if (rA < NN) {
                #pragma unroll
                for (int ni = 0; ni < 8; ni++)
                    g_Yh[(size_t)rA * 256 + cpb + ni * 4] = h2bits(d[mi2][ni][0], d[mi2][ni][1]);
            }
            if (rB < NN) {
                #pragma unroll
                for (int ni = 0; ni < 8; ni++)
                    g_Yh[(size_t)rB * 256 + cpb + ni * 4] = h2bits(d[mi2][ni][2], d[mi2][ni][3]);
            }
        }
    }
}

// ---------------- stats1: per (graph, 64-ch chunk), LDG.64 gather, 16 rows ----------------
__global__ void k_stats1g() {
    int g  = blockIdx.x >> 2;
    int c0u = (blockIdx.x & 3) * 32;     // u32 base within 128
    int t = threadIdx.x;
    int u2i = t & 15, r = t >> 4;        // uint2 index (16), row (16)
    int s = g_off[g], eend = g_off[g + 1];
    int cb = c0u + u2i * 2;
    float S0 = 0.f, S1 = 0.f, S2 = 0.f, S3 = 0.f;
    float Q0 = 0.f, Q1 = 0.f, Q2 = 0.f, Q3 = 0.f;
    for (int p = s + r; p < eend; p += 16) {
        int4 md = g_meta[p];
        uint2 a = *(const uint2*)(g_Yh + (size_t)md.z * 256 + cb);
        uint2 b = *(const uint2*)(g_Yh + (size_t)md.w * 256 + 128 + cb);
        float2 f0 = __half22float2(__hadd2(u2h(a.x), u2h(b.x)));
        float2 f1 = __half22float2(__hadd2(u2h(a.y), u2h(b.y)));
        S0 += f0.x; Q0 += f0.x * f0.x;
        S1 += f0.y; Q1 += f0.y * f0.y;
        S2 += f1.x; Q2 += f1.x * f1.x;
        S3 += f1.y; Q3 += f1.y * f1.y;
    }
    __shared__ float4 sS[256], sQ[256];
    sS[t] = make_float4(S0, S1, S2, S3);
    sQ[t] = make_float4(Q0, Q1, Q2, Q3);
    __syncthreads();
    for (int h2 = 128; h2 >= 16; h2 >>= 1) {
        if (t < h2) {
            float4 oS = sS[t + h2], oQ = sQ[t + h2];
            sS[t].x += oS.x; sS[t].y += oS.y; sS[t].z += oS.z; sS[t].w += oS.w;
            sQ[t].x += oQ.x; sQ[t].y += oQ.y; sQ[t].z += oQ.z; sQ[t].w += oQ.w;
        }
        __syncthreads();
    }
    if (t < 16) {
        float4 vS = sS[t], vQ = sQ[t];
        float cnt = (float)max(eend - s, 1);
        float m0 = vS.x / cnt, m1 = vS.y / cnt, m2 = vS.z / cnt, m3 = vS.w / cnt;
        float i0 = rsqrtf(vQ.x / cnt - m0 * m0 + EPS_IN);
        float i1 = rsqrtf(vQ.y / cnt - m1 * m1 + EPS_IN);
        float i2 = rsqrtf(vQ.z / cnt - m2 * m2 + EPS_IN);
        float i3 = rsqrtf(vQ.w / cnt - m3 * m3 + EPS_IN);
        int cw = c0u + t * 2;
        g_iv1h  [g * 128 + cw]     = h2bits(i0, i1);
        g_iv1h  [g * 128 + cw + 1] = h2bits(i2, i3);
        g_nmiv1h[g * 128 + cw]     = h2bits(-m0 * i0, -m1 * i1);
        g_nmiv1h[g * 128 + cw + 1] = h2bits(-m2 * i2, -m3 * i3);
    }
}

// ---------------- GEMM2: fp16 mma, meta prefetch, store/gather overlap ----------------
__global__ __launch_bounds__(512, 2) void k_gemm2_mma(const float* __restrict__ W2)
{
    extern __shared__ u32 sm[];
    u32* sB = sm;
    char* cA = (char*)sm + 33792;
    u32 aA = smem_u32(cA);

    int tid = threadIdx.x;
    for (int i = tid; i < 8192; i += 512) {
        int a = i >> 6, l = (i >> 1) & 31, r = i & 1;
        int ng = a >> 4, ki = a & 15;
        int k = ki * 16 + (l & 3) * 2 + r * 8;
        int n = ng * 8 + (l >> 2);
        sB[a * 66 + (i & 63)] = h2bits(W2[k * 64 + n], W2[(k + 1) * 64 + n]);
    }

    int w = tid >> 5, lane = tid & 31;
    int wm = w & 3, wn = w >> 2;
    int q = tid >> 7, m = tid & 127;
    int msw = m & 7;
    int lt = lane >> 3, lr = lane & 7;
    int lrow8 = (lt & 1) * 8 + lr;
    int lth = lt >> 1;
    const __half2 hz = __float2half2_rn(0.f);

    __syncthreads();   // sB ready

    int4 md = (blockIdx.x < NT) ? g_meta[blockIdx.x * 128 + m] : make_int4(0, 0, 0, 0);

    for (int tile = blockIdx.x; tile < NT; tile += GRID2) {
        // ---- gather (md prefetched): half2 SIMD norm+relu -> swizzled rows ----
        {
            int g = md.y, nc = md.z, nr = md.w;
            const uint4* yc = (const uint4*)(g_Yh + (size_t)nc * 256 + q * 32);
            const uint4* yr = (const uint4*)(g_Yh + (size_t)nr * 256 + 128 + q * 32);
            const uint4* hiv = (const uint4*)(g_iv1h   + g * 128 + q * 32);
            const uint4* hmv = (const uint4*)(g_nmiv1h + g * 128 + q * 32);
            #pragma unroll
            for (int jj = 0; jj < 8; jj++) {
                uint4 va = yc[jj], vb = yr[jj], vi = hiv[jj], vm = hmv[jj];
                u32 o0 = h2u(__hmax2(__hfma2(__hadd2(u2h(va.x), u2h(vb.x)), u2h(vi.x), u2h(vm.x)), hz));
                u32 o1 = h2u(__hmax2(__hfma2(__hadd2(u2h(va.y), u2h(vb.y)), u2h(vi.y), u2h(vm.y)), hz));
                u32 o2 = h2u(__hmax2(__hfma2(__hadd2(u2h(va.z), u2h(vb.z)), u2h(vi.z), u2h(vm.z)), hz));
                u32 o3 = h2u(__hmax2(__hfma2(__hadd2(u2h(va.w), u2h(vb.w)), u2h(vi.w), u2h(vm.w)), hz));
                int oct = q * 8 + jj;
                int gran = m * 32 + (oct ^ msw);
                *(uint4*)(cA + gran * 16) = make_uint4(o0, o1, o2, o3);
            }
        }
        __syncthreads();
        // prefetch next tile's meta (hides one L2 round trip under mma)
        int nt = tile + GRID2;
        if (nt < NT) md = g_meta[nt * 128 + m];
        // ---- mma ----
        float d[2][2][4];
        #pragma unroll
        for (int mi2 = 0; mi2 < 2; mi2++)
            #pragma unroll
            for (int ni = 0; ni < 2; ni++)
                #pragma unroll
                for (int r = 0; r < 4; r++) d[mi2][ni][r] = 0.f;

        #pragma unroll
        for (int ki = 0; ki < 16; ki++) {
            u32 ah[2][4];
            #pragma unroll
            for (int mi2 = 0; mi2 < 2; mi2++) {
                int ml = wm * 32 + mi2 * 16 + lrow8;
                int oct = 2 * ki + lth;
                u32 goff = (u32)(ml * 32 + (oct ^ (ml & 7))) * 16;
                ldm_x4(ah[mi2], aA + goff);
            }
            #pragma unroll
            for (int ni = 0; ni < 2; ni++) {
                int batom = ((wn * 2 + ni) * 16 + ki) * 66 + lane * 2;
                uint2 bv = *(const uint2*)(sB + batom);
                u32 bb[2] = {bv.x, bv.y};
                mma_f16(d[0][ni], ah[0], bb);
                mma_f16(d[1][ni], ah[1], bb);
            }
        }
        __syncthreads();   // A consumed; next gather may overwrite. Epilogue below
                           // uses only registers, so its STGs overlap next gather.
        {
            int r0base = tile * 128 + wm * 32 + (lane >> 2);
            int cpb = wn * 8 + (lane & 3);
            #pragma unroll
            for (int mi2 = 0; mi2 < 2; mi2++) {
                size_t rA = (size_t)(r0base + mi2 * 16);
                size_t rB = rA + 8;
                #pragma unroll
                for (int ni = 0; ni < 2; ni++) {
                    g_x2h[rA * 32 + cpb + ni * 4] = h2bits(d[mi2][ni][0], d[mi2][ni][1]);
                    g_x2h[rB * 32 + cpb + ni * 4] = h2bits(d[mi2][ni][2], d[mi2][ni][3]);
                }
            }
        }
    }
}

// ---------------- stats2 (fp16 x2) ----------------
__global__ void k_stats2() {
    int g = blockIdx.x;
    int t = threadIdx.x;
    int c2 = t & 31, r = t >> 5;
    int s = g_off[g], eend = g_off[g + 1];
    float Sx = 0.f, Sy = 0.f, Qx = 0.f, Qy = 0.f;
    for (int p = s + r; p < eend; p += 8) {
        float2 f = h22f2(g_x2h[(size_t)p * 32 + c2]);
        Sx += f.x; Qx += f.x * f.x;
        Sy += f.y; Qy += f.y * f.y;
    }
    __shared__ float4 sS[256];
    sS[t] = make_float4(Sx, Sy, Qx, Qy);
    __syncthreads();
    for (int h2 = 128; h2 >= 32; h2 >>= 1) {
        if (t < h2) {
            float4 o = sS[t + h2];
            sS[t].x += o.x; sS[t].y += o.y; sS[t].z += o.z; sS[t].w += o.w;
        }
        __syncthreads();
    }
    if (t < 32) {
        float4 v = sS[t];
        float cnt = (float)max(eend - s, 1);
        float mx = v.x / cnt, my = v.y / cnt;
        float ivx = rsqrtf(v.z / cnt - mx * mx + EPS_IN);
        float ivy = rsqrtf(v.w / cnt - my * my + EPS_IN);
        g_inv2 [g * C2 + t * 2]     = ivx;
        g_inv2 [g * C2 + t * 2 + 1] = ivy;
        g_miv2 [g * C2 + t * 2]     = mx * ivx;
        g_miv2 [g * C2 + t * 2 + 1] = my * ivy;
    }
}

// ---------------- final layer (fp16 x2) ----------------
__global__ void k_final(const float* __restrict__ W3, const float* __restrict__ b3,
                        float* __restrict__ out)
{
    __shared__ float sw[64];
    int tid = threadIdx.x;
    if (tid < 64) sw[tid] = W3[tid];
    __syncthreads();
    int pos = blockIdx.x * 128 + (tid >> 1);
    int half = tid & 1;
    float acc = 0.f;
    int perm = 0;
    if (pos < E_EDGES) {
        int4 md = g_meta[pos];
        perm = md.x;
        int g = md.y;
        const uint4* xr = (const uint4*)(g_x2h + (size_t)pos * 32 + half * 16);
        const float4* vr = (const float4*)(g_inv2 + g * C2 + half * 32);
        const float4* mr = (const float4*)(g_miv2 + g * C2 + half * 32);
        #pragma unroll
        for (int j = 0; j < 4; j++) {
            uint4 xv = xr[j];
            float4 iv0 = vr[2 * j], iv1 = vr[2 * j + 1];
            float4 mv0 = mr[2 * j], mv1 = mr[2 * j + 1];
            float2 a0 = h22f2(xv.x), a1 = h22f2(xv.y);
            float2 a2 = h22f2(xv.z), a3 = h22f2(xv.w);
            int k = half * 32 + j * 8;
            acc += fmaxf(fmaf(a0.x, iv0.x, -mv0.x), 0.f) * sw[k]
                 + fmaxf(fmaf(a0.y, iv0.y, -mv0.y), 0.f) * sw[k + 1]
                 + fmaxf(fmaf(a1.x, iv0.z, -mv0.z), 0.f) * sw[k + 2]
                 + fmaxf(fmaf(a1.y, iv0.w, -mv0.w), 0.f) * sw[k + 3]
                 + fmaxf(fmaf(a2.x, iv1.x, -mv1.x), 0.f) * sw[k + 4]
                 + fmaxf(fmaf(a2.y, iv1.y, -mv1.y), 0.f) * sw[k + 5]
                 + fmaxf(fmaf(a3.x, iv1.z, -mv1.z), 0.f) * sw[k + 6]
                 + fmaxf(fmaf(a3.y, iv1.w, -mv1.w), 0.f) * sw[k + 7];
        }
    }
    float other = __shfl_xor_sync(0xffffffffu, acc, 1);
    if (half == 0 && pos < E_EDGES) out[perm] = acc + other + b3[0];
}

// ---------------- launch ----------------
extern "C" void kernel_launch(void* const* d_in, const int* in_sizes, int n_in,
                              void* d_out, int out_size)
{
    const float* emb   = (const float*)d_in[0];
    const float* W1    = (const float*)d_in[1];
    const float* W2    = (const float*)d_in[3];
    const float* W3    = (const float*)d_in[5];
    const float* b3    = (const float*)d_in[6];
    const int*   ei    = (const int*)d_in[7];
    const int*   batch = (const int*)d_in[8];
    const int* col = ei;
    const int* row = ei + E_EDGES;
    float* out = (float*)d_out;

    static cudaStream_t s2;
    static cudaEvent_t ev1, ev2;
    static int init_done = 0;
    if (!init_done) {
        cudaFuncSetAttribute(k_gemm2_mma, cudaFuncAttributeMaxDynamicSharedMemorySize, 99328);
        cudaFuncSetAttribute(k_emb_mma, cudaFuncAttributeMaxDynamicSharedMemorySize, 50176);
        cudaStreamCreateWithFlags(&s2, cudaStreamNonBlocking);
        cudaEventCreateWithFlags(&ev1, cudaEventDisableTiming);
        cudaEventCreateWithFlags(&ev2, cudaEventDisableTiming);
        init_done = 1;
    }

    // fork: emb_mma on side stream overlaps hist/scan/scatter on main stream
    cudaEventRecord(ev1, 0);
    cudaStreamWaitEvent(s2, ev1, 0);
    k_emb_mma<<<dim3((NN + 127) / 128, 2), 512, 50176, s2>>>(emb, W1);
    cudaEventRecord(ev2, s2);

    k_hist<<<1024, 256>>>(col, batch);
    k_scan<<<1, 512>>>();
    k_scatter<<<(E_EDGES + 2047) / 2048, 256>>>(col, row, batch);

    cudaStreamWaitEvent(0, ev2, 0);   // join before stats1g (needs Y + sorted meta)
    k_stats1g<<<NG * 4, 256>>>();
    k_gemm2_mma<<<GRID2, 512, 99328>>>(W2);
    k_stats2<<<NG, 256>>>();
    k_final<<<EP / 128, 256>>>(W3, b3, out);
}

// round 15
// speedup vs baseline: 2.4837x; 1.0195x over previous
#include <cuda_runtime.h>
#include <cuda_fp16.h>
#include <cstdint>

// ExtractorMLP: per-edge MLP 128->256->64->1 with per-graph instance norm.
// R15: gemm2 warp-specialized: warps 0-7 gather tile t+1 while warps 8-15
//      run mma+epilogue on tile t, double-buffered A (1 CTA/SM, 161KB smem).
//      Avoids R8's same-warp STS-blocking and R9's register starvation.

#define E_EDGES 1000000
#define EP      1000064   // multiple of 128
#define NG      512
#define NN      50000
#define C1      256
#define C2      64
#define EPS_IN  1e-5f
#define NT      (EP / 128)   // 7813
#define GRID2   148

typedef unsigned long long ull;
typedef unsigned int u32;

// ---------------- scratch ----------------
__device__ u32   g_Yh[(size_t)NN * 256];   // 51 MB, half2-packed Y
__device__ u32   g_x2h[(size_t)EP * 32];   // 128 MB, half2-packed x2
__device__ int4  g_meta[EP];               // {perm, gid, col, row} per sorted pos
__device__ int   g_cnt[NG];                // invariant: zero at kernel_launch entry
__device__ int   g_off[NG + 1];
__device__ int   g_cur[NG];
__device__ u32   g_iv1h [NG * 128];        // half2-packed inv1
__device__ u32   g_nmiv1h[NG * 128];       // half2-packed NEGATED mean1*inv1
__device__ float g_inv2 [NG * C2];
__device__ float g_miv2 [NG * C2];

// ---------------- helpers ----------------
__device__ __forceinline__ u32 h2bits(float x, float y) {
    __half2 h = __floats2half2_rn(x, y);
    return *reinterpret_cast<u32*>(&h);
}
__device__ __forceinline__ __half2 u2h(u32 v) {
    return *reinterpret_cast<__half2*>(&v);
}
__device__ __forceinline__ u32 h2u(__half2 h) {
    return *reinterpret_cast<u32*>(&h);
}
__device__ __forceinline__ float2 h22f2(u32 v) {
    __half2 h = *reinterpret_cast<__half2*>(&v);
    return __half22float2(h);
}
__device__ __forceinline__ void mma_f16(float* d, const u32* a, const u32* b) {
    asm volatile(
        "mma.sync.aligned.m16n8k16.row.col.f32.f16.f16.f32 "
        "{%0,%1,%2,%3}, {%4,%5,%6,%7}, {%8,%9}, {%0,%1,%2,%3};"
        : "+f"(d[0]), "+f"(d[1]), "+f"(d[2]), "+f"(d[3])
        : "r"(a[0]), "r"(a[1]), "r"(a[2]), "r"(a[3]), "r"(b[0]), "r"(b[1]));
}
__device__ __forceinline__ void ldm_x4(u32* r, u32 addr) {
    asm volatile("ldmatrix.sync.aligned.m8n8.x4.shared.b16 {%0,%1,%2,%3}, [%4];"
        : "=r"(r[0]), "=r"(r[1]), "=r"(r[2]), "=r"(r[3]) : "r"(addr));
}
__device__ __forceinline__ u32 smem_u32(const void* p) {
    u32 a;
    asm("{ .reg .u64 t; cvta.to.shared.u64 t, %1; cvt.u32.u64 %0, t; }"
        : "=r"(a) : "l"(p));
    return a;
}

// ---------------- sort pipeline ----------------
__global__ void k_hist(const int* __restrict__ col, const int* __restrict__ batch) {
    __shared__ int h[NG];
    int t = threadIdx.x;
    for (int g = t; g < NG; g += blockDim.x) h[g] = 0;
    __syncthreads();
    int idx = blockIdx.x * blockDim.x + t;
    int stride = gridDim.x * blockDim.x;
    for (int e = idx; e < E_EDGES; e += stride)
        atomicAdd(&h[batch[col[e]]], 1);
    __syncthreads();
    for (int g = t; g < NG; g += blockDim.x)
        if (h[g]) atomicAdd(&g_cnt[g], h[g]);
}

__global__ void k_scan() {
    __shared__ int s[NG];
    int t = threadIdx.x;
    int c = g_cnt[t];
    s[t] = c;
    __syncthreads();
    for (int o = 1; o < NG; o <<= 1) {
        int v = (t >= o) ? s[t - o] : 0;
        __syncthreads();
        s[t] += v;
        __syncthreads();
    }
    int excl = s[t] - c;
    g_off[t] = excl;
    g_cur[t] = excl;
    if (t == NG - 1) g_off[NG] = s[t];
    g_cnt[t] = 0;                       // restore invariant for next replay
    if (t < (EP - E_EDGES))             // padding entries (idempotent)
        g_meta[E_EDGES + t] = make_int4(0, 0, 0, 0);
}

__global__ void k_scatter(const int* __restrict__ col, const int* __restrict__ row,
                          const int* __restrict__ batch) {
    __shared__ int sg[2048], sc[2048];
    __shared__ int hist[NG], base_[NG], cnt2[NG];
    int t = threadIdx.x;
    for (int g = t; g < NG; g += 256) { hist[g] = 0; cnt2[g] = 0; }
    __syncthreads();
    int e0 = blockIdx.x * 2048;
    #pragma unroll
    for (int j = 0; j < 8; j++) {
        int e = e0 + t + j * 256;
        int g = -1, c = 0;
        if (e < E_EDGES) {
            c = col[e];
            g = batch[c];
            atomicAdd(&hist[g], 1);
        }
        sg[t + j * 256] = g;
        sc[t + j * 256] = c;
    }
    __syncthreads();
    for (int g = t; g < NG; g += 256)
        if (hist[g]) base_[g] = atomicAdd(&g_cur[g], hist[g]);
    __syncthreads();
    #pragma unroll
    for (int j = 0; j < 8; j++) {
        int e = e0 + t + j * 256;
        if (e < E_EDGES) {
            int g = sg[t + j * 256];
            int l = atomicAdd(&cnt2[g], 1);
            g_meta[base_[g] + l] = make_int4(e, g, sc[t + j * 256], row[e]);
        }
    }
}

// ---------------- Y = emb @ [W1top | W1bot], fp16 mma ----------------
__global__ __launch_bounds__(512) void k_emb_mma(const float* __restrict__ emb,
                                                 const float* __restrict__ W1)
{
    extern __shared__ u32 sm[];
    u32* sB = sm;
    char* cA = (char*)sm + 33792;
    u32 aA = smem_u32(cA);

    int tid = threadIdx.x;
    int half = blockIdx.y;
    int nb = blockIdx.x * 128;

    for (int i = tid; i < 8192; i += 512) {
        int a = i >> 6, l = (i >> 1) & 31, r = i & 1;
        int ng = a >> 2, ki = a & 3;
        int k = ki * 16 + (l & 3) * 2 + r * 8;
        int n = ng * 8 + (l >> 2);
        const float* base = W1 + half * 64 * 256 + n;
        sB[a * 66 + (i & 63)] = h2bits(base[k * 256], base[(k + 1) * 256]);
    }
    {
        int m = tid >> 2, q = tid & 3;
        int node = nb + m, msw = m & 7;
        u32 h[8] = {0, 0, 0, 0, 0, 0, 0, 0};
        if (node < NN) {
            const float4* src = (const float4*)(emb + (size_t)node * 64 + q * 16);
            float4 v0 = src[0], v1 = src[1], v2 = src[2], v3 = src[3];
            h[0] = h2bits(v0.x, v0.y); h[1] = h2bits(v0.z, v0.w);
            h[2] = h2bits(v1.x, v1.y); h[3] = h2bits(v1.z, v1.w);
            h[4] = h2bits(v2.x, v2.y); h[5] = h2bits(v2.z, v2.w);
            h[6] = h2bits(v3.x, v3.y); h[7] = h2bits(v3.z, v3.w);
        }
        *(uint4*)(cA + (m * 8 + ((q * 2)     ^ msw)) * 16) = make_uint4(h[0], h[1], h[2], h[3]);
        *(uint4*)(cA + (m * 8 + ((q * 2 + 1) ^ msw)) * 16) = make_uint4(h[4], h[5], h[6], h[7]);
    }
    __syncthreads();

    int w = tid >> 5, lane = tid & 31;
    int wm = w & 3, wn = w >> 2;
    int lt = lane >> 3, lr = lane & 7;
    int lrow8 = (lt & 1) * 8 + lr, lth = lt >> 1;

    float d[2][8][4];
    #pragma unroll
    for (int a = 0; a < 2; a++)
        #pragma unroll
        for (int b = 0; b < 8; b++)
            #pragma unroll
            for (int c = 0; c < 4; c++) d[a][b][c] = 0.f;

    #pragma unroll
    for (int ki = 0; ki < 4; ki++) {
        u32 ah[2][4];
        #pragma unroll
        for (int mi2 = 0; mi2 < 2; mi2++) {
            int ml = wm * 32 + mi2 * 16 + lrow8;
            int oct = 2 * ki + lth;
            u32 goff = (u32)(ml * 8 + (oct ^ (ml & 7))) * 16;
            ldm_x4(ah[mi2], aA + goff);
        }
        #pragma unroll
        for (int ni = 0; ni < 8; ni++) {
            int batom = ((wn * 8 + ni) * 4 + ki) * 66 + lane * 2;
            uint2 bv = *(const uint2*)(sB + batom);
            u32 bb[2] = {bv.x, bv.y};
            mma_f16(d[0][ni], ah[0], bb);
            mma_f16(d[1][ni], ah[1], bb);
        }
    }
    {
        int r0 = nb + wm * 32 + (lane >> 2);
        int cpb = (half * 256 + wn * 64 + (lane & 3) * 2) >> 1;
        #pragma unroll
        for (int mi2 = 0; mi2 < 2; mi2++) {
            int rA = r0 + mi2 * 16, rB = rA + 8;
            if (rA < NN) {
                #pragma unroll
                for (int ni = 0; ni < 8; ni++)
                    g_Yh[(size_t)rA * 256 + cpb + ni * 4] = h2bits(d[mi2][ni][0], d[mi2][ni][1]);
            }
            if (rB < NN) {
                #pragma unroll
                for (int ni = 0; ni < 8; ni++)
                    g_Yh[(size_t)rB * 256 + cpb + ni * 4] = h2bits(d[mi2][ni][2], d[mi2][ni][3]);
            }
        }
    }
}

// ---------------- stats1: per (graph, 64-ch chunk), LDG.64 gather, 16 rows ----------------
__global__ void k_stats1g() {
    int g  = blockIdx.x >> 2;
    int c0u = (blockIdx.x & 3) * 32;     // u32 base within 128
    int t = threadIdx.x;
    int u2i = t & 15, r = t >> 4;        // uint2 index (16), row (16)
    int s = g_off[g], eend = g_off[g + 1];
    int cb = c0u + u2i * 2;
    float S0 = 0.f, S1 = 0.f, S2 = 0.f, S3 = 0.f;
    float Q0 = 0.f, Q1 = 0.f, Q2 = 0.f, Q3 = 0.f;
    for (int p = s + r; p < eend; p += 16) {
        int4 md = g_meta[p];
        uint2 a = *(const uint2*)(g_Yh + (size_t)md.z * 256 + cb);
        uint2 b = *(const uint2*)(g_Yh + (size_t)md.w * 256 + 128 + cb);
        float2 f0 = __half22float2(__hadd2(u2h(a.x), u2h(b.x)));
        float2 f1 = __half22float2(__hadd2(u2h(a.y), u2h(b.y)));
        S0 += f0.x; Q0 += f0.x * f0.x;
        S1 += f0.y; Q1 += f0.y * f0.y;
        S2 += f1.x; Q2 += f1.x * f1.x;
        S3 += f1.y; Q3 += f1.y * f1.y;
    }
    __shared__ float4 sS[256], sQ[256];
    sS[t] = make_float4(S0, S1, S2, S3);
    sQ[t] = make_float4(Q0, Q1, Q2, Q3);
    __syncthreads();
    for (int h2 = 128; h2 >= 16; h2 >>= 1) {
        if (t < h2) {
            float4 oS = sS[t + h2], oQ = sQ[t + h2];
            sS[t].x += oS.x; sS[t].y += oS.y; sS[t].z += oS.z; sS[t].w += oS.w;
            sQ[t].x += oQ.x; sQ[t].y += oQ.y; sQ[t].z += oQ.z; sQ[t].w += oQ.w;
        }
        __syncthreads();
    }
    if (t < 16) {
        float4 vS = sS[t], vQ = sQ[t];
        float cnt = (float)max(eend - s, 1);
        float m0 = vS.x / cnt, m1 = vS.y / cnt, m2 = vS.z / cnt, m3 = vS.w / cnt;
        float i0 = rsqrtf(vQ.x / cnt - m0 * m0 + EPS_IN);
        float i1 = rsqrtf(vQ.y / cnt - m1 * m1 + EPS_IN);
        float i2 = rsqrtf(vQ.z / cnt - m2 * m2 + EPS_IN);
        float i3 = rsqrtf(vQ.w / cnt - m3 * m3 + EPS_IN);
        int cw = c0u + t * 2;
        g_iv1h  [g * 128 + cw]     = h2bits(i0, i1);
        g_iv1h  [g * 128 + cw + 1] = h2bits(i2, i3);
        g_nmiv1h[g * 128 + cw]     = h2bits(-m0 * i0, -m1 * i1);
        g_nmiv1h[g * 128 + cw + 1] = h2bits(-m2 * i2, -m3 * i3);
    }
}

// ---------------- GEMM2: warp-specialized, double-buffered ----------------
// smem: [0) B frags 33792 | [33792) A buf0 65536 | [99328) A buf1 65536 = 164864.
// Warps 0-7 (tid<256): gather producers. Warps 8-15: mma consumers.
__device__ __forceinline__ void g2_fill(char* cA, int tile, int m, int hf) {
    int4 md = g_meta[tile * 128 + m];
    int g = md.y, nc = md.z, nr = md.w;
    const uint4* yc  = (const uint4*)(g_Yh + (size_t)nc * 256 + hf * 64);
    const uint4* yr  = (const uint4*)(g_Yh + (size_t)nr * 256 + 128 + hf * 64);
    const uint4* hiv = (const uint4*)(g_iv1h   + g * 128 + hf * 64);
    const uint4* hmv = (const uint4*)(g_nmiv1h + g * 128 + hf * 64);
    const __half2 hz = __float2half2_rn(0.f);
    int msw = m & 7;
    #pragma unroll
    for (int jj = 0; jj < 16; jj++) {
        uint4 va = yc[jj], vb = yr[jj], vi = hiv[jj], vm = hmv[jj];
        u32 o0 = h2u(__hmax2(__hfma2(__hadd2(u2h(va.x), u2h(vb.x)), u2h(vi.x), u2h(vm.x)), hz));
        u32 o1 = h2u(__hmax2(__hfma2(__hadd2(u2h(va.y), u2h(vb.y)), u2h(vi.y), u2h(vm.y)), hz));
        u32 o2 = h2u(__hmax2(__hfma2(__hadd2(u2h(va.z), u2h(vb.z)), u2h(vi.z), u2h(vm.z)), hz));
        u32 o3 = h2u(__hmax2(__hfma2(__hadd2(u2h(va.w), u2h(vb.w)), u2h(vi.w), u2h(vm.w)), hz));
        int oct = hf * 16 + jj;
        int gran = m * 32 + (oct ^ msw);
        *(uint4*)(cA + gran * 16) = make_uint4(o0, o1, o2, o3);
    }
}

__global__ __launch_bounds__(512) void k_gemm2_mma(const float* __restrict__ W2)
{
    extern __shared__ u32 sm[];
    u32* sB = sm;
    char* smc = (char*)sm;
    char* bufs[2] = {smc + 33792, smc + 99328};

    int tid = threadIdx.x;
    // B frags: convert W2 fp32 -> fp16 fragments in-CTA (all threads)
    for (int i = tid; i < 8192; i += 512) {
        int a = i >> 6, l = (i >> 1) & 31, r = i & 1;
        int ng = a >> 4, ki = a & 15;
        int k = ki * 16 + (l & 3) * 2 + r * 8;
        int n = ng * 8 + (l >> 2);
        sB[a * 66 + (i & 63)] = h2bits(W2[k * 64 + n], W2[(k + 1) * 64 + n]);
    }

    bool producer = (tid < 256);
    int m = tid & 127, hf = (tid >> 7) & 1;     // producer roles
    int wid2 = (tid >> 5) - 8;                  // consumer warp 0..7
    int lane = tid & 31;
    int wm = wid2 & 3, wn = wid2 >> 2;          // M 32-slice (4), N 32-slice (2)
    int lt = lane >> 3, lr = lane & 7;
    int lrow8 = (lt & 1) * 8 + lr;
    int lth = lt >> 1;

    // number of tiles for this CTA
    int n = 0;
    for (int t2 = blockIdx.x; t2 < NT; t2 += GRID2) n++;

    if (producer && n > 0)
        g2_fill(bufs[0], blockIdx.x, m, hf);
    __syncthreads();

    for (int i = 0; i < n; i++) {
        int tile = blockIdx.x + i * GRID2;
        if (producer) {
            if (i + 1 < n)
                g2_fill(bufs[(i + 1) & 1], tile + GRID2, m, hf);
        } else {
            u32 aA = smem_u32(bufs[i & 1]);
            float d[2][4][4];
            #pragma unroll
            for (int mi2 = 0; mi2 < 2; mi2++)
                #pragma unroll
                for (int ni = 0; ni < 4; ni++)
                    #pragma unroll
                    for (int r = 0; r < 4; r++) d[mi2][ni][r] = 0.f;

            #pragma unroll
            for (int ki = 0; ki < 16; ki++) {
                u32 ah[2][4];
                #pragma unroll
                for (int mi2 = 0; mi2 < 2; mi2++) {
                    int ml = wm * 32 + mi2 * 16 + lrow8;
                    int oct = 2 * ki + lth;
                    u32 goff = (u32)(ml * 32 + (oct ^ (ml & 7))) * 16;
                    ldm_x4(ah[mi2], aA + goff);
                }
                #pragma unroll
                for (int ni = 0; ni < 4; ni++) {
                    int batom = ((wn * 4 + ni) * 16 + ki) * 66 + lane * 2;
                    uint2 bv = *(const uint2*)(sB + batom);
                    u32 bb[2] = {bv.x, bv.y};
                    mma_f16(d[0][ni], ah[0], bb);
                    mma_f16(d[1][ni], ah[1], bb);
                }
            }
            // epilogue: pack fp16 -> g_x2h
            int r0base = tile * 128 + wm * 32 + (lane >> 2);
            int cpb = wn * 16 + (lane & 3);
            #pragma unroll
            for (int mi2 = 0; mi2 < 2; mi2++) {
                size_t rA = (size_t)(r0base + mi2 * 16);
                size_t rB = rA + 8;
                #pragma unroll
                for (int ni = 0; ni < 4; ni++) {
                    g_x2h[rA * 32 + cpb + ni * 4] = h2bits(d[mi2][ni][0], d[mi2][ni][1]);
                    g_x2h[rB * 32 + cpb + ni * 4] = h2bits(d[mi2][ni][2], d[mi2][ni][3]);
                }
            }
        }
        __syncthreads();
    }
}

// ---------------- stats2 (fp16 x2) ----------------
__global__ void k_stats2() {
    int g = blockIdx.x;
    int t = threadIdx.x;
    int c2 = t & 31, r = t >> 5;
    int s = g_off[g], eend = g_off[g + 1];
    float Sx = 0.f, Sy = 0.f, Qx = 0.f, Qy = 0.f;
    for (int p = s + r; p < eend; p += 8) {
        float2 f = h22f2(g_x2h[(size_t)p * 32 + c2]);
        Sx += f.x; Qx += f.x * f.x;
        Sy += f.y; Qy += f.y * f.y;
    }
    __shared__ float4 sS[256];
    sS[t] = make_float4(Sx, Sy, Qx, Qy);
    __syncthreads();
    for (int h2 = 128; h2 >= 32; h2 >>= 1) {
        if (t < h2) {
            float4 o = sS[t + h2];
            sS[t].x += o.x; sS[t].y += o.y; sS[t].z += o.z; sS[t].w += o.w;
        }
        __syncthreads();
    }
    if (t < 32) {
        float4 v = sS[t];
        float cnt = (float)max(eend - s, 1);
        float mx = v.x / cnt, my = v.y / cnt;
        float ivx = rsqrtf(v.z / cnt - mx * mx + EPS_IN);
        float ivy = rsqrtf(v.w / cnt - my * my + EPS_IN);
        g_inv2 [g * C2 + t * 2]     = ivx;
        g_inv2 [g * C2 + t * 2 + 1] = ivy;
        g_miv2 [g * C2 + t * 2]     = mx * ivx;
        g_miv2 [g * C2 + t * 2 + 1] = my * ivy;
    }
}

// ---------------- final layer (fp16 x2) ----------------
__global__ void k_final(const float* __restrict__ W3, const float* __restrict__ b3,
                        float* __restrict__ out)
{
    __shared__ float sw[64];
    int tid = threadIdx.x;
    if (tid < 64) sw[tid] = W3[tid];
    __syncthreads();
    int pos = blockIdx.x * 128 + (tid >> 1);
    int half = tid & 1;
    float acc = 0.f;
    int perm = 0;
    if (pos < E_EDGES) {
        int4 md = g_meta[pos];
        perm = md.x;
        int g = md.y;
        const uint4* xr = (const uint4*)(g_x2h + (size_t)pos * 32 + half * 16);
        const float4* vr = (const float4*)(g_inv2 + g * C2 + half * 32);
        const float4* mr = (const float4*)(g_miv2 + g * C2 + half * 32);
        #pragma unroll
        for (int j = 0; j < 4; j++) {
            uint4 xv = xr[j];
            float4 iv0 = vr[2 * j], iv1 = vr[2 * j + 1];
            float4 mv0 = mr[2 * j], mv1 = mr[2 * j + 1];
            float2 a0 = h22f2(xv.x), a1 = h22f2(xv.y);
            float2 a2 = h22f2(xv.z), a3 = h22f2(xv.w);
            int k = half * 32 + j * 8;
            acc += fmaxf(fmaf(a0.x, iv0.x, -mv0.x), 0.f) * sw[k]
                 + fmaxf(fmaf(a0.y, iv0.y, -mv0.y), 0.f) * sw[k + 1]
                 + fmaxf(fmaf(a1.x, iv0.z, -mv0.z), 0.f) * sw[k + 2]
                 + fmaxf(fmaf(a1.y, iv0.w, -mv0.w), 0.f) * sw[k + 3]
                 + fmaxf(fmaf(a2.x, iv1.x, -mv1.x), 0.f) * sw[k + 4]
                 + fmaxf(fmaf(a2.y, iv1.y, -mv1.y), 0.f) * sw[k + 5]
                 + fmaxf(fmaf(a3.x, iv1.z, -mv1.z), 0.f) * sw[k + 6]
                 + fmaxf(fmaf(a3.y, iv1.w, -mv1.w), 0.f) * sw[k + 7];
        }
    }
    float other = __shfl_xor_sync(0xffffffffu, acc, 1);
    if (half == 0 && pos < E_EDGES) out[perm] = acc + other + b3[0];
}

// ---------------- launch ----------------
extern "C" void kernel_launch(void* const* d_in, const int* in_sizes, int n_in,
                              void* d_out, int out_size)
{
    const float* emb   = (const float*)d_in[0];
    const float* W1    = (const float*)d_in[1];
    const float* W2    = (const float*)d_in[3];
    const float* W3    = (const float*)d_in[5];
    const float* b3    = (const float*)d_in[6];
    const int*   ei    = (const int*)d_in[7];
    const int*   batch = (const int*)d_in[8];
    const int* col = ei;
    const int* row = ei + E_EDGES;
    float* out = (float*)d_out;

    static cudaStream_t s2;
    static cudaEvent_t ev1, ev2;
    static int init_done = 0;
    if (!init_done) {
        cudaFuncSetAttribute(k_gemm2_mma, cudaFuncAttributeMaxDynamicSharedMemorySize, 164864);
        cudaFuncSetAttribute(k_emb_mma, cudaFuncAttributeMaxDynamicSharedMemorySize, 50176);
        cudaStreamCreateWithFlags(&s2, cudaStreamNonBlocking);
        cudaEventCreateWithFlags(&ev1, cudaEventDisableTiming);
        cudaEventCreateWithFlags(&ev2, cudaEventDisableTiming);
        init_done = 1;
    }

    // fork: emb_mma on side stream overlaps hist/scan/scatter on main stream
    cudaEventRecord(ev1, 0);
    cudaStreamWaitEvent(s2, ev1, 0);
    k_emb_mma<<<dim3((NN + 127) / 128, 2), 512, 50176, s2>>>(emb, W1);
    cudaEventRecord(ev2, s2);

    k_hist<<<1024, 256>>>(col, batch);
    k_scan<<<1, 512>>>();
    k_scatter<<<(E_EDGES + 2047) / 2048, 256>>>(col, row, batch);

    cudaStreamWaitEvent(0, ev2, 0);   // join before stats1g (needs Y + sorted meta)
    k_stats1g<<<NG * 4, 256>>>();
    k_gemm2_mma<<<GRID2, 512, 164864>>>(W2);
    k_stats2<<<NG, 256>>>();
    k_final<<<EP / 128, 256>>>(W3, b3, out);
}

// round 16
// speedup vs baseline: 2.7107x; 1.0914x over previous
#include <cuda_runtime.h>
#include <cuda_fp16.h>
#include <cstdint>

// ExtractorMLP: per-edge MLP 128->256->64->1 with per-graph instance norm.
// R16: edges counting-sorted by COL NODE (preserves graph order since batch
//      is node-sorted) -> ~20x reuse on Y[col] gathers in gemm2/stats1g;
//      __stcs on x2 stores keeps Y L2-resident; __ldcs on streamed reads.

#define E_EDGES 1000000
#define EP      1000064   // multiple of 128
#define NG      512
#define NN      50000
#define NBLK    98
#define NB      (NBLK * 512)   // 50176 >= NN
#define C1      256
#define C2      64
#define EPS_IN  1e-5f
#define NT      (EP / 128)   // 7813
#define GRID2   148

typedef unsigned long long ull;
typedef unsigned int u32;

// ---------------- scratch ----------------
__device__ u32   g_Yh[(size_t)NN * 256];   // 51 MB, half2-packed Y
__device__ u32   g_x2h[(size_t)EP * 32];   // 128 MB, half2-packed x2
__device__ int4  g_meta[EP];               // {perm, gid, col, row} per sorted pos
__device__ int   g_ncnt[NN];               // invariant: zero at kernel_launch entry
__device__ int   g_nexc[NB];
__device__ int   g_bsum[NBLK];
__device__ int   g_boff[NBLK];
__device__ int   g_ncur[NN];
__device__ int   g_off[NG + 1];
__device__ u32   g_iv1h [NG * 128];        // half2-packed inv1
__device__ u32   g_nmiv1h[NG * 128];       // half2-packed NEGATED mean1*inv1
__device__ float g_inv2 [NG * C2];
__device__ float g_miv2 [NG * C2];

// ---------------- helpers ----------------
__device__ __forceinline__ u32 h2bits(float x, float y) {
    __half2 h = __floats2half2_rn(x, y);
    return *reinterpret_cast<u32*>(&h);
}
__device__ __forceinline__ __half2 u2h(u32 v) {
    return *reinterpret_cast<__half2*>(&v);
}
__device__ __forceinline__ u32 h2u(__half2 h) {
    return *reinterpret_cast<u32*>(&h);
}
__device__ __forceinline__ float2 h22f2(u32 v) {
    __half2 h = *reinterpret_cast<__half2*>(&v);
    return __half22float2(h);
}
__device__ __forceinline__ void mma_f16(float* d, const u32* a, const u32* b) {
    asm volatile(
        "mma.sync.aligned.m16n8k16.row.col.f32.f16.f16.f32 "
        "{%0,%1,%2,%3}, {%4,%5,%6,%7}, {%8,%9}, {%0,%1,%2,%3};"
        : "+f"(d[0]), "+f"(d[1]), "+f"(d[2]), "+f"(d[3])
        : "r"(a[0]), "r"(a[1]), "r"(a[2]), "r"(a[3]), "r"(b[0]), "r"(b[1]));
}
__device__ __forceinline__ void ldm_x4(u32* r, u32 addr) {
    asm volatile("ldmatrix.sync.aligned.m8n8.x4.shared.b16 {%0,%1,%2,%3}, [%4];"
        : "=r"(r[0]), "=r"(r[1]), "=r"(r[2]), "=r"(r[3]) : "r"(addr));
}
__device__ __forceinline__ u32 smem_u32(const void* p) {
    u32 a;
    asm("{ .reg .u64 t; cvta.to.shared.u64 t, %1; cvt.u32.u64 %0, t; }"
        : "=r"(a) : "l"(p));
    return a;
}

// ---------------- col-node counting sort ----------------
__global__ void k_nhist(const int* __restrict__ col) {
    int idx = blockIdx.x * blockDim.x + threadIdx.x;
    int stride = gridDim.x * blockDim.x;
    for (int e = idx; e < E_EDGES; e += stride)
        atomicAdd(&g_ncnt[col[e]], 1);
}

__global__ void k_nscan1() {
    __shared__ int s[512];
    int t = threadIdx.x;
    int n = blockIdx.x * 512 + t;
    int c = (n < NN) ? g_ncnt[n] : 0;
    if (n < NN) g_ncnt[n] = 0;          // restore invariant
    s[t] = c;
    __syncthreads();
    for (int o = 1; o < 512; o <<= 1) {
        int v = (t >= o) ? s[t - o] : 0;
        __syncthreads();
        s[t] += v;
        __syncthreads();
    }
    g_nexc[n] = s[t] - c;
    if (t == 511) g_bsum[blockIdx.x] = s[511];
}

__global__ void k_nscan2() {
    __shared__ int s[128];
    int t = threadIdx.x;
    int c = (t < NBLK) ? g_bsum[t] : 0;
    s[t] = c;
    __syncthreads();
    for (int o = 1; o < 128; o <<= 1) {
        int v = (t >= o) ? s[t - o] : 0;
        __syncthreads();
        s[t] += v;
        __syncthreads();
    }
    if (t < NBLK) g_boff[t] = s[t] - c;
    if (t < (EP - E_EDGES)) g_meta[E_EDGES + t] = make_int4(0, 0, 0, 0);
}

__global__ void k_nscan3(const int* __restrict__ batch) {
    int n = blockIdx.x * 512 + threadIdx.x;
    if (n >= NN) return;
    int off = g_nexc[n] + g_boff[n >> 9];
    g_ncur[n] = off;
    int g = batch[n];
    int pg = (n == 0) ? -1 : batch[n - 1];
    for (int g2 = pg + 1; g2 <= g; g2++) g_off[g2] = off;
    if (n == NN - 1)
        for (int g2 = g + 1; g2 <= NG; g2++) g_off[g2] = E_EDGES;
}

__global__ void k_scatter(const int* __restrict__ col, const int* __restrict__ row,
                          const int* __restrict__ batch) {
    int idx = blockIdx.x * blockDim.x + threadIdx.x;
    int stride = gridDim.x * blockDim.x;
    for (int e = idx; e < E_EDGES; e += stride) {
        int c = col[e];
        int p = atomicAdd(&g_ncur[c], 1);
        g_meta[p] = make_int4(e, batch[c], c, row[e]);
    }
}

// ---------------- Y = emb @ [W1top | W1bot], fp16 mma ----------------
__global__ __launch_bounds__(512) void k_emb_mma(const float* __restrict__ emb,
                                                 const float* __restrict__ W1)
{
    extern __shared__ u32 sm[];
    u32* sB = sm;
    char* cA = (char*)sm + 33792;
    u32 aA = smem_u32(cA);

    int tid = threadIdx.x;
    int half = blockIdx.y;
    int nb = blockIdx.x * 128;

    for (int i = tid; i < 8192; i += 512) {
        int a = i >> 6, l = (i >> 1) & 31, r = i & 1;
        int ng = a >> 2, ki = a & 3;
        int k = ki * 16 + (l & 3) * 2 + r * 8;
        int n = ng * 8 + (l >> 2);
        const float* base = W1 + half * 64 * 256 + n;
        sB[a * 66 + (i & 63)] = h2bits(base[k * 256], base[(k + 1) * 256]);
    }
    {
        int m = tid >> 2, q = tid & 3;
        int node = nb + m, msw = m & 7;
        u32 h[8] = {0, 0, 0, 0, 0, 0, 0, 0};
        if (node < NN) {
            const float4* src = (const float4*)(emb + (size_t)node * 64 + q * 16);
            float4 v0 = src[0], v1 = src[1], v2 = src[2], v3 = src[3];
            h[0] = h2bits(v0.x, v0.y); h[1] = h2bits(v0.z, v0.w);
            h[2] = h2bits(v1.x, v1.y); h[3] = h2bits(v1.z, v1.w);
            h[4] = h2bits(v2.x, v2.y); h[5] = h2bits(v2.z, v2.w);
            h[6] = h2bits(v3.x, v3.y); h[7] = h2bits(v3.z, v3.w);
        }
        *(uint4*)(cA + (m * 8 + ((q * 2)     ^ msw)) * 16) = make_uint4(h[0], h[1], h[2], h[3]);
        *(uint4*)(cA + (m * 8 + ((q * 2 + 1) ^ msw)) * 16) = make_uint4(h[4], h[5], h[6], h[7]);
    }
    __syncthreads();

    int w = tid >> 5, lane = tid & 31;
    int wm = w & 3, wn = w >> 2;
    int lt = lane >> 3, lr = lane & 7;
    int lrow8 = (lt & 1) * 8 + lr, lth = lt >> 1;

    float d[2][8][4];
    #pragma unroll
    for (int a = 0; a < 2; a++)
        #pragma unroll
        for (int b = 0; b < 8; b++)
            #pragma unroll
            for (int c = 0; c < 4; c++) d[a][b][c] = 0.f;

    #pragma unroll
    for (int ki = 0; ki < 4; ki++) {
        u32 ah[2][4];
        #pragma unroll
        for (int mi2 = 0; mi2 < 2; mi2++) {
            int ml = wm * 32 + mi2 * 16 + lrow8;
            int oct = 2 * ki + lth;
            u32 goff = (u32)(ml * 8 + (oct ^ (ml & 7))) * 16;
            ldm_x4(ah[mi2], aA + goff);
        }
        #pragma unroll
        for (int ni = 0; ni < 8; ni++) {
            int batom = ((wn * 8 + ni) * 4 + ki) * 66 + lane * 2;
            uint2 bv = *(const uint2*)(sB + batom);
            u32 bb[2] = {bv.x, bv.y};
            mma_f16(d[0][ni], ah[0], bb);
            mma_f16(d[1][ni], ah[1], bb);
        }
    }
    {
        int r0 = nb + wm * 32 + (lane >> 2);
        int cpb = (half * 256 + wn * 64 + (lane & 3) * 2) >> 1;
        #pragma unroll
        for (int mi2 = 0; mi2 < 2; mi2++) {
            int rA = r0 + mi2 * 16, rB = rA + 8;
            if (rA < NN) {
                #pragma unroll
                for (int ni = 0; ni < 8; ni++)
                    g_Yh[(size_t)rA * 256 + cpb + ni * 4] = h2bits(d[mi2][ni][0], d[mi2][ni][1]);
            }
            if (rB < NN) {
                #pragma unroll
                for (int ni = 0; ni < 8; ni++)
                    g_Yh[(size_t)rB * 256 + cpb + ni * 4] = h2bits(d[mi2][ni][2], d[mi2][ni][3]);
            }
        }
    }
}

// ---------------- stats1: per (graph, 64-ch chunk), LDG.64 gather, 16 rows ----------------
__global__ void k_stats1g() {
    int g  = blockIdx.x >> 2;
    int c0u = (blockIdx.x & 3) * 32;     // u32 base within 128
    int t = threadIdx.x;
    int u2i = t & 15, r = t >> 4;        // uint2 index (16), row (16)
    int s = g_off[g], eend = g_off[g + 1];
    int cb = c0u + u2i * 2;
    float S0 = 0.f, S1 = 0.f, S2 = 0.f, S3 = 0.f;
    float Q0 = 0.f, Q1 = 0.f, Q2 = 0.f, Q3 = 0.f;
    for (int p = s + r; p < eend; p += 16) {
        int4 md = __ldcs(&g_meta[p]);
        uint2 a = *(const uint2*)(g_Yh + (size_t)md.z * 256 + cb);
        uint2 b = *(const uint2*)(g_Yh + (size_t)md.w * 256 + 128 + cb);
        float2 f0 = __half22float2(__hadd2(u2h(a.x), u2h(b.x)));
        float2 f1 = __half22float2(__hadd2(u2h(a.y), u2h(b.y)));
        S0 += f0.x; Q0 += f0.x * f0.x;
        S1 += f0.y; Q1 += f0.y * f0.y;
        S2 += f1.x; Q2 += f1.x * f1.x;
        S3 += f1.y; Q3 += f1.y * f1.y;
    }
    __shared__ float4 sS[256], sQ[256];
    sS[t] = make_float4(S0, S1, S2, S3);
    sQ[t] = make_float4(Q0, Q1, Q2, Q3);
    __syncthreads();
    for (int h2 = 128; h2 >= 16; h2 >>= 1) {
        if (t < h2) {
            float4 oS = sS[t + h2], oQ = sQ[t + h2];
            sS[t].x += oS.x; sS[t].y += oS.y; sS[t].z += oS.z; sS[t].w += oS.w;
            sQ[t].x += oQ.x; sQ[t].y += oQ.y; sQ[t].z += oQ.z; sQ[t].w += oQ.w;
        }
        __syncthreads();
    }
    if (t < 16) {
        float4 vS = sS[t], vQ = sQ[t];
        float cnt = (float)max(eend - s, 1);
        float m0 = vS.x / cnt, m1 = vS.y / cnt, m2 = vS.z / cnt, m3 = vS.w / cnt;
        float i0 = rsqrtf(vQ.x / cnt - m0 * m0 + EPS_IN);
        float i1 = rsqrtf(vQ.y / cnt - m1 * m1 + EPS_IN);
        float i2 = rsqrtf(vQ.z / cnt - m2 * m2 + EPS_IN);
        float i3 = rsqrtf(vQ.w / cnt - m3 * m3 + EPS_IN);
        int cw = c0u + t * 2;
        g_iv1h  [g * 128 + cw]     = h2bits(i0, i1);
        g_iv1h  [g * 128 + cw + 1] = h2bits(i2, i3);
        g_nmiv1h[g * 128 + cw]     = h2bits(-m0 * i0, -m1 * i1);
        g_nmiv1h[g * 128 + cw + 1] = h2bits(-m2 * i2, -m3 * i3);
    }
}

// ---------------- GEMM2: warp-specialized, double-buffered ----------------
// smem: [0) B frags 33792 | [33792) A buf0 65536 | [99328) A buf1 65536 = 164864.
__device__ __forceinline__ void g2_fill(char* cA, int tile, int m, int hf) {
    int4 md = g_meta[tile * 128 + m];
    int g = md.y, nc = md.z, nr = md.w;
    const uint4* yc  = (const uint4*)(g_Yh + (size_t)nc * 256 + hf * 64);
    const uint4* yr  = (const uint4*)(g_Yh + (size_t)nr * 256 + 128 + hf * 64);
    const uint4* hiv = (const uint4*)(g_iv1h   + g * 128 + hf * 64);
    const uint4* hmv = (const uint4*)(g_nmiv1h + g * 128 + hf * 64);
    const __half2 hz = __float2half2_rn(0.f);
    int msw = m & 7;
    #pragma unroll
    for (int jj = 0; jj < 16; jj++) {
        uint4 va = yc[jj], vb = yr[jj], vi = hiv[jj], vm = hmv[jj];
        u32 o0 = h2u(__hmax2(__hfma2(__hadd2(u2h(va.x), u2h(vb.x)), u2h(vi.x), u2h(vm.x)), hz));
        u32 o1 = h2u(__hmax2(__hfma2(__hadd2(u2h(va.y), u2h(vb.y)), u2h(vi.y), u2h(vm.y)), hz));
        u32 o2 = h2u(__hmax2(__hfma2(__hadd2(u2h(va.z), u2h(vb.z)), u2h(vi.z), u2h(vm.z)), hz));
        u32 o3 = h2u(__hmax2(__hfma2(__hadd2(u2h(va.w), u2h(vb.w)), u2h(vi.w), u2h(vm.w)), hz));
        int oct = hf * 16 + jj;
        int gran = m * 32 + (oct ^ msw);
        *(uint4*)(cA + gran * 16) = make_uint4(o0, o1, o2, o3);
    }
}

__global__ __launch_bounds__(512) void k_gemm2_mma(const float* __restrict__ W2)
{
    extern __shared__ u32 sm[];
    u32* sB = sm;
    char* smc = (char*)sm;
    char* bufs[2] = {smc + 33792, smc + 99328};

    int tid = threadIdx.x;
    for (int i = tid; i < 8192; i += 512) {
        int a = i >> 6, l = (i >> 1) & 31, r = i & 1;
        int ng = a >> 4, ki = a & 15;
        int k = ki * 16 + (l & 3) * 2 + r * 8;
        int n = ng * 8 + (l >> 2);
        sB[a * 66 + (i & 63)] = h2bits(W2[k * 64 + n], W2[(k + 1) * 64 + n]);
    }

    bool producer = (tid < 256);
    int m = tid & 127, hf = (tid >> 7) & 1;
    int wid2 = (tid >> 5) - 8;
    int lane = tid & 31;
    int wm = wid2 & 3, wn = wid2 >> 2;
    int lt = lane >> 3, lr = lane & 7;
    int lrow8 = (lt & 1) * 8 + lr;
    int lth = lt >> 1;

    int n = 0;
    for (int t2 = blockIdx.x; t2 < NT; t2 += GRID2) n++;

    if (producer && n > 0)
        g2_fill(bufs[0], blockIdx.x, m, hf);
    __syncthreads();

    for (int i = 0; i < n; i++) {
        int tile = blockIdx.x + i * GRID2;
        if (producer) {
            if (i + 1 < n)
                g2_fill(bufs[(i + 1) & 1], tile + GRID2, m, hf);
        } else {
            u32 aA = smem_u32(bufs[i & 1]);
            float d[2][4][4];
            #pragma unroll
            for (int mi2 = 0; mi2 < 2; mi2++)
                #pragma unroll
                for (int ni = 0; ni < 4; ni++)
                    #pragma unroll
                    for (int r = 0; r < 4; r++) d[mi2][ni][r] = 0.f;

            #pragma unroll
            for (int ki = 0; ki < 16; ki++) {
                u32 ah[2][4];
                #pragma unroll
                for (int mi2 = 0; mi2 < 2; mi2++) {
                    int ml = wm * 32 + mi2 * 16 + lrow8;
                    int oct = 2 * ki + lth;
                    u32 goff = (u32)(ml * 32 + (oct ^ (ml & 7))) * 16;
                    ldm_x4(ah[mi2], aA + goff);
                }
                #pragma unroll
                for (int ni = 0; ni < 4; ni++) {
                    int batom = ((wn * 4 + ni) * 16 + ki) * 66 + lane * 2;
                    uint2 bv = *(const uint2*)(sB + batom);
                    u32 bb[2] = {bv.x, bv.y};
                    mma_f16(d[0][ni], ah[0], bb);
                    mma_f16(d[1][ni], ah[1], bb);
                }
            }
            int r0base = tile * 128 + wm * 32 + (lane >> 2);
            int cpb = wn * 16 + (lane & 3);
            #pragma unroll
            for (int mi2 = 0; mi2 < 2; mi2++) {
                size_t rA = (size_t)(r0base + mi2 * 16);
                size_t rB = rA + 8;
                #pragma unroll
                for (int ni = 0; ni < 4; ni++) {
                    __stcs(&g_x2h[rA * 32 + cpb + ni * 4], h2bits(d[mi2][ni][0], d[mi2][ni][1]));
                    __stcs(&g_x2h[rB * 32 + cpb + ni * 4], h2bits(d[mi2][ni][2], d[mi2][ni][3]));
                }
            }
        }
        __syncthreads();
    }
}

// ---------------- stats2 (fp16 x2) ----------------
__global__ void k_stats2() {
    int g = blockIdx.x;
    int t = threadIdx.x;
    int c2 = t & 31, r = t >> 5;
    int s = g_off[g], eend = g_off[g + 1];
    float Sx = 0.f, Sy = 0.f, Qx = 0.f, Qy = 0.f;
    for (int p = s + r; p < eend; p += 8) {
        float2 f = h22f2(__ldcs(&g_x2h[(size_t)p * 32 + c2]));
        Sx += f.x; Qx += f.x * f.x;
        Sy += f.y; Qy += f.y * f.y;
    }
    __shared__ float4 sS[256];
    sS[t] = make_float4(Sx, Sy, Qx, Qy);
    __syncthreads();
    for (int h2 = 128; h2 >= 32; h2 >>= 1) {
        if (t < h2) {
            float4 o = sS[t + h2];
            sS[t].x += o.x; sS[t].y += o.y; sS[t].z += o.z; sS[t].w += o.w;
        }
        __syncthreads();
    }
    if (t < 32) {
        float4 v = sS[t];
        float cnt = (float)max(eend - s, 1);
        float mx = v.x / cnt, my = v.y / cnt;
        float ivx = rsqrtf(v.z / cnt - mx * mx + EPS_IN);
        float ivy = rsqrtf(v.w / cnt - my * my + EPS_IN);
        g_inv2 [g * C2 + t * 2]     = ivx;
        g_inv2 [g * C2 + t * 2 + 1] = ivy;
        g_miv2 [g * C2 + t * 2]     = mx * ivx;
        g_miv2 [g * C2 + t * 2 + 1] = my * ivy;
    }
}

// ---------------- final layer (fp16 x2) ----------------
__global__ void k_final(const float* __restrict__ W3, const float* __restrict__ b3,
                        float* __restrict__ out)
{
    __shared__ float sw[64];
    int tid = threadIdx.x;
    if (tid < 64) sw[tid] = W3[tid];
    __syncthreads();
    int pos = blockIdx.x * 128 + (tid >> 1);
    int half = tid & 1;
    float acc = 0.f;
    int perm = 0;
    if (pos < E_EDGES) {
        int4 md = __ldcs(&g_meta[pos]);
        perm = md.x;
        int g = md.y;
        const uint4* xr = (const uint4*)(g_x2h + (size_t)pos * 32 + half * 16);
        const float4* vr = (const float4*)(g_inv2 + g * C2 + half * 32);
        const float4* mr = (const float4*)(g_miv2 + g * C2 + half * 32);
        #pragma unroll
        for (int j = 0; j < 4; j++) {
            uint4 xv = __ldcs(&xr[j]);
            float4 iv0 = vr[2 * j], iv1 = vr[2 * j + 1];
            float4 mv0 = mr[2 * j], mv1 = mr[2 * j + 1];
            float2 a0 = h22f2(xv.x), a1 = h22f2(xv.y);
            float2 a2 = h22f2(xv.z), a3 = h22f2(xv.w);
            int k = half * 32 + j * 8;
            acc += fmaxf(fmaf(a0.x, iv0.x, -mv0.x), 0.f) * sw[k]
                 + fmaxf(fmaf(a0.y, iv0.y, -mv0.y), 0.f) * sw[k + 1]
                 + fmaxf(fmaf(a1.x, iv0.z, -mv0.z), 0.f) * sw[k + 2]
                 + fmaxf(fmaf(a1.y, iv0.w, -mv0.w), 0.f) * sw[k + 3]
                 + fmaxf(fmaf(a2.x, iv1.x, -mv1.x), 0.f) * sw[k + 4]
                 + fmaxf(fmaf(a2.y, iv1.y, -mv1.y), 0.f) * sw[k + 5]
                 + fmaxf(fmaf(a3.x, iv1.z, -mv1.z), 0.f) * sw[k + 6]
                 + fmaxf(fmaf(a3.y, iv1.w, -mv1.w), 0.f) * sw[k + 7];
        }
    }
    float other = __shfl_xor_sync(0xffffffffu, acc, 1);
    if (half == 0 && pos < E_EDGES) out[perm] = acc + other + b3[0];
}

// ---------------- launch ----------------
extern "C" void kernel_launch(void* const* d_in, const int* in_sizes, int n_in,
                              void* d_out, int out_size)
{
    const float* emb   = (const float*)d_in[0];
    const float* W1    = (const float*)d_in[1];
    const float* W2    = (const float*)d_in[3];
    const float* W3    = (const float*)d_in[5];
    const float* b3    = (const float*)d_in[6];
    const int*   ei    = (const int*)d_in[7];
    const int*   batch = (const int*)d_in[8];
    const int* col = ei;
    const int* row = ei + E_EDGES;
    float* out = (float*)d_out;

    static cudaStream_t s2;
    static cudaEvent_t ev1, ev2;
    static int init_done = 0;
    if (!init_done) {
        cudaFuncSetAttribute(k_gemm2_mma, cudaFuncAttributeMaxDynamicSharedMemorySize, 164864);
        cudaFuncSetAttribute(k_emb_mma, cudaFuncAttributeMaxDynamicSharedMemorySize, 50176);
        cudaStreamCreateWithFlags(&s2, cudaStreamNonBlocking);
        cudaEventCreateWithFlags(&ev1, cudaEventDisableTiming);
        cudaEventCreateWithFlags(&ev2, cudaEventDisableTiming);
        init_done = 1;
    }

    // fork: emb_mma on side stream overlaps the col-sort chain on main stream
    cudaEventRecord(ev1, 0);
    cudaStreamWaitEvent(s2, ev1, 0);
    k_emb_mma<<<dim3((NN + 127) / 128, 2), 512, 50176, s2>>>(emb, W1);
    cudaEventRecord(ev2, s2);

    k_nhist<<<1024, 256>>>(col);
    k_nscan1<<<NBLK, 512>>>();
    k_nscan2<<<1, 128>>>();
    k_nscan3<<<NBLK, 512>>>(batch);
    k_scatter<<<1024, 256>>>(col, row, batch);

    cudaStreamWaitEvent(0, ev2, 0);   // join before stats1g (needs Y + sorted meta)
    k_stats1g<<<NG * 4, 256>>>();
    k_gemm2_mma<<<GRID2, 512, 164864>>>(W2);
    k_stats2<<<NG, 256>>>();
    k_final<<<EP / 128, 256>>>(W3, b3, out);
}

// round 17
// speedup vs baseline: 2.9443x; 1.0862x over previous
#include <cuda_runtime.h>
#include <cuda_fp16.h>
#include <cstdint>

// ExtractorMLP: per-edge MLP 128->256->64->1 with per-graph instance norm.
// R17: gemm2 contiguous tile ranges (cross-tile col-run/L1 reuse);
//      stats1g stages meta in smem (kills 16x redundant LDG);
//      stats2+final fused into one per-graph kernel (x2 slice stays warm).

#define E_EDGES 1000000
#define EP      1000064   // multiple of 128
#define NG      512
#define NN      50000
#define NBLK    98
#define NB      (NBLK * 512)   // 50176 >= NN
#define C1      256
#define C2      64
#define EPS_IN  1e-5f
#define NT      (EP / 128)   // 7813
#define GRID2   148
#define TPC2    ((NT + GRID2 - 1) / GRID2)   // 53

typedef unsigned long long ull;
typedef unsigned int u32;

// ---------------- scratch ----------------
__device__ u32   g_Yh[(size_t)NN * 256];   // 51 MB, half2-packed Y
__device__ u32   g_x2h[(size_t)EP * 32];   // 128 MB, half2-packed x2
__device__ int4  g_meta[EP];               // {perm, gid, col, row} per sorted pos
__device__ int   g_ncnt[NN];               // invariant: zero at kernel_launch entry
__device__ int   g_nexc[NB];
__device__ int   g_bsum[NBLK];
__device__ int   g_boff[NBLK];
__device__ int   g_ncur[NN];
__device__ int   g_off[NG + 1];
__device__ u32   g_iv1h [NG * 128];        // half2-packed inv1
__device__ u32   g_nmiv1h[NG * 128];       // half2-packed NEGATED mean1*inv1

// ---------------- helpers ----------------
__device__ __forceinline__ u32 h2bits(float x, float y) {
    __half2 h = __floats2half2_rn(x, y);
    return *reinterpret_cast<u32*>(&h);
}
__device__ __forceinline__ __half2 u2h(u32 v) {
    return *reinterpret_cast<__half2*>(&v);
}
__device__ __forceinline__ u32 h2u(__half2 h) {
    return *reinterpret_cast<u32*>(&h);
}
__device__ __forceinline__ float2 h22f2(u32 v) {
    __half2 h = *reinterpret_cast<__half2*>(&v);
    return __half22float2(h);
}
__device__ __forceinline__ void mma_f16(float* d, const u32* a, const u32* b) {
    asm volatile(
        "mma.sync.aligned.m16n8k16.row.col.f32.f16.f16.f32 "
        "{%0,%1,%2,%3}, {%4,%5,%6,%7}, {%8,%9}, {%0,%1,%2,%3};"
        : "+f"(d[0]), "+f"(d[1]), "+f"(d[2]), "+f"(d[3])
        : "r"(a[0]), "r"(a[1]), "r"(a[2]), "r"(a[3]), "r"(b[0]), "r"(b[1]));
}
__device__ __forceinline__ void ldm_x4(u32* r, u32 addr) {
    asm volatile("ldmatrix.sync.aligned.m8n8.x4.shared.b16 {%0,%1,%2,%3}, [%4];"
        : "=r"(r[0]), "=r"(r[1]), "=r"(r[2]), "=r"(r[3]) : "r"(addr));
}
__device__ __forceinline__ u32 smem_u32(const void* p) {
    u32 a;
    asm("{ .reg .u64 t; cvta.to.shared.u64 t, %1; cvt.u32.u64 %0, t; }"
        : "=r"(a) : "l"(p));
    return a;
}

// ---------------- col-node counting sort ----------------
__global__ void k_nhist(const int* __restrict__ col) {
    int idx = blockIdx.x * blockDim.x + threadIdx.x;
    int stride = gridDim.x * blockDim.x;
    for (int e = idx; e < E_EDGES; e += stride)
        atomicAdd(&g_ncnt[col[e]], 1);
}

__global__ void k_nscan1() {
    __shared__ int s[512];
    int t = threadIdx.x;
    int n = blockIdx.x * 512 + t;
    int c = (n < NN) ? g_ncnt[n] : 0;
    if (n < NN) g_ncnt[n] = 0;          // restore invariant
    s[t] = c;
    __syncthreads();
    for (int o = 1; o < 512; o <<= 1) {
        int v = (t >= o) ? s[t - o] : 0;
        __syncthreads();
        s[t] += v;
        __syncthreads();
    }
    g_nexc[n] = s[t] - c;
    if (t == 511) g_bsum[blockIdx.x] = s[511];
}

__global__ void k_nscan2() {
    __shared__ int s[128];
    int t = threadIdx.x;
    int c = (t < NBLK) ? g_bsum[t] : 0;
    s[t] = c;
    __syncthreads();
    for (int o = 1; o < 128; o <<= 1) {
        int v = (t >= o) ? s[t - o] : 0;
        __syncthreads();
        s[t] += v;
        __syncthreads();
    }
    if (t < NBLK) g_boff[t] = s[t] - c;
    if (t < (EP - E_EDGES)) g_meta[E_EDGES + t] = make_int4(0, 0, 0, 0);
}

__global__ void k_nscan3(const int* __restrict__ batch) {
    int n = blockIdx.x * 512 + threadIdx.x;
    if (n >= NN) return;
    int off = g_nexc[n] + g_boff[n >> 9];
    g_ncur[n] = off;
    int g = batch[n];
    int pg = (n == 0) ? -1 : batch[n - 1];
    for (int g2 = pg + 1; g2 <= g; g2++) g_off[g2] = off;
    if (n == NN - 1)
        for (int g2 = g + 1; g2 <= NG; g2++) g_off[g2] = E_EDGES;
}

__global__ void k_scatter(const int* __restrict__ col, const int* __restrict__ row,
                          const int* __restrict__ batch) {
    int idx = blockIdx.x * blockDim.x + threadIdx.x;
    int stride = gridDim.x * blockDim.x;
    for (int e = idx; e < E_EDGES; e += stride) {
        int c = col[e];
        int p = atomicAdd(&g_ncur[c], 1);
        g_meta[p] = make_int4(e, batch[c], c, row[e]);
    }
}

// ---------------- Y = emb @ [W1top | W1bot], fp16 mma ----------------
__global__ __launch_bounds__(512) void k_emb_mma(const float* __restrict__ emb,
                                                 const float* __restrict__ W1)
{
    extern __shared__ u32 sm[];
    u32* sB = sm;
    char* cA = (char*)sm + 33792;
    u32 aA = smem_u32(cA);

    int tid = threadIdx.x;
    int half = blockIdx.y;
    int nb = blockIdx.x * 128;

    for (int i = tid; i < 8192; i += 512) {
        int a = i >> 6, l = (i >> 1) & 31, r = i & 1;
        int ng = a >> 2, ki = a & 3;
        int k = ki * 16 + (l & 3) * 2 + r * 8;
        int n = ng * 8 + (l >> 2);
        const float* base = W1 + half * 64 * 256 + n;
        sB[a * 66 + (i & 63)] = h2bits(base[k * 256], base[(k + 1) * 256]);
    }
    {
        int m = tid >> 2, q = tid & 3;
        int node = nb + m, msw = m & 7;
        u32 h[8] = {0, 0, 0, 0, 0, 0, 0, 0};
        if (node < NN) {
            const float4* src = (const float4*)(emb + (size_t)node * 64 + q * 16);
            float4 v0 = src[0], v1 = src[1], v2 = src[2], v3 = src[3];
            h[0] = h2bits(v0.x, v0.y); h[1] = h2bits(v0.z, v0.w);
            h[2] = h2bits(v1.x, v1.y); h[3] = h2bits(v1.z, v1.w);
            h[4] = h2bits(v2.x, v2.y); h[5] = h2bits(v2.z, v2.w);
            h[6] = h2bits(v3.x, v3.y); h[7] = h2bits(v3.z, v3.w);
        }
        *(uint4*)(cA + (m * 8 + ((q * 2)     ^ msw)) * 16) = make_uint4(h[0], h[1], h[2], h[3]);
        *(uint4*)(cA + (m * 8 + ((q * 2 + 1) ^ msw)) * 16) = make_uint4(h[4], h[5], h[6], h[7]);
    }
    __syncthreads();

    int w = tid >> 5, lane = tid & 31;
    int wm = w & 3, wn = w >> 2;
    int lt = lane >> 3, lr = lane & 7;
    int lrow8 = (lt & 1) * 8 + lr, lth = lt >> 1;

    float d[2][8][4];
    #pragma unroll
    for (int a = 0; a < 2; a++)
        #pragma unroll
        for (int b = 0; b < 8; b++)
            #pragma unroll
            for (int c = 0; c < 4; c++) d[a][b][c] = 0.f;

    #pragma unroll
    for (int ki = 0; ki < 4; ki++) {
        u32 ah[2][4];
        #pragma unroll
        for (int mi2 = 0; mi2 < 2; mi2++) {
            int ml = wm * 32 + mi2 * 16 + lrow8;
            int oct = 2 * ki + lth;
            u32 goff = (u32)(ml * 8 + (oct ^ (ml & 7))) * 16;
            ldm_x4(ah[mi2], aA + goff);
        }
        #pragma unroll
        for (int ni = 0; ni < 8; ni++) {
            int batom = ((wn * 8 + ni) * 4 + ki) * 66 + lane * 2;
            uint2 bv = *(const uint2*)(sB + batom);
            u32 bb[2] = {bv.x, bv.y};
            mma_f16(d[0][ni], ah[0], bb);
            mma_f16(d[1][ni], ah[1], bb);
        }
    }
    {
        int r0 = nb + wm * 32 + (lane >> 2);
        int cpb = (half * 256 + wn * 64 + (lane & 3) * 2) >> 1;
        #pragma unroll
        for (int mi2 = 0; mi2 < 2; mi2++) {
            int rA = r0 + mi2 * 16, rB = rA + 8;
            if (rA < NN) {
                #pragma unroll
                for (int ni = 0; ni < 8; ni++)
                    g_Yh[(size_t)rA * 256 + cpb + ni * 4] = h2bits(d[mi2][ni][0], d[mi2][ni][1]);
            }
            if (rB < NN) {
                #pragma unroll
                for (int ni = 0; ni < 8; ni++)
                    g_Yh[(size_t)rB * 256 + cpb + ni * 4] = h2bits(d[mi2][ni][2], d[mi2][ni][3]);
            }
        }
    }
}

// ---------------- stats1: per (graph, 64-ch chunk); meta staged in smem ----------------
__global__ void k_stats1g() {
    int g  = blockIdx.x >> 2;
    int c0u = (blockIdx.x & 3) * 32;     // u32 base within 128
    int t = threadIdx.x;
    int u2i = t & 15, r = t >> 4;        // uint2 index (16), edge slot (16)
    int s = g_off[g], eend = g_off[g + 1];
    int cb = c0u + u2i * 2;
    float S0 = 0.f, S1 = 0.f, S2 = 0.f, S3 = 0.f;
    float Q0 = 0.f, Q1 = 0.f, Q2 = 0.f, Q3 = 0.f;
    __shared__ int2 smeta[256];
    for (int chunk = s; chunk < eend; chunk += 256) {
        __syncthreads();
        if (chunk + t < eend) {
            int4 md = g_meta[chunk + t];
            smeta[t] = make_int2(md.z, md.w);
        }
        __syncthreads();
        int lim = min(256, eend - chunk);
        for (int j = r; j < lim; j += 16) {
            int2 cr = smeta[j];
            uint2 a = *(const uint2*)(g_Yh + (size_t)cr.x * 256 + cb);
            uint2 b = *(const uint2*)(g_Yh + (size_t)cr.y * 256 + 128 + cb);
            float2 f0 = __half22float2(__hadd2(u2h(a.x), u2h(b.x)));
            float2 f1 = __half22float2(__hadd2(u2h(a.y), u2h(b.y)));
            S0 += f0.x; Q0 += f0.x * f0.x;
            S1 += f0.y; Q1 += f0.y * f0.y;
            S2 += f1.x; Q2 += f1.x * f1.x;
            S3 += f1.y; Q3 += f1.y * f1.y;
        }
    }
    __shared__ float4 sS[256], sQ[256];
    __syncthreads();
    sS[t] = make_float4(S0, S1, S2, S3);
    sQ[t] = make_float4(Q0, Q1, Q2, Q3);
    __syncthreads();
    for (int h2 = 128; h2 >= 16; h2 >>= 1) {
        if (t < h2) {
            float4 oS = sS[t + h2], oQ = sQ[t + h2];
            sS[t].x += oS.x; sS[t].y += oS.y; sS[t].z += oS.z; sS[t].w += oS.w;
            sQ[t].x += oQ.x; sQ[t].y += oQ.y; sQ[t].z += oQ.z; sQ[t].w += oQ.w;
        }
        __syncthreads();
    }
    if (t < 16) {
        float4 vS = sS[t], vQ = sQ[t];
        float cnt = (float)max(eend - s, 1);
        float m0 = vS.x / cnt, m1 = vS.y / cnt, m2 = vS.z / cnt, m3 = vS.w / cnt;
        float i0 = rsqrtf(vQ.x / cnt - m0 * m0 + EPS_IN);
        float i1 = rsqrtf(vQ.y / cnt - m1 * m1 + EPS_IN);
        float i2 = rsqrtf(vQ.z / cnt - m2 * m2 + EPS_IN);
        float i3 = rsqrtf(vQ.w / cnt - m3 * m3 + EPS_IN);
        int cw = c0u + t * 2;
        g_iv1h  [g * 128 + cw]     = h2bits(i0, i1);
        g_iv1h  [g * 128 + cw + 1] = h2bits(i2, i3);
        g_nmiv1h[g * 128 + cw]     = h2bits(-m0 * i0, -m1 * i1);
        g_nmiv1h[g * 128 + cw + 1] = h2bits(-m2 * i2, -m3 * i3);
    }
}

// ---------------- GEMM2: warp-specialized, double-buffered, contiguous tiles ----------------
// smem: [0) B frags 33792 | [33792) A buf0 65536 | [99328) A buf1 65536 = 164864.
__device__ __forceinline__ void g2_fill(char* cA, int tile, int m, int hf) {
    int4 md = g_meta[tile * 128 + m];
    int g = md.y, nc = md.z, nr = md.w;
    const uint4* yc  = (const uint4*)(g_Yh + (size_t)nc * 256 + hf * 64);
    const uint4* yr  = (const uint4*)(g_Yh + (size_t)nr * 256 + 128 + hf * 64);
    const uint4* hiv = (const uint4*)(g_iv1h   + g * 128 + hf * 64);
    const uint4* hmv = (const uint4*)(g_nmiv1h + g * 128 + hf * 64);
    const __half2 hz = __float2half2_rn(0.f);
    int msw = m & 7;
    #pragma unroll
    for (int jj = 0; jj < 16; jj++) {
        uint4 va = yc[jj], vb = yr[jj], vi = hiv[jj], vm = hmv[jj];
        u32 o0 = h2u(__hmax2(__hfma2(__hadd2(u2h(va.x), u2h(vb.x)), u2h(vi.x), u2h(vm.x)), hz));
        u32 o1 = h2u(__hmax2(__hfma2(__hadd2(u2h(va.y), u2h(vb.y)), u2h(vi.y), u2h(vm.y)), hz));
        u32 o2 = h2u(__hmax2(__hfma2(__hadd2(u2h(va.z), u2h(vb.z)), u2h(vi.z), u2h(vm.z)), hz));
        u32 o3 = h2u(__hmax2(__hfma2(__hadd2(u2h(va.w), u2h(vb.w)), u2h(vi.w), u2h(vm.w)), hz));
        int oct = hf * 16 + jj;
        int gran = m * 32 + (oct ^ msw);
        *(uint4*)(cA + gran * 16) = make_uint4(o0, o1, o2, o3);
    }
}

__global__ __launch_bounds__(512) void k_gemm2_mma(const float* __restrict__ W2)
{
    extern __shared__ u32 sm[];
    u32* sB = sm;
    char* smc = (char*)sm;
    char* bufs[2] = {smc + 33792, smc + 99328};

    int tid = threadIdx.x;
    for (int i = tid; i < 8192; i += 512) {
        int a = i >> 6, l = (i >> 1) & 31, r = i & 1;
        int ng = a >> 4, ki = a & 15;
        int k = ki * 16 + (l & 3) * 2 + r * 8;
        int n = ng * 8 + (l >> 2);
        sB[a * 66 + (i & 63)] = h2bits(W2[k * 64 + n], W2[(k + 1) * 64 + n]);
    }

    bool producer = (tid < 256);
    int m = tid & 127, hf = (tid >> 7) & 1;
    int wid2 = (tid >> 5) - 8;
    int lane = tid & 31;
    int wm = wid2 & 3, wn = wid2 >> 2;
    int lt = lane >> 3, lr = lane & 7;
    int lrow8 = (lt & 1) * 8 + lr;
    int lth = lt >> 1;

    int t0 = blockIdx.x * TPC2;
    int tend = t0 + TPC2;
    if (tend > NT) tend = NT;
    int n = tend - t0;

    if (producer && n > 0)
        g2_fill(bufs[0], t0, m, hf);
    __syncthreads();

    for (int i = 0; i < n; i++) {
        int tile = t0 + i;
        if (producer) {
            if (i + 1 < n)
                g2_fill(bufs[(i + 1) & 1], tile + 1, m, hf);
        } else {
            u32 aA = smem_u32(bufs[i & 1]);
            float d[2][4][4];
            #pragma unroll
            for (int mi2 = 0; mi2 < 2; mi2++)
                #pragma unroll
                for (int ni = 0; ni < 4; ni++)
                    #pragma unroll
                    for (int r = 0; r < 4; r++) d[mi2][ni][r] = 0.f;

            #pragma unroll
            for (int ki = 0; ki < 16; ki++) {
                u32 ah[2][4];
                #pragma unroll
                for (int mi2 = 0; mi2 < 2; mi2++) {
                    int ml = wm * 32 + mi2 * 16 + lrow8;
                    int oct = 2 * ki + lth;
                    u32 goff = (u32)(ml * 32 + (oct ^ (ml & 7))) * 16;
                    ldm_x4(ah[mi2], aA + goff);
                }
                #pragma unroll
                for (int ni = 0; ni < 4; ni++) {
                    int batom = ((wn * 4 + ni) * 16 + ki) * 66 + lane * 2;
                    uint2 bv = *(const uint2*)(sB + batom);
                    u32 bb[2] = {bv.x, bv.y};
                    mma_f16(d[0][ni], ah[0], bb);
                    mma_f16(d[1][ni], ah[1], bb);
                }
            }
            int r0base = tile * 128 + wm * 32 + (lane >> 2);
            int cpb = wn * 16 + (lane & 3);
            #pragma unroll
            for (int mi2 = 0; mi2 < 2; mi2++) {
                size_t rA = (size_t)(r0base + mi2 * 16);
                size_t rB = rA + 8;
                #pragma unroll
                for (int ni = 0; ni < 4; ni++) {
                    __stcs(&g_x2h[rA * 32 + cpb + ni * 4], h2bits(d[mi2][ni][0], d[mi2][ni][1]));
                    __stcs(&g_x2h[rB * 32 + cpb + ni * 4], h2bits(d[mi2][ni][2], d[mi2][ni][3]));
                }
            }
        }
        __syncthreads();
    }
}

// ---------------- fused stats2 + final: one block per graph ----------------
__global__ __launch_bounds__(256) void k_norm2final(
    const float* __restrict__ W3, const float* __restrict__ b3,
    float* __restrict__ out)
{
    __shared__ float sw[64];
    __shared__ float siv[64], smv[64];
    __shared__ float4 sS[256];
    int g = blockIdx.x;
    int t = threadIdx.x;
    if (t < 64) sw[t] = W3[t];
    int s = g_off[g], eend = g_off[g + 1];

    // ---- pass 1: per-graph stats over x2 (identical order to old k_stats2) ----
    int c2 = t & 31, r = t >> 5;
    float Sx = 0.f, Sy = 0.f, Qx = 0.f, Qy = 0.f;
    for (int p = s + r; p < eend; p += 8) {
        float2 f = h22f2(g_x2h[(size_t)p * 32 + c2]);
        Sx += f.x; Qx += f.x * f.x;
        Sy += f.y; Qy += f.y * f.y;
    }
    sS[t] = make_float4(Sx, Sy, Qx, Qy);
    __syncthreads();
    for (int h2 = 128; h2 >= 32; h2 >>= 1) {
        if (t < h2) {
            float4 o = sS[t + h2];
            sS[t].x += o.x; sS[t].y += o.y; sS[t].z += o.z; sS[t].w += o.w;
        }
        __syncthreads();
    }
    if (t < 32) {
        float4 v = sS[t];
        float cnt = (float)max(eend - s, 1);
        float mx = v.x / cnt, my = v.y / cnt;
        float ivx = rsqrtf(v.z / cnt - mx * mx + EPS_IN);
        float ivy = rsqrtf(v.w / cnt - my * my + EPS_IN);
        siv[t * 2]     = ivx;
        siv[t * 2 + 1] = ivy;
        smv[t * 2]     = mx * ivx;
        smv[t * 2 + 1] = my * ivy;
    }
    __syncthreads();

    // ---- pass 2: normalize + dot W3 + scatter (identical math to old k_final) ----
    float b3v = b3[0];
    int half = t & 1;
    const float4* vr = (const float4*)(siv + half * 32);
    const float4* mr = (const float4*)(smv + half * 32);
    for (int pos = s + (t >> 1); pos < eend; pos += 128) {
        float acc = 0.f;
        const uint4* xr = (const uint4*)(g_x2h + (size_t)pos * 32 + half * 16);
        #pragma unroll
        for (int j = 0; j < 4; j++) {
            uint4 xv = xr[j];
            float4 iv0 = vr[2 * j], iv1 = vr[2 * j + 1];
            float4 mv0 = mr[2 * j], mv1 = mr[2 * j + 1];
            float2 a0 = h22f2(xv.x), a1 = h22f2(xv.y);
            float2 a2 = h22f2(xv.z), a3 = h22f2(xv.w);
            int k = half * 32 + j * 8;
            acc += fmaxf(fmaf(a0.x, iv0.x, -mv0.x), 0.f) * sw[k]
                 + fmaxf(fmaf(a0.y, iv0.y, -mv0.y), 0.f) * sw[k + 1]
                 + fmaxf(fmaf(a1.x, iv0.z, -mv0.z), 0.f) * sw[k + 2]
                 + fmaxf(fmaf(a1.y, iv0.w, -mv0.w), 0.f) * sw[k + 3]
                 + fmaxf(fmaf(a2.x, iv1.x, -mv1.x), 0.f) * sw[k + 4]
                 + fmaxf(fmaf(a2.y, iv1.y, -mv1.y), 0.f) * sw[k + 5]
                 + fmaxf(fmaf(a3.x, iv1.z, -mv1.z), 0.f) * sw[k + 6]
                 + fmaxf(fmaf(a3.y, iv1.w, -mv1.w), 0.f) * sw[k + 7];
        }
        float other = __shfl_xor_sync(0xffffffffu, acc, 1);
        if (half == 0)
            out[g_meta[pos].x] = acc + other + b3v;
    }
}

// ---------------- launch ----------------
extern "C" void kernel_launch(void* const* d_in, const int* in_sizes, int n_in,
                              void* d_out, int out_size)
{
    const float* emb   = (const float*)d_in[0];
    const float* W1    = (const float*)d_in[1];
    const float* W2    = (const float*)d_in[3];
    const float* W3    = (const float*)d_in[5];
    const float* b3    = (const float*)d_in[6];
    const int*   ei    = (const int*)d_in[7];
    const int*   batch = (const int*)d_in[8];
    const int* col = ei;
    const int* row = ei + E_EDGES;
    float* out = (float*)d_out;

    static cudaStream_t s2;
    static cudaEvent_t ev1, ev2;
    static int init_done = 0;
    if (!init_done) {
        cudaFuncSetAttribute(k_gemm2_mma, cudaFuncAttributeMaxDynamicSharedMemorySize, 164864);
        cudaFuncSetAttribute(k_emb_mma, cudaFuncAttributeMaxDynamicSharedMemorySize, 50176);
        cudaStreamCreateWithFlags(&s2, cudaStreamNonBlocking);
        cudaEventCreateWithFlags(&ev1, cudaEventDisableTiming);
        cudaEventCreateWithFlags(&ev2, cudaEventDisableTiming);
        init_done = 1;
    }

    // fork: emb_mma on side stream overlaps the col-sort chain on main stream
    cudaEventRecord(ev1, 0);
    cudaStreamWaitEvent(s2, ev1, 0);
    k_emb_mma<<<dim3((NN + 127) / 128, 2), 512, 50176, s2>>>(emb, W1);
    cudaEventRecord(ev2, s2);

    k_nhist<<<1024, 256>>>(col);
    k_nscan1<<<NBLK, 512>>>();
    k_nscan2<<<1, 128>>>();
    k_nscan3<<<NBLK, 512>>>(batch);
    k_scatter<<<1024, 256>>>(col, row, batch);

    cudaStreamWaitEvent(0, ev2, 0);   // join before stats1g (needs Y + sorted meta)
    k_stats1g<<<NG * 4, 256>>>();
    k_gemm2_mma<<<GRID2, 512, 164864>>>(W2);
    k_norm2final<<<NG, 256>>>(W3, b3, out);
}